// round 8
// baseline (speedup 1.0000x reference)
#include <cuda_runtime.h>
#include <cstdint>

#if defined(__CUDA_ARCH_FEAT_SM103_ALL) || defined(__CUDA_ARCH_FEAT_SM100_ALL) || defined(__CUDA_ARCH_FEAT_SM101_ALL)
#define TC_OK 1
#endif

#define TOKENS 4096
#define HIDDEN 2048
#define INTER  768
#define NEXP   64
#define TOPK   8
#define NPAIRS (TOKENS*TOPK)
#define MCAP   2048
#define BK     32
#define STG    65536        // stage: A 32KB + B 32KB
#define KT1    (HIDDEN/BK)  // 64
#define KT2    (INTER/BK)   // 24
#define WSZ    100663296

__device__ int   g_tc_ok;
__device__ int   g_amode;   // 0=legacy, 1=cp.async A, 2=bulk A (nosw)
__device__ int   g_ok1;
__device__ int   g_ok2;
__device__ int   g_counts[NEXP];
__device__ int   g_offsets[NEXP+1];
__device__ int   g_cursor[NEXP];
__device__ int   g_pair_e[NPAIRS];
__device__ float g_pair_w[NPAIRS];
__device__ int   g_row_token[NPAIRS];
__device__ float g_row_weight[NPAIRS];
__device__ int   g_s2p[NPAIRS];
__device__ float g_act[(size_t)NPAIRS * INTER];
__device__ float g_pout[(size_t)NPAIRS * HIDDEN];
__device__ float g_hid[(size_t)TOKENS * HIDDEN];
__device__ float g_wtg[WSZ];   // gate^T tiled+swizzled [e][nb(6)][kk(64)][16KB]
__device__ float g_wtu[WSZ];
__device__ float g_wtd[WSZ];   // down^T tiled [e][nb(16)][kk(24)][16KB]

__device__ __forceinline__ uint32_t smem_u32(const void* p) {
    return (uint32_t)__cvta_generic_to_shared(p);
}
__device__ __forceinline__ float f2tf(float x) {
    uint32_t r;
    asm("cvt.rna.tf32.f32 %0, %1;" : "=r"(r) : "f"(x));
    return __uint_as_float(r);
}
__device__ __forceinline__ uint32_t f2tfu(float x) {
    uint32_t r;
    asm("cvt.rna.tf32.f32 %0, %1;" : "=r"(r) : "f"(x));
    return r;
}
#define SW128(o) ((o) ^ (((o) >> 3) & 0x70))
#define CP16(d, s) asm volatile("cp.async.cg.shared.global [%0], [%1], 16;\n" :: "r"(d), "l"(s))
#define CP_COMMIT  asm volatile("cp.async.commit_group;\n")
#define CP_WAIT(n) asm volatile("cp.async.wait_group %0;\n" :: "n"(n))
#define MBAR_INIT(mb, c) asm volatile("mbarrier.init.shared.b64 [%0], %1;" :: "r"(mb), "r"(c) : "memory")
#define MBAR_ARRIVE_TX(mb, tx) asm volatile("mbarrier.arrive.expect_tx.shared.b64 _, [%0], %1;" :: "r"(mb), "r"(tx) : "memory")
#define BULK_G2S(dst, src, sz, mb)                                            \
    asm volatile("cp.async.bulk.shared::cluster.global.mbarrier::complete_tx::bytes [%0], [%1], %2, [%3];" \
                 :: "r"(dst), "l"(src), "r"(sz), "r"(mb) : "memory")
#define MBAR_WAIT(mb, ph)                                                     \
    asm volatile("{\n\t.reg .pred P1;\n\t"                                    \
        "WL_%=:\n\t"                                                          \
        "mbarrier.try_wait.parity.acquire.cta.shared::cta.b64 P1, [%0], %1, 0x989680;\n\t" \
        "@P1 bra.uni WD_%=;\n\t"                                              \
        "bra.uni WL_%=;\n\t"                                                  \
        "WD_%=:\n\t}" :: "r"(mb), "r"(ph) : "memory")

#ifdef TC_OK
#define TC_ALLOC(sm, n)  asm volatile("tcgen05.alloc.cta_group::1.sync.aligned.shared::cta.b32 [%0], %1;" :: "r"(sm), "r"(n) : "memory")
#define TC_DEALLOC(t, n) asm volatile("tcgen05.dealloc.cta_group::1.sync.aligned.b32 %0, %1;" :: "r"(t), "r"(n))
#define TC_RELINQ()      asm volatile("tcgen05.relinquish_alloc_permit.cta_group::1.sync.aligned;")
#define TC_COMMIT(mb)    asm volatile("tcgen05.commit.cta_group::1.mbarrier::arrive::one.shared::cluster.b64 [%0];" :: "r"(mb) : "memory")
#define TC_FENCE_AFTER() asm volatile("tcgen05.fence::after_thread_sync;" ::: "memory")
#define TC_WAIT_LD()     asm volatile("tcgen05.wait::ld.sync.aligned;" ::: "memory")
#define FENCE_ASYNC()    asm volatile("fence.proxy.async.shared::cta;" ::: "memory")
#define LDTM_X32(r, a)                                                        \
    asm volatile("tcgen05.ld.sync.aligned.32x32b.x32.b32 "                    \
        "{%0,%1,%2,%3,%4,%5,%6,%7,%8,%9,%10,%11,%12,%13,%14,%15,"             \
        "%16,%17,%18,%19,%20,%21,%22,%23,%24,%25,%26,%27,%28,%29,%30,%31},[%32];" \
        : "=r"((r)[0]),"=r"((r)[1]),"=r"((r)[2]),"=r"((r)[3]),                \
          "=r"((r)[4]),"=r"((r)[5]),"=r"((r)[6]),"=r"((r)[7]),                \
          "=r"((r)[8]),"=r"((r)[9]),"=r"((r)[10]),"=r"((r)[11]),              \
          "=r"((r)[12]),"=r"((r)[13]),"=r"((r)[14]),"=r"((r)[15]),            \
          "=r"((r)[16]),"=r"((r)[17]),"=r"((r)[18]),"=r"((r)[19]),            \
          "=r"((r)[20]),"=r"((r)[21]),"=r"((r)[22]),"=r"((r)[23]),            \
          "=r"((r)[24]),"=r"((r)[25]),"=r"((r)[26]),"=r"((r)[27]),            \
          "=r"((r)[28]),"=r"((r)[29]),"=r"((r)[30]),"=r"((r)[31]) : "r"(a))

__device__ __forceinline__ uint64_t desc_k(uint32_t a) {     // SW128 K-major
    return (uint64_t(2) << 61) | (uint64_t(1) << 46) | (uint64_t(64) << 32) |
           (uint64_t(1) << 16) | ((uint64_t)(a >> 4) & 0x3FFF);
}
__device__ __forceinline__ uint64_t desc_nosw(uint32_t a) {  // no-swizzle K-major
    return (uint64_t(1) << 46) | (uint64_t(64) << 32) |
           (uint64_t(1) << 16) | ((uint64_t)(a >> 4) & 0x3FFF);
}
#define IDESC32 ((1u<<4)|(2u<<7)|(2u<<10)|(4u<<17)|(8u<<24))
#define IDESC64 ((1u<<4)|(2u<<7)|(2u<<10)|(8u<<17)|(8u<<24))
__device__ __forceinline__ void mma_n32(uint32_t d, uint64_t ad, uint64_t bd, uint32_t acc) {
    asm volatile(
        "{\n\t.reg .pred p;\n\tsetp.ne.u32 p, %4, 0;\n\t"
        "tcgen05.mma.cta_group::1.kind::tf32 [%0], %1, %2, %3, {%5,%5,%5,%5}, p;\n\t}"
        :: "r"(d), "l"(ad), "l"(bd), "r"(IDESC32), "r"(acc), "r"(0u) : "memory");
}
__device__ __forceinline__ void mma_n64(uint32_t d, uint64_t ad, uint64_t bd, uint32_t acc) {
    asm volatile(
        "{\n\t.reg .pred p;\n\tsetp.ne.u32 p, %4, 0;\n\t"
        "tcgen05.mma.cta_group::1.kind::tf32 [%0], %1, %2, %3, {%5,%5,%5,%5}, p;\n\t}"
        :: "r"(d), "l"(ad), "l"(bd), "r"(IDESC64), "r"(acc), "r"(0u) : "memory");
}
#endif

// ---------------- self-tests ----------------
__device__ __forceinline__ float tva(int m, int k) {
    return f2tf(0.01f * (float)((m * 7 + k * 13) % 31 - 15));
}
__device__ __forceinline__ float tvb(int n, int k) {
    return f2tf(0.02f * (float)((n * 5 + k * 3) % 29 - 14));
}
#ifdef TC_OK
// shared body: A layout selected by nosw flag
__device__ void selftest_body(int nosw, int* result) {
    __shared__ __align__(1024) float sma[4096];
    __shared__ __align__(1024) float smb[1024];
    __shared__ uint32_t s_tmem[1];
    __shared__ __align__(8) uint64_t s_mbar[1];
    __shared__ float s_d, s_r;
    int tid = threadIdx.x, wid = tid >> 5, lane = tid & 31;

    if (wid == 0) { TC_ALLOC(smem_u32(s_tmem), 128); TC_RELINQ(); }
    if (tid == 0) { MBAR_INIT(smem_u32(s_mbar), 1); s_d = 0.f; s_r = 0.f; }
    for (int idx = tid; idx < 4096; idx += 128) {
        int m = idx >> 5, k = idx & 31;
        uint32_t o = (uint32_t)(m * 128 + k * 4);
        *(float*)((char*)sma + (nosw ? o : SW128(o))) = tva(m, k);
    }
    for (int idx = tid; idx < 1024; idx += 128) {
        int n = idx >> 5, k = idx & 31;
        *(float*)((char*)smb + SW128((uint32_t)(n * 128 + k * 4))) = tvb(n, k);
    }
    __syncthreads();
    uint32_t tmem = s_tmem[0], mb = smem_u32(s_mbar);
    if (tid == 0) {
        FENCE_ASYNC();
        uint64_t ad = nosw ? desc_nosw(smem_u32(sma)) : desc_k(smem_u32(sma));
        uint64_t bd = desc_k(smem_u32(smb));
#pragma unroll
        for (int ks = 0; ks < 4; ++ks)
            mma_n32(tmem, ad + ks * 2, bd + ks * 2, ks > 0 ? 1u : 0u);
        TC_COMMIT(mb);
    }
    __syncthreads();
    MBAR_WAIT(mb, 0);
    TC_FENCE_AFTER();
    uint32_t r[32];
    LDTM_X32(r, tmem);
    TC_WAIT_LD();
    int m = wid * 32 + lane;
    float d = 0.f, rf = 0.f;
#pragma unroll 4
    for (int n = 0; n < 32; ++n) {
        float ref = 0.f;
        for (int k = 0; k < 32; ++k) ref += tva(m, k) * tvb(n, k);
        d  += fabsf(__uint_as_float(r[n]) - ref);
        rf += fabsf(ref);
    }
    atomicAdd(&s_d, d); atomicAdd(&s_r, rf);
    __syncthreads();
    if (tid == 0) *result = (s_d <= 0.01f * s_r + 1e-3f) ? 1 : 0;
    __syncthreads();
    if (wid == 0) TC_DEALLOC(tmem, 128);
}
#endif
__global__ void selftest_kernel() {
#ifdef TC_OK
    selftest_body(0, &g_tc_ok);
#else
    if (threadIdx.x == 0) g_tc_ok = 0;
#endif
}
__global__ void selftest2_kernel() {
#ifdef TC_OK
    __shared__ int res;
    selftest_body(1, &res);
    if (threadIdx.x == 0) g_amode = g_tc_ok ? (res ? 2 : 1) : 0;
#else
    if (threadIdx.x == 0) g_amode = 0;
#endif
}

// ---------------- prep ----------------
__global__ void rnd_kernel(const float4* __restrict__ src, float4* __restrict__ dst, int n4) {
    int i = blockIdx.x * blockDim.x + threadIdx.x, st = gridDim.x * blockDim.x;
    for (; i < n4; i += st) {
        float4 v = src[i];
        v.x = f2tf(v.x); v.y = f2tf(v.y); v.z = f2tf(v.z); v.w = f2tf(v.w);
        dst[i] = v;
    }
}
// W[e][K][N] -> tiled+swizzled WT: tile (e, nb=n>>7, kk=k>>5) 16KB, inner SW128
__global__ void tile_kernel(const float* __restrict__ src, float* __restrict__ dst,
                            int K, int N, int NB, int KK) {
    if (g_tc_ok == 0) return;
    __shared__ float t[32][33];
    int e = blockIdx.z;
    int k0 = blockIdx.x * 32, n0 = blockIdx.y * 32;
    int r = threadIdx.x >> 3, c4 = (threadIdx.x & 7) << 2;
    float4 v = *(const float4*)(src + ((size_t)e * K + k0 + r) * N + n0 + c4);
    t[r][c4] = v.x; t[r][c4 + 1] = v.y; t[r][c4 + 2] = v.z; t[r][c4 + 3] = v.w;
    __syncthreads();
    int n = n0 + r;
    size_t tile = ((size_t)e * NB + (n >> 7)) * KK + (k0 >> 5);
    uint32_t inner = SW128((uint32_t)(((n & 127) << 7) + (c4 << 2)));
    float4 o;
    o.x = f2tf(t[c4    ][r]);
    o.y = f2tf(t[c4 + 1][r]);
    o.z = f2tf(t[c4 + 2][r]);
    o.w = f2tf(t[c4 + 3][r]);
    *(float4*)((char*)dst + tile * 16384 + inner) = o;
}
__device__ __forceinline__ float wt_read(const float* wt, int NB, int KK, int e, int n, int k) {
    size_t tile = ((size_t)e * NB + (n >> 7)) * KK + (k >> 5);
    uint32_t inner = SW128((uint32_t)(((n & 127) << 7) + ((k & 31) << 2)));
    return *(const float*)((const char*)wt + tile * 16384 + inner);
}
__global__ void init_kernel() { if (threadIdx.x < NEXP) g_counts[threadIdx.x] = 0; }

__global__ void route_kernel(const float* __restrict__ logits) {
    int t = blockIdx.x * blockDim.x + threadIdx.x;
    if (t >= TOKENS) return;
    float l[NEXP];
    const float* lp = logits + (size_t)t * NEXP;
#pragma unroll
    for (int i = 0; i < NEXP; ++i) l[i] = lp[i];
    float val[TOPK]; int sel[TOPK];
#pragma unroll
    for (int k = 0; k < TOPK; ++k) {
        float best = -1e30f; int bi = 0;
#pragma unroll
        for (int i = 0; i < NEXP; ++i)
            if (l[i] > best) { best = l[i]; bi = i; }
        val[k] = best; sel[k] = bi; l[bi] = -1e30f;
    }
    float m = val[0], s = 0.f, w[TOPK];
#pragma unroll
    for (int k = 0; k < TOPK; ++k) { w[k] = __expf(val[k] - m); s += w[k]; }
    float inv = 1.f / s;
#pragma unroll
    for (int k = 0; k < TOPK; ++k) {
        g_pair_e[t * TOPK + k] = sel[k];
        g_pair_w[t * TOPK + k] = w[k] * inv;
        atomicAdd(&g_counts[sel[k]], 1);
    }
}
__global__ void scan_kernel() {
    if (threadIdx.x == 0) {
        int acc = 0;
        for (int e = 0; e < NEXP; ++e) { g_offsets[e] = acc; g_cursor[e] = acc; acc += g_counts[e]; }
        g_offsets[NEXP] = acc;
    }
}
__global__ void scatter_kernel() {
    int p = blockIdx.x * blockDim.x + threadIdx.x;
    if (p >= NPAIRS) return;
    int slot = atomicAdd(&g_cursor[g_pair_e[p]], 1);
    g_row_token[slot]  = p >> 3;
    g_row_weight[slot] = g_pair_w[p];
    g_s2p[slot] = p;
}

// ============ tcgen05 GEMM1: M=256, N=128 (gate+up), 3-stage, bulk B ======
__global__ void __launch_bounds__(256, 1)
gemm1_tc() {
#ifdef TC_OK
    int am = g_amode;
    if (am == 0) return;
    int e = blockIdx.z;
    int off = g_offsets[e], cnt = g_offsets[e + 1] - off;
    int m0 = blockIdx.x * 256;
    if (m0 >= cnt) return;
    int nb = blockIdx.y;           // n-block of 128
    int n0 = nb * 128;

    extern __shared__ char dyn[];
    uint32_t sbase = (smem_u32(dyn) + 1023u) & ~1023u;
    __shared__ uint32_t s_tmem[1];
    __shared__ __align__(8) uint64_t s_full[3], s_mdone[3];
    int tid = threadIdx.x, wid = tid >> 5, lane = tid & 31;

    if (wid == 0) { TC_ALLOC(smem_u32(s_tmem), 512); TC_RELINQ(); }
    if (tid == 0) {
        int fcnt = (am == 2) ? 256 : 1;
#pragma unroll
        for (int i = 0; i < 3; ++i) {
            MBAR_INIT(smem_u32(&s_full[i]), fcnt);
            MBAR_INIT(smem_u32(&s_mdone[i]), 1);
        }
    }
    __syncthreads();
    uint32_t tmem = s_tmem[0];
    uint32_t full[3]  = { smem_u32(&s_full[0]),  smem_u32(&s_full[1]),  smem_u32(&s_full[2])  };
    uint32_t mdone[3] = { smem_u32(&s_mdone[0]), smem_u32(&s_mdone[1]), smem_u32(&s_mdone[2]) };

    int maxslot = off + cnt - 1;
    // A row for this thread (bulk mode): one 128B row per thread
    int slot = off + m0 + tid; if (slot > maxslot) slot = maxslot;
    const char* a_row = (const char*)(g_hid + (size_t)g_row_token[slot] * HIDDEN);
    // B tile pointers
    const char* tg = (const char*)g_wtg + (((size_t)e * 6 + nb) * KT1) * 16384;
    const char* tu = (const char*)g_wtu + (((size_t)e * 6 + nb) * KT1) * 16384;

    // cp.async A setup (mode 1)
    const float* asrc[8]; uint32_t aoff[8];
    if (am == 1) {
#pragma unroll
        for (int j = 0; j < 8; ++j) {
            int id = tid + j * 256;
            int row = id >> 3, c = id & 7;
            int sl = off + m0 + row; if (sl > maxslot) sl = maxslot;
            asrc[j] = g_hid + (size_t)g_row_token[sl] * HIDDEN + c * 4;
            aoff[j] = SW128((uint32_t)(row * 128 + c * 16));
        }
    }

    auto load_stage = [&](int s, int kt) {
        uint32_t sb = sbase + s * STG;
        if (am == 2) {
            MBAR_ARRIVE_TX(full[s], (tid == 0) ? (128u + 32768u) : 128u);
            BULK_G2S(sb + (uint32_t)tid * 128u, a_row + (size_t)kt * 128, 128u, full[s]);
            if (tid == 0) {
                BULK_G2S(sb + 32768u, tg + (size_t)kt * 16384, 16384u, full[s]);
                BULK_G2S(sb + 49152u, tu + (size_t)kt * 16384, 16384u, full[s]);
            }
        } else {
            if (tid == 0) {
                MBAR_ARRIVE_TX(full[s], 32768u);
                BULK_G2S(sb + 32768u, tg + (size_t)kt * 16384, 16384u, full[s]);
                BULK_G2S(sb + 49152u, tu + (size_t)kt * 16384, 16384u, full[s]);
            }
#pragma unroll
            for (int j = 0; j < 8; ++j) CP16(sb + aoff[j], asrc[j] + (size_t)kt * BK);
            CP_COMMIT;
        }
    };

    load_stage(0, 0);
    load_stage(1, 1);
    for (int kt = 0; kt < KT1; ++kt) {
        int s = kt % 3;
        if (am == 1) { if (kt < KT1 - 1) { CP_WAIT(1); } else { CP_WAIT(0); } }
        if (tid == 0) MBAR_WAIT(full[s], (kt / 3) & 1);
        __syncthreads();
        if (tid == 0) {
            FENCE_ASYNC();
            uint32_t sb = sbase + s * STG;
            uint64_t ad = (am == 2) ? desc_nosw(sb) : desc_k(sb);
            uint64_t bg = desc_k(sb + 32768u), bu = desc_k(sb + 49152u);
#pragma unroll
            for (int ks = 0; ks < 4; ++ks) {
                uint32_t acc = (kt > 0 || ks > 0) ? 1u : 0u;
#pragma unroll
                for (int mh = 0; mh < 2; ++mh) {
                    uint64_t amd = ad + mh * 1024 + ks * 2;
#pragma unroll
                    for (int j = 0; j < 2; ++j) {
                        mma_n64(tmem + mh * 256 + j * 64,       amd, bg + j * 512 + ks * 2, acc);
                        mma_n64(tmem + mh * 256 + 128 + j * 64, amd, bu + j * 512 + ks * 2, acc);
                    }
                }
            }
            TC_COMMIT(mdone[s]);
        }
        if (kt + 2 < KT1) {
            if (kt >= 1)
                MBAR_WAIT(mdone[(kt - 1) % 3], ((kt - 1) / 3) & 1);
            load_stage((kt + 2) % 3, kt + 2);
        }
    }
    MBAR_WAIT(mdone[(KT1 - 1) % 3], ((KT1 - 1) / 3) & 1);
    TC_FENCE_AFTER();

    int mh = wid >> 2, sp = wid & 3;
    int row = mh * 128 + sp * 32 + lane;
    bool valid = (m0 + row) < cnt;
    float* dst = g_act + (size_t)(off + m0 + row) * INTER + n0;
    uint32_t tb = tmem + mh * 256;
#pragma unroll
    for (int cb = 0; cb < 4; ++cb) {
        int c0 = cb * 32;
        uint32_t rg[32], ru[32];
        LDTM_X32(rg, tb + c0);
        LDTM_X32(ru, tb + 128 + c0);
        TC_WAIT_LD();
        if (valid) {
#pragma unroll
            for (int i = 0; i < 32; i += 4) {
                float4 v;
#pragma unroll
                for (int q = 0; q < 4; ++q) {
                    float g = __uint_as_float(rg[i + q]);
                    float u = __uint_as_float(ru[i + q]);
                    ((float*)&v)[q] = f2tf(g / (1.f + __expf(-g)) * u);
                }
                *(float4*)(dst + c0 + i) = v;
            }
        }
    }
    __syncthreads();
    if (wid == 0) TC_DEALLOC(tmem, 512);
#endif
}

// ============ tcgen05 GEMM2: M=256, N=256, 3-stage, bulk B ================
__global__ void __launch_bounds__(256, 1)
gemm2_tc() {
#ifdef TC_OK
    int am = g_amode;
    if (am == 0 || g_ok1 == 0) return;
    int e = blockIdx.z;
    int off = g_offsets[e], cnt = g_offsets[e + 1] - off;
    int m0 = blockIdx.x * 256;
    if (m0 >= cnt) return;
    int nb0 = blockIdx.y * 2;       // two 128-row n-blocks
    int n0 = nb0 * 128;

    extern __shared__ char dyn[];
    uint32_t sbase = (smem_u32(dyn) + 1023u) & ~1023u;
    __shared__ uint32_t s_tmem[1];
    __shared__ __align__(8) uint64_t s_full[3], s_mdone[3];
    int tid = threadIdx.x, wid = tid >> 5, lane = tid & 31;

    if (wid == 0) { TC_ALLOC(smem_u32(s_tmem), 512); TC_RELINQ(); }
    if (tid == 0) {
        int fcnt = (am == 2) ? 256 : 1;
#pragma unroll
        for (int i = 0; i < 3; ++i) {
            MBAR_INIT(smem_u32(&s_full[i]), fcnt);
            MBAR_INIT(smem_u32(&s_mdone[i]), 1);
        }
    }
    __syncthreads();
    uint32_t tmem = s_tmem[0];
    uint32_t full[3]  = { smem_u32(&s_full[0]),  smem_u32(&s_full[1]),  smem_u32(&s_full[2])  };
    uint32_t mdone[3] = { smem_u32(&s_mdone[0]), smem_u32(&s_mdone[1]), smem_u32(&s_mdone[2]) };

    int ar = off + m0 + tid; if (ar > NPAIRS - 1) ar = NPAIRS - 1;
    const char* a_row = (const char*)(g_act + (size_t)ar * INTER);
    const char* t0p = (const char*)g_wtd + (((size_t)e * 16 + nb0)     * KT2) * 16384;
    const char* t1p = (const char*)g_wtd + (((size_t)e * 16 + nb0 + 1) * KT2) * 16384;

    const float* asrc[8]; uint32_t aoff[8];
    if (am == 1) {
#pragma unroll
        for (int j = 0; j < 8; ++j) {
            int id = tid + j * 256;
            int row = id >> 3, c = id & 7;
            int a2 = off + m0 + row; if (a2 > NPAIRS - 1) a2 = NPAIRS - 1;
            asrc[j] = g_act + (size_t)a2 * INTER + c * 4;
            aoff[j] = SW128((uint32_t)(row * 128 + c * 16));
        }
    }

    auto load_stage = [&](int s, int kt) {
        uint32_t sb = sbase + s * STG;
        if (am == 2) {
            MBAR_ARRIVE_TX(full[s], (tid == 0) ? (128u + 32768u) : 128u);
            BULK_G2S(sb + (uint32_t)tid * 128u, a_row + (size_t)kt * 128, 128u, full[s]);
            if (tid == 0) {
                BULK_G2S(sb + 32768u, t0p + (size_t)kt * 16384, 16384u, full[s]);
                BULK_G2S(sb + 49152u, t1p + (size_t)kt * 16384, 16384u, full[s]);
            }
        } else {
            if (tid == 0) {
                MBAR_ARRIVE_TX(full[s], 32768u);
                BULK_G2S(sb + 32768u, t0p + (size_t)kt * 16384, 16384u, full[s]);
                BULK_G2S(sb + 49152u, t1p + (size_t)kt * 16384, 16384u, full[s]);
            }
#pragma unroll
            for (int j = 0; j < 8; ++j) CP16(sb + aoff[j], asrc[j] + (size_t)kt * BK);
            CP_COMMIT;
        }
    };

    load_stage(0, 0);
    load_stage(1, 1);
    for (int kt = 0; kt < KT2; ++kt) {
        int s = kt % 3;
        if (am == 1) { if (kt < KT2 - 1) { CP_WAIT(1); } else { CP_WAIT(0); } }
        if (tid == 0) MBAR_WAIT(full[s], (kt / 3) & 1);
        __syncthreads();
        if (tid == 0) {
            FENCE_ASYNC();
            uint32_t sb = sbase + s * STG;
            uint64_t ad = (am == 2) ? desc_nosw(sb) : desc_k(sb);
            uint64_t b0 = desc_k(sb + 32768u), b1 = desc_k(sb + 49152u);
#pragma unroll
            for (int ks = 0; ks < 4; ++ks) {
                uint32_t acc = (kt > 0 || ks > 0) ? 1u : 0u;
#pragma unroll
                for (int mh = 0; mh < 2; ++mh) {
                    uint64_t amd = ad + mh * 1024 + ks * 2;
#pragma unroll
                    for (int j = 0; j < 4; ++j) {
                        uint64_t bd = (j < 2) ? (b0 + j * 512 + ks * 2)
                                              : (b1 + (j - 2) * 512 + ks * 2);
                        mma_n64(tmem + mh * 256 + j * 64, amd, bd, acc);
                    }
                }
            }
            TC_COMMIT(mdone[s]);
        }
        if (kt + 2 < KT2) {
            if (kt >= 1)
                MBAR_WAIT(mdone[(kt - 1) % 3], ((kt - 1) / 3) & 1);
            load_stage((kt + 2) % 3, kt + 2);
        }
    }
    MBAR_WAIT(mdone[(KT2 - 1) % 3], ((KT2 - 1) / 3) & 1);
    TC_FENCE_AFTER();

    int mh = wid >> 2, sp = wid & 3;
    int row = mh * 128 + sp * 32 + lane;
    bool valid = (m0 + row) < cnt;
    int slot = off + m0 + row; if (slot > NPAIRS - 1) slot = NPAIRS - 1;
    float w = g_row_weight[slot];
    float* dst = g_pout + (size_t)g_s2p[slot] * HIDDEN + n0;
    uint32_t tb = tmem + mh * 256;
#pragma unroll
    for (int cb = 0; cb < 8; ++cb) {
        int c0 = cb * 32;
        uint32_t r[32];
        LDTM_X32(r, tb + c0);
        TC_WAIT_LD();
        if (valid) {
#pragma unroll
            for (int i = 0; i < 32; i += 4) {
                float4 v;
                ((float*)&v)[0] = __uint_as_float(r[i])     * w;
                ((float*)&v)[1] = __uint_as_float(r[i + 1]) * w;
                ((float*)&v)[2] = __uint_as_float(r[i + 2]) * w;
                ((float*)&v)[3] = __uint_as_float(r[i + 3]) * w;
                *(float4*)(dst + c0 + i) = v;
            }
        }
    }
    __syncthreads();
    if (wid == 0) TC_DEALLOC(tmem, 512);
#endif
}

// ---------------- verifiers (tiled weight layout) ----------------
__global__ void verify1_kernel() {
    if (g_amode == 0) { if (threadIdx.x == 0) g_ok1 = 0; return; }
    int j = threadIdx.x * 24;
    int e = 0;
    while (g_offsets[e + 1] < 1) ++e;
    int tok = g_row_token[0];
    const float* h = g_hid + (size_t)tok * HIDDEN;
    float ag = 0.f, au = 0.f;
    for (int k = 0; k < HIDDEN; ++k) {
        ag += h[k] * wt_read(g_wtg, 6, KT1, e, j, k);
        au += h[k] * wt_read(g_wtu, 6, KT1, e, j, k);
    }
    float ref = f2tf(ag / (1.f + expf(-ag)) * au);
    float d = fabsf(g_act[j] - ref), r = fabsf(ref);
#pragma unroll
    for (int o = 16; o; o >>= 1) {
        d += __shfl_xor_sync(~0u, d, o);
        r += __shfl_xor_sync(~0u, r, o);
    }
    if (threadIdx.x == 0) g_ok1 = (d <= 0.02f * r + 1e-2f) ? 1 : 0;
}
__global__ void verify2_kernel() {
    if (g_ok1 == 0) { if (threadIdx.x == 0) g_ok2 = 0; return; }
    int n = threadIdx.x * 64;
    int e = 0;
    while (g_offsets[e + 1] < 1) ++e;
    int p = g_s2p[0];
    float w = g_row_weight[0];
    float acc = 0.f;
    for (int k = 0; k < INTER; ++k)
        acc += g_act[k] * wt_read(g_wtd, 16, KT2, e, n, k);
    float ref = acc * w;
    float d = fabsf(g_pout[(size_t)p * HIDDEN + n] - ref), r = fabsf(ref);
#pragma unroll
    for (int o = 16; o; o >>= 1) {
        d += __shfl_xor_sync(~0u, d, o);
        r += __shfl_xor_sync(~0u, r, o);
    }
    if (threadIdx.x == 0) g_ok2 = (d <= 0.02f * r + 1e-2f) ? 1 : 0;
}

// ================= legacy mma.sync fallback =================
#define MMA_TF32(c, a, b)                                                     \
    asm volatile(                                                             \
        "mma.sync.aligned.m16n8k8.row.col.f32.tf32.tf32.f32 "                 \
        "{%0,%1,%2,%3},{%4,%5,%6,%7},{%8,%9},{%0,%1,%2,%3};"                  \
        : "+f"((c)[0]), "+f"((c)[1]), "+f"((c)[2]), "+f"((c)[3])              \
        : "r"((a)[0]), "r"((a)[1]), "r"((a)[2]), "r"((a)[3]),                 \
          "r"((b)[0]), "r"((b)[1]))

__global__ void __launch_bounds__(256, 2)
gemm1_legacy(const float* __restrict__ gate_w, const float* __restrict__ up_w) {
    if (g_ok1) return;
    int e = blockIdx.z;
    int off = g_offsets[e], cnt = g_offsets[e + 1] - off;
    int m0 = blockIdx.x * 128;
    if (m0 >= cnt) return;
    int n0 = blockIdx.y * 64;

    __shared__ float sA [2][128][20];
    __shared__ float sBg[2][16][68];
    __shared__ float sBu[2][16][68];

    int tid = threadIdx.x;
    const size_t wbase = (size_t)e * HIDDEN * INTER;
    int maxslot = off + cnt - 1;

    const float* asrc[2]; int arowi[2], akc[2];
#pragma unroll
    for (int j = 0; j < 2; ++j) {
        int c = tid + j * 256;
        int row = c >> 2, kc = (c & 3) << 2;
        int slot = off + m0 + row; if (slot > maxslot) slot = maxslot;
        asrc[j] = g_hid + (size_t)g_row_token[slot] * HIDDEN + kc;
        arowi[j] = row; akc[j] = kc;
    }
    int bkr = tid >> 4, bnc = (tid & 15) << 2;
    const float* gsrc = gate_w + wbase + (size_t)bkr * INTER + n0 + bnc;
    const float* usrc = up_w   + wbase + (size_t)bkr * INTER + n0 + bnc;

    auto load_tile = [&](int s, int k0) {
#pragma unroll
        for (int j = 0; j < 2; ++j)
            CP16(smem_u32(&sA[s][arowi[j]][akc[j]]), asrc[j] + k0);
        CP16(smem_u32(&sBg[s][bkr][bnc]), gsrc + (size_t)k0 * INTER);
        CP16(smem_u32(&sBu[s][bkr][bnc]), usrc + (size_t)k0 * INTER);
    };

    float cg[2][4][4] = {}, cu[2][4][4] = {};
    int warp = tid >> 5, lane = tid & 31;
    int wm = warp >> 1, wn = warp & 1;
    int gid = lane >> 2, tig = lane & 3;

    load_tile(0, 0); CP_COMMIT;
    const int KT = HIDDEN / 16;
    for (int kt = 0; kt < KT; ++kt) {
        int s = kt & 1;
        if (kt + 1 < KT) { load_tile(s ^ 1, (kt + 1) * 16); CP_COMMIT; CP_WAIT(1); }
        else             { CP_WAIT(0); }
        __syncthreads();
#pragma unroll
        for (int ks = 0; ks < 2; ++ks) {
            int k8 = ks * 8;
            uint32_t af[2][4];
#pragma unroll
            for (int mt = 0; mt < 2; ++mt) {
                int r = wm * 32 + mt * 16;
                af[mt][0] = f2tfu(sA[s][r + gid    ][k8 + tig    ]);
                af[mt][1] = f2tfu(sA[s][r + gid + 8][k8 + tig    ]);
                af[mt][2] = f2tfu(sA[s][r + gid    ][k8 + tig + 4]);
                af[mt][3] = f2tfu(sA[s][r + gid + 8][k8 + tig + 4]);
            }
            uint32_t bg[4][2], bu[4][2];
#pragma unroll
            for (int nt = 0; nt < 4; ++nt) {
                int cix = wn * 32 + nt * 8 + gid;
                bg[nt][0] = f2tfu(sBg[s][k8 + tig    ][cix]);
                bg[nt][1] = f2tfu(sBg[s][k8 + tig + 4][cix]);
                bu[nt][0] = f2tfu(sBu[s][k8 + tig    ][cix]);
                bu[nt][1] = f2tfu(sBu[s][k8 + tig + 4][cix]);
            }
#pragma unroll
            for (int mt = 0; mt < 2; ++mt)
#pragma unroll
                for (int nt = 0; nt < 4; ++nt) {
                    MMA_TF32(cg[mt][nt], af[mt], bg[nt]);
                    MMA_TF32(cu[mt][nt], af[mt], bu[nt]);
                }
        }
        __syncthreads();
    }
#pragma unroll
    for (int mt = 0; mt < 2; ++mt) {
#pragma unroll
        for (int i = 0; i < 4; ++i) {
            int row  = wm * 32 + mt * 16 + gid + ((i >> 1) << 3);
            int srow = m0 + row;
            if (srow >= cnt) continue;
            size_t base = (size_t)(off + srow) * INTER + n0 + wn * 32;
#pragma unroll
            for (int nt = 0; nt < 4; ++nt) {
                float g = cg[mt][nt][i], u = cu[mt][nt][i];
                g_act[base + nt * 8 + 2 * tig + (i & 1)] = f2tf(g / (1.f + __expf(-g)) * u);
            }
        }
    }
}

__global__ void __launch_bounds__(256, 2)
gemm2_legacy(const float* __restrict__ down_w) {
    if (g_ok2) return;
    int e = blockIdx.z;
    int off = g_offsets[e], cnt = g_offsets[e + 1] - off;
    int m0 = blockIdx.x * 128;
    if (m0 >= cnt) return;
    int n0 = blockIdx.y * 128;

    __shared__ float sA[2][128][20];
    __shared__ float sB[2][16][132];

    int tid = threadIdx.x;
    const size_t wbase = (size_t)e * INTER * HIDDEN;

    const float* asrc[2]; int arowi[2], akc[2];
#pragma unroll
    for (int j = 0; j < 2; ++j) {
        int c = tid + j * 256;
        int row = c >> 2, kc = (c & 3) << 2;
        int ar = off + m0 + row; if (ar > NPAIRS - 1) ar = NPAIRS - 1;
        asrc[j] = g_act + (size_t)ar * INTER + kc;
        arowi[j] = row; akc[j] = kc;
    }
    const float* bsrc[2]; int bkri[2], bnci[2];
#pragma unroll
    for (int j = 0; j < 2; ++j) {
        int c = tid + j * 256;
        int kr = c >> 5, nc = (c & 31) << 2;
        bsrc[j] = down_w + wbase + (size_t)kr * HIDDEN + n0 + nc;
        bkri[j] = kr; bnci[j] = nc;
    }
    auto load_tile = [&](int s, int k0) {
#pragma unroll
        for (int j = 0; j < 2; ++j)
            CP16(smem_u32(&sA[s][arowi[j]][akc[j]]), asrc[j] + k0);
#pragma unroll
        for (int j = 0; j < 2; ++j)
            CP16(smem_u32(&sB[s][bkri[j]][bnci[j]]), bsrc[j] + (size_t)k0 * HIDDEN);
    };

    float acc[2][8][4] = {};
    int warp = tid >> 5, lane = tid & 31;
    int wm = warp >> 1, wn = warp & 1;
    int gid = lane >> 2, tig = lane & 3;

    load_tile(0, 0); CP_COMMIT;
    const int KT = INTER / 16;
    for (int kt = 0; kt < KT; ++kt) {
        int s = kt & 1;
        if (kt + 1 < KT) { load_tile(s ^ 1, (kt + 1) * 16); CP_COMMIT; CP_WAIT(1); }
        else             { CP_WAIT(0); }
        __syncthreads();
#pragma unroll
        for (int ks = 0; ks < 2; ++ks) {
            int k8 = ks * 8;
            uint32_t af[2][4];
#pragma unroll
            for (int mt = 0; mt < 2; ++mt) {
                int r = wm * 32 + mt * 16;
                af[mt][0] = f2tfu(sA[s][r + gid    ][k8 + tig    ]);
                af[mt][1] = f2tfu(sA[s][r + gid + 8][k8 + tig    ]);
                af[mt][2] = f2tfu(sA[s][r + gid    ][k8 + tig + 4]);
                af[mt][3] = f2tfu(sA[s][r + gid + 8][k8 + tig + 4]);
            }
            uint32_t bf[8][2];
#pragma unroll
            for (int nt = 0; nt < 8; ++nt) {
                int cix = wn * 64 + nt * 8 + gid;
                bf[nt][0] = f2tfu(sB[s][k8 + tig    ][cix]);
                bf[nt][1] = f2tfu(sB[s][k8 + tig + 4][cix]);
            }
#pragma unroll
            for (int mt = 0; mt < 2; ++mt)
#pragma unroll
                for (int nt = 0; nt < 8; ++nt)
                    MMA_TF32(acc[mt][nt], af[mt], bf[nt]);
        }
        __syncthreads();
    }
#pragma unroll
    for (int mt = 0; mt < 2; ++mt) {
#pragma unroll
        for (int i = 0; i < 4; ++i) {
            int row  = wm * 32 + mt * 16 + gid + ((i >> 1) << 3);
            int srow = m0 + row;
            if (srow >= cnt) continue;
            int slot = off + srow;
            float w  = g_row_weight[slot];
            float* orow = g_pout + (size_t)g_s2p[slot] * HIDDEN + n0 + wn * 64;
#pragma unroll
            for (int nt = 0; nt < 8; ++nt)
                orow[nt * 8 + 2 * tig + (i & 1)] = acc[mt][nt][i] * w;
        }
    }
}

// ---------------- combine ----------------
__global__ void combine_kernel(float* __restrict__ out) {
    int t = blockIdx.x, c = threadIdx.x;
    const float* base = g_pout + (size_t)t * TOPK * HIDDEN + c * 4;
    float4 acc = make_float4(0.f, 0.f, 0.f, 0.f);
#pragma unroll
    for (int k = 0; k < TOPK; ++k) {
        float4 v = *(const float4*)(base + (size_t)k * HIDDEN);
        acc.x += v.x; acc.y += v.y; acc.z += v.z; acc.w += v.w;
    }
    *(float4*)(out + (size_t)t * HIDDEN + c * 4) = acc;
}

// ---------------- launch ----------------
extern "C" void kernel_launch(void* const* d_in, const int* in_sizes, int n_in,
                              void* d_out, int out_size) {
    const float* hidden = (const float*)d_in[0];
    const float* logits = (const float*)d_in[1];
    const float* gate   = (const float*)d_in[2];
    const float* up     = (const float*)d_in[3];
    const float* down   = (const float*)d_in[4];
    float* out = (float*)d_out;

    cudaFuncSetAttribute(gemm1_tc, cudaFuncAttributeMaxDynamicSharedMemorySize, 3 * STG + 1024);
    cudaFuncSetAttribute(gemm2_tc, cudaFuncAttributeMaxDynamicSharedMemorySize, 3 * STG + 1024);

    float *wtg, *wtu, *wtd, *rh;
    cudaGetSymbolAddress((void**)&wtg, g_wtg);
    cudaGetSymbolAddress((void**)&wtu, g_wtu);
    cudaGetSymbolAddress((void**)&wtd, g_wtd);
    cudaGetSymbolAddress((void**)&rh,  g_hid);

    selftest_kernel <<<1, 128>>>();
    selftest2_kernel<<<1, 128>>>();
    rnd_kernel      <<<2048, 512>>>((const float4*)hidden, (float4*)rh, TOKENS * HIDDEN / 4);
    tile_kernel     <<<dim3(HIDDEN / 32, INTER / 32, NEXP), 256>>>(gate, wtg, HIDDEN, INTER, 6, KT1);
    tile_kernel     <<<dim3(HIDDEN / 32, INTER / 32, NEXP), 256>>>(up,   wtu, HIDDEN, INTER, 6, KT1);
    tile_kernel     <<<dim3(INTER / 32, HIDDEN / 32, NEXP), 256>>>(down, wtd, INTER, HIDDEN, 16, KT2);
    init_kernel     <<<1, 64>>>();
    route_kernel    <<<TOKENS / 256, 256>>>(logits);
    scan_kernel     <<<1, 32>>>();
    scatter_kernel  <<<NPAIRS / 256, 256>>>();
    gemm1_tc        <<<dim3(MCAP / 256, INTER / 128, NEXP), 256, 3 * STG + 1024>>>();
    verify1_kernel  <<<1, 32>>>();
    gemm1_legacy    <<<dim3(MCAP / 128, INTER / 64,  NEXP), 256>>>(gate, up);
    gemm2_tc        <<<dim3(MCAP / 256, HIDDEN / 256, NEXP), 256, 3 * STG + 1024>>>();
    verify2_kernel  <<<1, 32>>>();
    gemm2_legacy    <<<dim3(MCAP / 128, HIDDEN / 128, NEXP), 256>>>(down);
    combine_kernel  <<<TOKENS, 512>>>(out);
}

// round 10
// speedup vs baseline: 1.3786x; 1.3786x over previous
#include <cuda_runtime.h>
#include <cstdint>

#if defined(__CUDA_ARCH_FEAT_SM103_ALL) || defined(__CUDA_ARCH_FEAT_SM100_ALL) || defined(__CUDA_ARCH_FEAT_SM101_ALL)
#define TC_OK 1
#endif

#define TOKENS 4096
#define HIDDEN 2048
#define INTER  768
#define NEXP   64
#define TOPK   8
#define NPAIRS (TOKENS*TOPK)
#define MCAP   2048
#define BK     32
#define STG    65536        // stage: A 2x16KB + B 2x16KB
#define KT1    (HIDDEN/BK)  // 64
#define KT2    (INTER/BK)   // 24
#define WSZ    100663296
#define PBMAX  320

__device__ int   g_tc_ok;
__device__ int   g_ok1;
__device__ int   g_ok2;
__device__ int   g_counts[NEXP];
__device__ int   g_offsets[NEXP+1];
__device__ int   g_poff[NEXP+1];
__device__ int   g_cursor[NEXP];
__device__ int   g_pair_e[NPAIRS];
__device__ float g_pair_w[NPAIRS];
__device__ int   g_row_token[NPAIRS];
__device__ float g_row_weight[NPAIRS];
__device__ int   g_s2p[NPAIRS];
__device__ float g_act[(size_t)PBMAX * 128 * INTER];    // ALWAYS tiled [pb][kk24][16KB]
__device__ float g_pout[(size_t)NPAIRS * HIDDEN];
__device__ float g_hid[(size_t)TOKENS * HIDDEN];
__device__ float g_hs[(size_t)PBMAX * 128 * HIDDEN];    // gathered A, tiled [pb][kk64][16KB]
__device__ float g_wtg[WSZ];   // gate^T tiled [e][nb6][kk64][16KB]
__device__ float g_wtu[WSZ];
__device__ float g_wtd[WSZ];   // down^T tiled [e][nb16][kk24][16KB]

__device__ __forceinline__ uint32_t smem_u32(const void* p) {
    return (uint32_t)__cvta_generic_to_shared(p);
}
__device__ __forceinline__ float f2tf(float x) {
    uint32_t r;
    asm("cvt.rna.tf32.f32 %0, %1;" : "=r"(r) : "f"(x));
    return __uint_as_float(r);
}
__device__ __forceinline__ uint32_t f2tfu(float x) {
    uint32_t r;
    asm("cvt.rna.tf32.f32 %0, %1;" : "=r"(r) : "f"(x));
    return r;
}
#define SW128(o) ((o) ^ (((o) >> 3) & 0x70))
#define CP16(d, s) asm volatile("cp.async.cg.shared.global [%0], [%1], 16;\n" :: "r"(d), "l"(s))
#define CP_COMMIT  asm volatile("cp.async.commit_group;\n")
#define CP_WAIT(n) asm volatile("cp.async.wait_group %0;\n" :: "n"(n))
#define MBAR_INIT(mb, c) asm volatile("mbarrier.init.shared.b64 [%0], %1;" :: "r"(mb), "r"(c) : "memory")
#define MBAR_ARRIVE_TX(mb, tx) asm volatile("mbarrier.arrive.expect_tx.shared.b64 _, [%0], %1;" :: "r"(mb), "r"(tx) : "memory")
#define BULK_G2S(dst, src, sz, mb)                                            \
    asm volatile("cp.async.bulk.shared::cluster.global.mbarrier::complete_tx::bytes [%0], [%1], %2, [%3];" \
                 :: "r"(dst), "l"(src), "r"(sz), "r"(mb) : "memory")
#define MBAR_WAIT(mb, ph)                                                     \
    asm volatile("{\n\t.reg .pred P1;\n\t"                                    \
        "WL_%=:\n\t"                                                          \
        "mbarrier.try_wait.parity.acquire.cta.shared::cta.b64 P1, [%0], %1, 0x989680;\n\t" \
        "@P1 bra.uni WD_%=;\n\t"                                              \
        "bra.uni WL_%=;\n\t"                                                  \
        "WD_%=:\n\t}" :: "r"(mb), "r"(ph) : "memory")

#ifdef TC_OK
#define TC_ALLOC(sm, n)  asm volatile("tcgen05.alloc.cta_group::1.sync.aligned.shared::cta.b32 [%0], %1;" :: "r"(sm), "r"(n) : "memory")
#define TC_DEALLOC(t, n) asm volatile("tcgen05.dealloc.cta_group::1.sync.aligned.b32 %0, %1;" :: "r"(t), "r"(n))
#define TC_RELINQ()      asm volatile("tcgen05.relinquish_alloc_permit.cta_group::1.sync.aligned;")
#define TC_COMMIT(mb)    asm volatile("tcgen05.commit.cta_group::1.mbarrier::arrive::one.shared::cluster.b64 [%0];" :: "r"(mb) : "memory")
#define TC_FENCE_AFTER() asm volatile("tcgen05.fence::after_thread_sync;" ::: "memory")
#define TC_WAIT_LD()     asm volatile("tcgen05.wait::ld.sync.aligned;" ::: "memory")
#define FENCE_ASYNC()    asm volatile("fence.proxy.async.shared::cta;" ::: "memory")
#define LDTM_X32(r, a)                                                        \
    asm volatile("tcgen05.ld.sync.aligned.32x32b.x32.b32 "                    \
        "{%0,%1,%2,%3,%4,%5,%6,%7,%8,%9,%10,%11,%12,%13,%14,%15,"             \
        "%16,%17,%18,%19,%20,%21,%22,%23,%24,%25,%26,%27,%28,%29,%30,%31},[%32];" \
        : "=r"((r)[0]),"=r"((r)[1]),"=r"((r)[2]),"=r"((r)[3]),                \
          "=r"((r)[4]),"=r"((r)[5]),"=r"((r)[6]),"=r"((r)[7]),                \
          "=r"((r)[8]),"=r"((r)[9]),"=r"((r)[10]),"=r"((r)[11]),              \
          "=r"((r)[12]),"=r"((r)[13]),"=r"((r)[14]),"=r"((r)[15]),            \
          "=r"((r)[16]),"=r"((r)[17]),"=r"((r)[18]),"=r"((r)[19]),            \
          "=r"((r)[20]),"=r"((r)[21]),"=r"((r)[22]),"=r"((r)[23]),            \
          "=r"((r)[24]),"=r"((r)[25]),"=r"((r)[26]),"=r"((r)[27]),            \
          "=r"((r)[28]),"=r"((r)[29]),"=r"((r)[30]),"=r"((r)[31]) : "r"(a))

__device__ __forceinline__ uint64_t desc_k(uint32_t a) {     // SW128 K-major
    return (uint64_t(2) << 61) | (uint64_t(1) << 46) | (uint64_t(64) << 32) |
           (uint64_t(1) << 16) | ((uint64_t)(a >> 4) & 0x3FFF);
}
#define IDESC32 ((1u<<4)|(2u<<7)|(2u<<10)|(4u<<17)|(8u<<24))
#define IDESC64 ((1u<<4)|(2u<<7)|(2u<<10)|(8u<<17)|(8u<<24))
__device__ __forceinline__ void mma_n32(uint32_t d, uint64_t ad, uint64_t bd, uint32_t acc) {
    asm volatile(
        "{\n\t.reg .pred p;\n\tsetp.ne.u32 p, %4, 0;\n\t"
        "tcgen05.mma.cta_group::1.kind::tf32 [%0], %1, %2, %3, {%5,%5,%5,%5}, p;\n\t}"
        :: "r"(d), "l"(ad), "l"(bd), "r"(IDESC32), "r"(acc), "r"(0u) : "memory");
}
__device__ __forceinline__ void mma_n64(uint32_t d, uint64_t ad, uint64_t bd, uint32_t acc) {
    asm volatile(
        "{\n\t.reg .pred p;\n\tsetp.ne.u32 p, %4, 0;\n\t"
        "tcgen05.mma.cta_group::1.kind::tf32 [%0], %1, %2, %3, {%5,%5,%5,%5}, p;\n\t}"
        :: "r"(d), "l"(ad), "l"(bd), "r"(IDESC64), "r"(acc), "r"(0u) : "memory");
}
#endif

// ---------------- tiled-layout helpers ----------------
__device__ __forceinline__ float wt_read(const float* wt, int NB, int KK, int e, int n, int k) {
    size_t tile = ((size_t)e * NB + (n >> 7)) * KK + (k >> 5);
    uint32_t inner = SW128((uint32_t)(((n & 127) << 7) + ((k & 31) << 2)));
    return *(const float*)((const char*)wt + tile * 16384 + inner);
}
__device__ __forceinline__ char* act_addr(int ps, int k) {
    size_t tile = (size_t)(ps >> 7) * KT2 + (k >> 5);
    uint32_t inner = SW128((uint32_t)(((ps & 127) << 7) + ((k & 31) << 2)));
    return (char*)g_act + tile * 16384 + inner;
}
__device__ __forceinline__ float act_read(int ps, int k) {
    return *(const float*)act_addr(ps, k);
}

// ---------------- self-test ----------------
__device__ __forceinline__ float tva(int m, int k) {
    return f2tf(0.01f * (float)((m * 7 + k * 13) % 31 - 15));
}
__device__ __forceinline__ float tvb(int n, int k) {
    return f2tf(0.02f * (float)((n * 5 + k * 3) % 29 - 14));
}
__global__ void selftest_kernel() {
#ifdef TC_OK
    __shared__ __align__(1024) float sma[4096];
    __shared__ __align__(1024) float smb[1024];
    __shared__ uint32_t s_tmem[1];
    __shared__ __align__(8) uint64_t s_mbar[1];
    __shared__ float s_d, s_r;
    int tid = threadIdx.x, wid = tid >> 5, lane = tid & 31;

    if (wid == 0) { TC_ALLOC(smem_u32(s_tmem), 128); TC_RELINQ(); }
    if (tid == 0) { MBAR_INIT(smem_u32(s_mbar), 1); s_d = 0.f; s_r = 0.f; }
    for (int idx = tid; idx < 4096; idx += 128) {
        int m = idx >> 5, k = idx & 31;
        *(float*)((char*)sma + SW128((uint32_t)(m * 128 + k * 4))) = tva(m, k);
    }
    for (int idx = tid; idx < 1024; idx += 128) {
        int n = idx >> 5, k = idx & 31;
        *(float*)((char*)smb + SW128((uint32_t)(n * 128 + k * 4))) = tvb(n, k);
    }
    __syncthreads();
    uint32_t tmem = s_tmem[0], mb = smem_u32(s_mbar);
    if (tid == 0) {
        FENCE_ASYNC();
        uint64_t ad = desc_k(smem_u32(sma)), bd = desc_k(smem_u32(smb));
#pragma unroll
        for (int ks = 0; ks < 4; ++ks)
            mma_n32(tmem, ad + ks * 2, bd + ks * 2, ks > 0 ? 1u : 0u);
        TC_COMMIT(mb);
    }
    __syncthreads();
    MBAR_WAIT(mb, 0);
    TC_FENCE_AFTER();
    uint32_t r[32];
    LDTM_X32(r, tmem);
    TC_WAIT_LD();
    int m = wid * 32 + lane;
    float d = 0.f, rf = 0.f;
#pragma unroll 4
    for (int n = 0; n < 32; ++n) {
        float ref = 0.f;
        for (int k = 0; k < 32; ++k) ref += tva(m, k) * tvb(n, k);
        d  += fabsf(__uint_as_float(r[n]) - ref);
        rf += fabsf(ref);
    }
    atomicAdd(&s_d, d); atomicAdd(&s_r, rf);
    __syncthreads();
    if (tid == 0) g_tc_ok = (s_d <= 0.01f * s_r + 1e-3f) ? 1 : 0;
    __syncthreads();
    if (wid == 0) TC_DEALLOC(tmem, 128);
#else
    if (threadIdx.x == 0) g_tc_ok = 0;
#endif
}

// ---------------- prep ----------------
__global__ void rnd_kernel(const float4* __restrict__ src, float4* __restrict__ dst, int n4) {
    int i = blockIdx.x * blockDim.x + threadIdx.x, st = gridDim.x * blockDim.x;
    for (; i < n4; i += st) {
        float4 v = src[i];
        v.x = f2tf(v.x); v.y = f2tf(v.y); v.z = f2tf(v.z); v.w = f2tf(v.w);
        dst[i] = v;
    }
}
__global__ void tile_kernel(const float* __restrict__ src, float* __restrict__ dst,
                            int K, int N, int NB, int KK) {
    if (g_tc_ok == 0) return;
    __shared__ float t[32][33];
    int e = blockIdx.z;
    int k0 = blockIdx.x * 32, n0 = blockIdx.y * 32;
    int r = threadIdx.x >> 3, c4 = (threadIdx.x & 7) << 2;
    float4 v = *(const float4*)(src + ((size_t)e * K + k0 + r) * N + n0 + c4);
    t[r][c4] = v.x; t[r][c4 + 1] = v.y; t[r][c4 + 2] = v.z; t[r][c4 + 3] = v.w;
    __syncthreads();
    int n = n0 + r;
    size_t tile = ((size_t)e * NB + (n >> 7)) * KK + (k0 >> 5);
    uint32_t inner = SW128((uint32_t)(((n & 127) << 7) + (c4 << 2)));
    float4 o;
    o.x = f2tf(t[c4    ][r]);
    o.y = f2tf(t[c4 + 1][r]);
    o.z = f2tf(t[c4 + 2][r]);
    o.w = f2tf(t[c4 + 3][r]);
    *(float4*)((char*)dst + tile * 16384 + inner) = o;
}
__global__ void init_kernel() { if (threadIdx.x < NEXP) g_counts[threadIdx.x] = 0; }

__global__ void route_kernel(const float* __restrict__ logits) {
    int t = blockIdx.x * blockDim.x + threadIdx.x;
    if (t >= TOKENS) return;
    float l[NEXP];
    const float* lp = logits + (size_t)t * NEXP;
#pragma unroll
    for (int i = 0; i < NEXP; ++i) l[i] = lp[i];
    float val[TOPK]; int sel[TOPK];
#pragma unroll
    for (int k = 0; k < TOPK; ++k) {
        float best = -1e30f; int bi = 0;
#pragma unroll
        for (int i = 0; i < NEXP; ++i)
            if (l[i] > best) { best = l[i]; bi = i; }
        val[k] = best; sel[k] = bi; l[bi] = -1e30f;
    }
    float m = val[0], s = 0.f, w[TOPK];
#pragma unroll
    for (int k = 0; k < TOPK; ++k) { w[k] = __expf(val[k] - m); s += w[k]; }
    float inv = 1.f / s;
#pragma unroll
    for (int k = 0; k < TOPK; ++k) {
        g_pair_e[t * TOPK + k] = sel[k];
        g_pair_w[t * TOPK + k] = w[k] * inv;
        atomicAdd(&g_counts[sel[k]], 1);
    }
}
__global__ void scan_kernel() {
    if (threadIdx.x == 0) {
        int acc = 0, pacc = 0;
        for (int e = 0; e < NEXP; ++e) {
            g_offsets[e] = acc; g_cursor[e] = acc;
            g_poff[e] = pacc;
            acc += g_counts[e];
            pacc += (g_counts[e] + 127) & ~127;
        }
        g_offsets[NEXP] = acc;
        g_poff[NEXP] = pacc;
    }
}
__global__ void scatter_kernel() {
    int p = blockIdx.x * blockDim.x + threadIdx.x;
    if (p >= NPAIRS) return;
    int slot = atomicAdd(&g_cursor[g_pair_e[p]], 1);
    g_row_token[slot]  = p >> 3;
    g_row_weight[slot] = g_pair_w[p];
    g_s2p[slot] = p;
}
__global__ void gather_kernel(const float* __restrict__ hidden) {
    if (g_tc_ok == 0) return;
    int pb = blockIdx.x, kk = blockIdx.y;
    __shared__ int s_e;
    if (threadIdx.x == 0) {
        int e = 0;
        while (e < NEXP && !(g_poff[e] <= pb * 128 && pb * 128 < g_poff[e + 1])) ++e;
        s_e = e;
    }
    __syncthreads();
    int e = s_e;
    if (e >= NEXP) return;
    int off = g_offsets[e], cnt = g_counts[e];
    char* tile = (char*)g_hs + ((size_t)pb * KT1 + kk) * 16384;
#pragma unroll
    for (int j = 0; j < 4; ++j) {
        int f = threadIdx.x + j * 256;
        int row = f >> 3, c = f & 7;
        int lidx = pb * 128 + row - g_poff[e];
        if (lidx > cnt - 1) lidx = cnt - 1;
        int token = g_row_token[off + lidx];
        float4 v = *(const float4*)(hidden + (size_t)token * HIDDEN + kk * 32 + c * 4);
        v.x = f2tf(v.x); v.y = f2tf(v.y); v.z = f2tf(v.z); v.w = f2tf(v.w);
        *(float4*)(tile + SW128((uint32_t)(row * 128 + c * 16))) = v;
    }
}

// ============ tcgen05 GEMM1: M=256, N=128 (gate+up), 3-stage all-bulk ======
__global__ void __launch_bounds__(256, 1)
gemm1_tc() {
#ifdef TC_OK
    if (g_tc_ok == 0) return;
    int e = blockIdx.z;
    int off = g_offsets[e], cnt = g_offsets[e + 1] - off;
    int m0 = blockIdx.x * 256;
    if (m0 >= cnt) return;
    int nb = blockIdx.y;
    int n0 = nb * 128;

    extern __shared__ char dyn[];
    uint32_t sbase = (smem_u32(dyn) + 1023u) & ~1023u;
    __shared__ uint32_t s_tmem[1];
    __shared__ __align__(8) uint64_t s_full[3], s_mdone[3];
    int tid = threadIdx.x, wid = tid >> 5, lane = tid & 31;

    if (wid == 0) { TC_ALLOC(smem_u32(s_tmem), 512); TC_RELINQ(); }
    if (tid == 0) {
#pragma unroll
        for (int i = 0; i < 3; ++i) {
            MBAR_INIT(smem_u32(&s_full[i]), 1);
            MBAR_INIT(smem_u32(&s_mdone[i]), 1);
        }
    }
    __syncthreads();
    uint32_t tmem = s_tmem[0];

    if (tid == 0) {
        uint32_t full[3]  = { smem_u32(&s_full[0]),  smem_u32(&s_full[1]),  smem_u32(&s_full[2])  };
        uint32_t mdone[3] = { smem_u32(&s_mdone[0]), smem_u32(&s_mdone[1]), smem_u32(&s_mdone[2]) };
        int pb = (g_poff[e] + m0) >> 7;
        const char* a0 = (const char*)g_hs + ((size_t)pb       * KT1) * 16384;
        const char* a1 = (const char*)g_hs + ((size_t)(pb + 1) * KT1) * 16384;
        const char* tg = (const char*)g_wtg + (((size_t)e * 6 + nb) * KT1) * 16384;
        const char* tu = (const char*)g_wtu + (((size_t)e * 6 + nb) * KT1) * 16384;

        auto load_stage = [&](int s, int kt) {
            uint32_t sb = sbase + s * STG;
            MBAR_ARRIVE_TX(full[s], 65536u);
            BULK_G2S(sb,           a0 + (size_t)kt * 16384, 16384u, full[s]);
            BULK_G2S(sb + 16384u,  a1 + (size_t)kt * 16384, 16384u, full[s]);
            BULK_G2S(sb + 32768u,  tg + (size_t)kt * 16384, 16384u, full[s]);
            BULK_G2S(sb + 49152u,  tu + (size_t)kt * 16384, 16384u, full[s]);
        };
        load_stage(0, 0);
        load_stage(1, 1);
        for (int kt = 0; kt < KT1; ++kt) {
            int s = kt % 3;
            MBAR_WAIT(full[s], (kt / 3) & 1);
            FENCE_ASYNC();
            uint32_t sb = sbase + s * STG;
            uint64_t ad = desc_k(sb);
            uint64_t bg = desc_k(sb + 32768u), bu = desc_k(sb + 49152u);
#pragma unroll
            for (int ks = 0; ks < 4; ++ks) {
                uint32_t acc = (kt > 0 || ks > 0) ? 1u : 0u;
#pragma unroll
                for (int mh = 0; mh < 2; ++mh) {
                    uint64_t amd = ad + mh * 1024 + ks * 2;
#pragma unroll
                    for (int j = 0; j < 2; ++j) {
                        mma_n64(tmem + mh * 256 + j * 64,       amd, bg + j * 512 + ks * 2, acc);
                        mma_n64(tmem + mh * 256 + 128 + j * 64, amd, bu + j * 512 + ks * 2, acc);
                    }
                }
            }
            TC_COMMIT(mdone[s]);
            if (kt + 2 < KT1) {
                if (kt >= 1)
                    MBAR_WAIT(mdone[(kt - 1) % 3], ((kt - 1) / 3) & 1);
                load_stage((kt + 2) % 3, kt + 2);
            }
        }
        // FINAL wait by tid0 only: tid0's phase tracking is sequential, no aliasing
        MBAR_WAIT(mdone[(KT1 - 1) % 3], ((KT1 - 1) / 3) & 1);
    }
    __syncthreads();          // release epilogue warps ONLY after all MMAs done
    TC_FENCE_AFTER();

    // epilogue: swiglu -> g_act (TILED layout)
    int mh = wid >> 2, sp = wid & 3;
    int row = mh * 128 + sp * 32 + lane;
    bool valid = (m0 + row) < cnt;
    int ps = g_poff[e] + m0 + row;
    size_t tb0 = (size_t)(ps >> 7) * KT2 * 16384;
    uint32_t rinner = (uint32_t)((ps & 127) << 7);
    uint32_t tmb = tmem + mh * 256;
#pragma unroll
    for (int cb = 0; cb < 4; ++cb) {
        int c0 = cb * 32;
        uint32_t rg[32], ru[32];
        LDTM_X32(rg, tmb + c0);
        LDTM_X32(ru, tmb + 128 + c0);
        TC_WAIT_LD();
        if (valid) {
            char* tile = (char*)g_act + tb0 + (size_t)((n0 + c0) >> 5) * 16384;
#pragma unroll
            for (int i = 0; i < 32; i += 4) {
                float4 v;
#pragma unroll
                for (int q = 0; q < 4; ++q) {
                    float g = __uint_as_float(rg[i + q]);
                    float u = __uint_as_float(ru[i + q]);
                    ((float*)&v)[q] = f2tf(g / (1.f + __expf(-g)) * u);
                }
                *(float4*)(tile + SW128(rinner + i * 4)) = v;
            }
        }
    }
    __syncthreads();
    if (wid == 0) TC_DEALLOC(tmem, 512);
#endif
}

// ============ tcgen05 GEMM2: M=256, N=256, 3-stage all-bulk ================
__global__ void __launch_bounds__(256, 1)
gemm2_tc() {
#ifdef TC_OK
    if (g_ok1 == 0) return;
    int e = blockIdx.z;
    int off = g_offsets[e], cnt = g_offsets[e + 1] - off;
    int m0 = blockIdx.x * 256;
    if (m0 >= cnt) return;
    int nb0 = blockIdx.y * 2;
    int n0 = nb0 * 128;

    extern __shared__ char dyn[];
    uint32_t sbase = (smem_u32(dyn) + 1023u) & ~1023u;
    __shared__ uint32_t s_tmem[1];
    __shared__ __align__(8) uint64_t s_full[3], s_mdone[3];
    int tid = threadIdx.x, wid = tid >> 5, lane = tid & 31;

    if (wid == 0) { TC_ALLOC(smem_u32(s_tmem), 512); TC_RELINQ(); }
    if (tid == 0) {
#pragma unroll
        for (int i = 0; i < 3; ++i) {
            MBAR_INIT(smem_u32(&s_full[i]), 1);
            MBAR_INIT(smem_u32(&s_mdone[i]), 1);
        }
    }
    __syncthreads();
    uint32_t tmem = s_tmem[0];

    if (tid == 0) {
        uint32_t full[3]  = { smem_u32(&s_full[0]),  smem_u32(&s_full[1]),  smem_u32(&s_full[2])  };
        uint32_t mdone[3] = { smem_u32(&s_mdone[0]), smem_u32(&s_mdone[1]), smem_u32(&s_mdone[2]) };
        int pb = (g_poff[e] + m0) >> 7;
        const char* a0 = (const char*)g_act + ((size_t)pb       * KT2) * 16384;
        const char* a1 = (const char*)g_act + ((size_t)(pb + 1) * KT2) * 16384;
        const char* b0p = (const char*)g_wtd + (((size_t)e * 16 + nb0)     * KT2) * 16384;
        const char* b1p = (const char*)g_wtd + (((size_t)e * 16 + nb0 + 1) * KT2) * 16384;

        auto load_stage = [&](int s, int kt) {
            uint32_t sb = sbase + s * STG;
            MBAR_ARRIVE_TX(full[s], 65536u);
            BULK_G2S(sb,          a0  + (size_t)kt * 16384, 16384u, full[s]);
            BULK_G2S(sb + 16384u, a1  + (size_t)kt * 16384, 16384u, full[s]);
            BULK_G2S(sb + 32768u, b0p + (size_t)kt * 16384, 16384u, full[s]);
            BULK_G2S(sb + 49152u, b1p + (size_t)kt * 16384, 16384u, full[s]);
        };
        load_stage(0, 0);
        load_stage(1, 1);
        for (int kt = 0; kt < KT2; ++kt) {
            int s = kt % 3;
            MBAR_WAIT(full[s], (kt / 3) & 1);
            FENCE_ASYNC();
            uint32_t sb = sbase + s * STG;
            uint64_t ad = desc_k(sb);
            uint64_t b0 = desc_k(sb + 32768u), b1 = desc_k(sb + 49152u);
#pragma unroll
            for (int ks = 0; ks < 4; ++ks) {
                uint32_t acc = (kt > 0 || ks > 0) ? 1u : 0u;
#pragma unroll
                for (int mh = 0; mh < 2; ++mh) {
                    uint64_t amd = ad + mh * 1024 + ks * 2;
#pragma unroll
                    for (int j = 0; j < 4; ++j) {
                        uint64_t bd = (j < 2) ? (b0 + j * 512 + ks * 2)
                                              : (b1 + (j - 2) * 512 + ks * 2);
                        mma_n64(tmem + mh * 256 + j * 64, amd, bd, acc);
                    }
                }
            }
            TC_COMMIT(mdone[s]);
            if (kt + 2 < KT2) {
                if (kt >= 1)
                    MBAR_WAIT(mdone[(kt - 1) % 3], ((kt - 1) / 3) & 1);
                load_stage((kt + 2) % 3, kt + 2);
            }
        }
        MBAR_WAIT(mdone[(KT2 - 1) % 3], ((KT2 - 1) / 3) & 1);
    }
    __syncthreads();
    TC_FENCE_AFTER();

    int mh = wid >> 2, sp = wid & 3;
    int row = mh * 128 + sp * 32 + lane;
    bool valid = (m0 + row) < cnt;
    int slot = off + m0 + row; if (slot > NPAIRS - 1) slot = NPAIRS - 1;
    float w = g_row_weight[slot];
    float* dst = g_pout + (size_t)g_s2p[slot] * HIDDEN + n0;
    uint32_t tmb = tmem + mh * 256;
#pragma unroll
    for (int cb = 0; cb < 8; ++cb) {
        int c0 = cb * 32;
        uint32_t r[32];
        LDTM_X32(r, tmb + c0);
        TC_WAIT_LD();
        if (valid) {
#pragma unroll
            for (int i = 0; i < 32; i += 4) {
                float4 v;
                ((float*)&v)[0] = __uint_as_float(r[i])     * w;
                ((float*)&v)[1] = __uint_as_float(r[i + 1]) * w;
                ((float*)&v)[2] = __uint_as_float(r[i + 2]) * w;
                ((float*)&v)[3] = __uint_as_float(r[i + 3]) * w;
                *(float4*)(dst + c0 + i) = v;
            }
        }
    }
    __syncthreads();
    if (wid == 0) TC_DEALLOC(tmem, 512);
#endif
}

// ---------------- verifiers: rows 0 AND 150 (covers m-half 1) ----------------
__global__ void verify1_kernel() {
    if (g_tc_ok == 0) { if (threadIdx.x == 0) g_ok1 = 0; return; }
    __shared__ float sd[2], sr[2];
    int e = 0;
    while (g_offsets[e + 1] < 1) ++e;
    int cnt = g_offsets[e + 1] - g_offsets[e];
    int w = threadIdx.x >> 5, lane = threadIdx.x & 31;
    int r = (w == 0) ? 0 : (cnt > 150 ? 150 : cnt - 1);
    int tok = g_row_token[g_offsets[e] + r];
    const float* h = g_hid + (size_t)tok * HIDDEN;
    int j = lane * 24;
    float ag = 0.f, au = 0.f;
    for (int k = 0; k < HIDDEN; ++k) {
        ag += h[k] * wt_read(g_wtg, 6, KT1, e, j, k);
        au += h[k] * wt_read(g_wtu, 6, KT1, e, j, k);
    }
    float ref = f2tf(ag / (1.f + expf(-ag)) * au);
    float d = fabsf(act_read(g_poff[e] + r, j) - ref), rf = fabsf(ref);
#pragma unroll
    for (int o = 16; o; o >>= 1) {
        d  += __shfl_xor_sync(~0u, d, o);
        rf += __shfl_xor_sync(~0u, rf, o);
    }
    if (lane == 0) { sd[w] = d; sr[w] = rf; }
    __syncthreads();
    if (threadIdx.x == 0)
        g_ok1 = (sd[0] + sd[1] <= 0.02f * (sr[0] + sr[1]) + 1e-2f) ? 1 : 0;
}
__global__ void verify2_kernel() {
    if (g_ok1 == 0) { if (threadIdx.x == 0) g_ok2 = 0; return; }
    __shared__ float sd[2], sr[2];
    int e = 0;
    while (g_offsets[e + 1] < 1) ++e;
    int cnt = g_offsets[e + 1] - g_offsets[e];
    int w = threadIdx.x >> 5, lane = threadIdx.x & 31;
    int r = (w == 0) ? 0 : (cnt > 150 ? 150 : cnt - 1);
    int slot = g_offsets[e] + r;
    int p = g_s2p[slot];
    float wgt = g_row_weight[slot];
    int ps = g_poff[e] + r;
    int n = lane * 64;
    float acc = 0.f;
    for (int k = 0; k < INTER; ++k)
        acc += act_read(ps, k) * wt_read(g_wtd, 16, KT2, e, n, k);
    float ref = acc * wgt;
    float d = fabsf(g_pout[(size_t)p * HIDDEN + n] - ref), rf = fabsf(ref);
#pragma unroll
    for (int o = 16; o; o >>= 1) {
        d  += __shfl_xor_sync(~0u, d, o);
        rf += __shfl_xor_sync(~0u, rf, o);
    }
    if (lane == 0) { sd[w] = d; sr[w] = rf; }
    __syncthreads();
    if (threadIdx.x == 0)
        g_ok2 = (sd[0] + sd[1] <= 0.02f * (sr[0] + sr[1]) + 1e-2f) ? 1 : 0;
}

// ================= legacy mma.sync fallback (TILED g_act) =================
#define MMA_TF32(c, a, b)                                                     \
    asm volatile(                                                             \
        "mma.sync.aligned.m16n8k8.row.col.f32.tf32.tf32.f32 "                 \
        "{%0,%1,%2,%3},{%4,%5,%6,%7},{%8,%9},{%0,%1,%2,%3};"                  \
        : "+f"((c)[0]), "+f"((c)[1]), "+f"((c)[2]), "+f"((c)[3])              \
        : "r"((a)[0]), "r"((a)[1]), "r"((a)[2]), "r"((a)[3]),                 \
          "r"((b)[0]), "r"((b)[1]))

__global__ void __launch_bounds__(256, 2)
gemm1_legacy(const float* __restrict__ gate_w, const float* __restrict__ up_w) {
    if (g_ok1) return;
    int e = blockIdx.z;
    int off = g_offsets[e], cnt = g_offsets[e + 1] - off;
    int m0 = blockIdx.x * 128;
    if (m0 >= cnt) return;
    int n0 = blockIdx.y * 64;

    __shared__ float sA [2][128][20];
    __shared__ float sBg[2][16][68];
    __shared__ float sBu[2][16][68];

    int tid = threadIdx.x;
    const size_t wbase = (size_t)e * HIDDEN * INTER;
    int maxslot = off + cnt - 1;

    const float* asrc[2]; int arowi[2], akc[2];
#pragma unroll
    for (int j = 0; j < 2; ++j) {
        int c = tid + j * 256;
        int row = c >> 2, kc = (c & 3) << 2;
        int slot = off + m0 + row; if (slot > maxslot) slot = maxslot;
        asrc[j] = g_hid + (size_t)g_row_token[slot] * HIDDEN + kc;
        arowi[j] = row; akc[j] = kc;
    }
    int bkr = tid >> 4, bnc = (tid & 15) << 2;
    const float* gsrc = gate_w + wbase + (size_t)bkr * INTER + n0 + bnc;
    const float* usrc = up_w   + wbase + (size_t)bkr * INTER + n0 + bnc;

    auto load_tile = [&](int s, int k0) {
#pragma unroll
        for (int j = 0; j < 2; ++j)
            CP16(smem_u32(&sA[s][arowi[j]][akc[j]]), asrc[j] + k0);
        CP16(smem_u32(&sBg[s][bkr][bnc]), gsrc + (size_t)k0 * INTER);
        CP16(smem_u32(&sBu[s][bkr][bnc]), usrc + (size_t)k0 * INTER);
    };

    float cg[2][4][4] = {}, cu[2][4][4] = {};
    int warp = tid >> 5, lane = tid & 31;
    int wm = warp >> 1, wn = warp & 1;
    int gid = lane >> 2, tig = lane & 3;

    load_tile(0, 0); CP_COMMIT;
    const int KT = HIDDEN / 16;
    for (int kt = 0; kt < KT; ++kt) {
        int s = kt & 1;
        if (kt + 1 < KT) { load_tile(s ^ 1, (kt + 1) * 16); CP_COMMIT; CP_WAIT(1); }
        else             { CP_WAIT(0); }
        __syncthreads();
#pragma unroll
        for (int ks = 0; ks < 2; ++ks) {
            int k8 = ks * 8;
            uint32_t af[2][4];
#pragma unroll
            for (int mt = 0; mt < 2; ++mt) {
                int r = wm * 32 + mt * 16;
                af[mt][0] = f2tfu(sA[s][r + gid    ][k8 + tig    ]);
                af[mt][1] = f2tfu(sA[s][r + gid + 8][k8 + tig    ]);
                af[mt][2] = f2tfu(sA[s][r + gid    ][k8 + tig + 4]);
                af[mt][3] = f2tfu(sA[s][r + gid + 8][k8 + tig + 4]);
            }
            uint32_t bg[4][2], bu[4][2];
#pragma unroll
            for (int nt = 0; nt < 4; ++nt) {
                int cix = wn * 32 + nt * 8 + gid;
                bg[nt][0] = f2tfu(sBg[s][k8 + tig    ][cix]);
                bg[nt][1] = f2tfu(sBg[s][k8 + tig + 4][cix]);
                bu[nt][0] = f2tfu(sBu[s][k8 + tig    ][cix]);
                bu[nt][1] = f2tfu(sBu[s][k8 + tig + 4][cix]);
            }
#pragma unroll
            for (int mt = 0; mt < 2; ++mt)
#pragma unroll
                for (int nt = 0; nt < 4; ++nt) {
                    MMA_TF32(cg[mt][nt], af[mt], bg[nt]);
                    MMA_TF32(cu[mt][nt], af[mt], bu[nt]);
                }
        }
        __syncthreads();
    }
#pragma unroll
    for (int mt = 0; mt < 2; ++mt) {
#pragma unroll
        for (int i = 0; i < 4; ++i) {
            int row  = wm * 32 + mt * 16 + gid + ((i >> 1) << 3);
            int srow = m0 + row;
            if (srow >= cnt) continue;
            int ps = g_poff[e] + srow;
#pragma unroll
            for (int nt = 0; nt < 4; ++nt) {
                int k = n0 + wn * 32 + nt * 8 + 2 * tig + (i & 1);
                float g = cg[mt][nt][i], u = cu[mt][nt][i];
                *(float*)act_addr(ps, k) = f2tf(g / (1.f + __expf(-g)) * u);
            }
        }
    }
}

__global__ void __launch_bounds__(256, 2)
gemm2_legacy(const float* __restrict__ down_w) {
    if (g_ok2) return;
    int e = blockIdx.z;
    int off = g_offsets[e], cnt = g_offsets[e + 1] - off;
    int m0 = blockIdx.x * 128;
    if (m0 >= cnt) return;
    int n0 = blockIdx.y * 128;

    __shared__ float sA[2][128][20];
    __shared__ float sB[2][16][132];

    int tid = threadIdx.x;
    const size_t wbase = (size_t)e * INTER * HIDDEN;

    int aps[2], akc2[2], arowi[2];
#pragma unroll
    for (int j = 0; j < 2; ++j) {
        int c = tid + j * 256;
        int row = c >> 2, kc = (c & 3) << 2;
        aps[j] = g_poff[e] + m0 + row;     // always inside this expert's padded blocks
        arowi[j] = row; akc2[j] = kc;
    }
    const float* bsrc[2]; int bkri[2], bnci[2];
#pragma unroll
    for (int j = 0; j < 2; ++j) {
        int c = tid + j * 256;
        int kr = c >> 5, nc = (c & 31) << 2;
        bsrc[j] = down_w + wbase + (size_t)kr * HIDDEN + n0 + nc;
        bkri[j] = kr; bnci[j] = nc;
    }
    auto load_tile = [&](int s, int k0) {
#pragma unroll
        for (int j = 0; j < 2; ++j)
            CP16(smem_u32(&sA[s][arowi[j]][akc2[j]]), act_addr(aps[j], k0 + akc2[j]));
#pragma unroll
        for (int j = 0; j < 2; ++j)
            CP16(smem_u32(&sB[s][bkri[j]][bnci[j]]), bsrc[j] + (size_t)k0 * HIDDEN);
    };

    float acc[2][8][4] = {};
    int warp = tid >> 5, lane = tid & 31;
    int wm = warp >> 1, wn = warp & 1;
    int gid = lane >> 2, tig = lane & 3;

    load_tile(0, 0); CP_COMMIT;
    const int KT = INTER / 16;
    for (int kt = 0; kt < KT; ++kt) {
        int s = kt & 1;
        if (kt + 1 < KT) { load_tile(s ^ 1, (kt + 1) * 16); CP_COMMIT; CP_WAIT(1); }
        else             { CP_WAIT(0); }
        __syncthreads();
#pragma unroll
        for (int ks = 0; ks < 2; ++ks) {
            int k8 = ks * 8;
            uint32_t af[2][4];
#pragma unroll
            for (int mt = 0; mt < 2; ++mt) {
                int r = wm * 32 + mt * 16;
                af[mt][0] = f2tfu(sA[s][r + gid    ][k8 + tig    ]);
                af[mt][1] = f2tfu(sA[s][r + gid + 8][k8 + tig    ]);
                af[mt][2] = f2tfu(sA[s][r + gid    ][k8 + tig + 4]);
                af[mt][3] = f2tfu(sA[s][r + gid + 8][k8 + tig + 4]);
            }
            uint32_t bf[8][2];
#pragma unroll
            for (int nt = 0; nt < 8; ++nt) {
                int cix = wn * 64 + nt * 8 + gid;
                bf[nt][0] = f2tfu(sB[s][k8 + tig    ][cix]);
                bf[nt][1] = f2tfu(sB[s][k8 + tig + 4][cix]);
            }
#pragma unroll
            for (int mt = 0; mt < 2; ++mt)
#pragma unroll
                for (int nt = 0; nt < 8; ++nt)
                    MMA_TF32(acc[mt][nt], af[mt], bf[nt]);
        }
        __syncthreads();
    }
#pragma unroll
    for (int mt = 0; mt < 2; ++mt) {
#pragma unroll
        for (int i = 0; i < 4; ++i) {
            int row  = wm * 32 + mt * 16 + gid + ((i >> 1) << 3);
            int srow = m0 + row;
            if (srow >= cnt) continue;
            int slot = off + srow;
            float w  = g_row_weight[slot];
            float* orow = g_pout + (size_t)g_s2p[slot] * HIDDEN + n0 + wn * 64;
#pragma unroll
            for (int nt = 0; nt < 8; ++nt)
                orow[nt * 8 + 2 * tig + (i & 1)] = acc[mt][nt][i] * w;
        }
    }
}

// ---------------- combine ----------------
__global__ void combine_kernel(float* __restrict__ out) {
    int t = blockIdx.x, c = threadIdx.x;
    const float* base = g_pout + (size_t)t * TOPK * HIDDEN + c * 4;
    float4 acc = make_float4(0.f, 0.f, 0.f, 0.f);
#pragma unroll
    for (int k = 0; k < TOPK; ++k) {
        float4 v = *(const float4*)(base + (size_t)k * HIDDEN);
        acc.x += v.x; acc.y += v.y; acc.z += v.z; acc.w += v.w;
    }
    *(float4*)(out + (size_t)t * HIDDEN + c * 4) = acc;
}

// ---------------- launch ----------------
extern "C" void kernel_launch(void* const* d_in, const int* in_sizes, int n_in,
                              void* d_out, int out_size) {
    const float* hidden = (const float*)d_in[0];
    const float* logits = (const float*)d_in[1];
    const float* gate   = (const float*)d_in[2];
    const float* up     = (const float*)d_in[3];
    const float* down   = (const float*)d_in[4];
    float* out = (float*)d_out;

    cudaFuncSetAttribute(gemm1_tc, cudaFuncAttributeMaxDynamicSharedMemorySize, 3 * STG + 1024);
    cudaFuncSetAttribute(gemm2_tc, cudaFuncAttributeMaxDynamicSharedMemorySize, 3 * STG + 1024);

    float *wtg, *wtu, *wtd, *rh;
    cudaGetSymbolAddress((void**)&wtg, g_wtg);
    cudaGetSymbolAddress((void**)&wtu, g_wtu);
    cudaGetSymbolAddress((void**)&wtd, g_wtd);
    cudaGetSymbolAddress((void**)&rh,  g_hid);

    selftest_kernel <<<1, 128>>>();
    rnd_kernel      <<<2048, 512>>>((const float4*)hidden, (float4*)rh, TOKENS * HIDDEN / 4);
    tile_kernel     <<<dim3(HIDDEN / 32, INTER / 32, NEXP), 256>>>(gate, wtg, HIDDEN, INTER, 6, KT1);
    tile_kernel     <<<dim3(HIDDEN / 32, INTER / 32, NEXP), 256>>>(up,   wtu, HIDDEN, INTER, 6, KT1);
    tile_kernel     <<<dim3(INTER / 32, HIDDEN / 32, NEXP), 256>>>(down, wtd, INTER, HIDDEN, 16, KT2);
    init_kernel     <<<1, 64>>>();
    route_kernel    <<<TOKENS / 256, 256>>>(logits);
    scan_kernel     <<<1, 32>>>();
    scatter_kernel  <<<NPAIRS / 256, 256>>>();
    gather_kernel   <<<dim3(PBMAX, KT1), 256>>>(hidden);
    gemm1_tc        <<<dim3(MCAP / 256, INTER / 128, NEXP), 256, 3 * STG + 1024>>>();
    verify1_kernel  <<<1, 64>>>();
    gemm1_legacy    <<<dim3(MCAP / 128, INTER / 64,  NEXP), 256>>>(gate, up);
    gemm2_tc        <<<dim3(MCAP / 256, HIDDEN / 256, NEXP), 256, 3 * STG + 1024>>>();
    verify2_kernel  <<<1, 64>>>();
    gemm2_legacy    <<<dim3(MCAP / 128, HIDDEN / 128, NEXP), 256>>>(down);
    combine_kernel  <<<TOKENS, 512>>>(out);
}

// round 11
// speedup vs baseline: 1.4951x; 1.0845x over previous
#include <cuda_runtime.h>
#include <cstdint>

#if defined(__CUDA_ARCH_FEAT_SM103_ALL) || defined(__CUDA_ARCH_FEAT_SM100_ALL) || defined(__CUDA_ARCH_FEAT_SM101_ALL)
#define TC_OK 1
#endif

#define TOKENS 4096
#define HIDDEN 2048
#define INTER  768
#define NEXP   64
#define TOPK   8
#define NPAIRS (TOKENS*TOPK)
#define MCAP   2048
#define BK     32
#define STG    65536        // stage: A 2x16KB + B 2x16KB
#define KT1    (HIDDEN/BK)  // 64
#define KT2    (INTER/BK)   // 24
#define WSZ    100663296
#define PBMAX  320

__device__ int   g_tc_ok;
__device__ int   g_ok1;
__device__ int   g_ok2;
__device__ int   g_counts[NEXP];
__device__ int   g_offsets[NEXP+1];
__device__ int   g_poff[NEXP+1];
__device__ int   g_cursor[NEXP];
__device__ int   g_pair_e[NPAIRS];
__device__ float g_pair_w[NPAIRS];
__device__ int   g_row_token[NPAIRS];
__device__ float g_row_weight[NPAIRS];
__device__ int   g_s2p[NPAIRS];
__device__ float g_act[(size_t)PBMAX * 128 * INTER];    // ALWAYS tiled [pb][kk24][16KB]
__device__ float g_pout[(size_t)NPAIRS * HIDDEN];
__device__ float g_hid[(size_t)TOKENS * HIDDEN];
__device__ float g_hs[(size_t)PBMAX * 128 * HIDDEN];    // gathered A, tiled [pb][kk64][16KB]
__device__ float g_wtg[WSZ];   // gate^T tiled [e][nb6][kk64][16KB]
__device__ float g_wtu[WSZ];
__device__ float g_wtd[WSZ];   // down^T tiled [e][nb16][kk24][16KB]

__device__ __forceinline__ uint32_t smem_u32(const void* p) {
    return (uint32_t)__cvta_generic_to_shared(p);
}
__device__ __forceinline__ float f2tf(float x) {
    uint32_t r;
    asm("cvt.rna.tf32.f32 %0, %1;" : "=r"(r) : "f"(x));
    return __uint_as_float(r);
}
__device__ __forceinline__ uint32_t f2tfu(float x) {
    uint32_t r;
    asm("cvt.rna.tf32.f32 %0, %1;" : "=r"(r) : "f"(x));
    return r;
}
#define SW128(o) ((o) ^ (((o) >> 3) & 0x70))
#define CP16(d, s) asm volatile("cp.async.cg.shared.global [%0], [%1], 16;\n" :: "r"(d), "l"(s))
#define CP_COMMIT  asm volatile("cp.async.commit_group;\n")
#define CP_WAIT(n) asm volatile("cp.async.wait_group %0;\n" :: "n"(n))
#define MBAR_INIT(mb, c) asm volatile("mbarrier.init.shared.b64 [%0], %1;" :: "r"(mb), "r"(c) : "memory")
#define MBAR_ARRIVE_TX(mb, tx) asm volatile("mbarrier.arrive.expect_tx.shared.b64 _, [%0], %1;" :: "r"(mb), "r"(tx) : "memory")
#define BULK_G2S(dst, src, sz, mb)                                            \
    asm volatile("cp.async.bulk.shared::cluster.global.mbarrier::complete_tx::bytes [%0], [%1], %2, [%3];" \
                 :: "r"(dst), "l"(src), "r"(sz), "r"(mb) : "memory")
#define MBAR_WAIT(mb, ph)                                                     \
    asm volatile("{\n\t.reg .pred P1;\n\t"                                    \
        "WL_%=:\n\t"                                                          \
        "mbarrier.try_wait.parity.acquire.cta.shared::cta.b64 P1, [%0], %1, 0x989680;\n\t" \
        "@P1 bra.uni WD_%=;\n\t"                                              \
        "bra.uni WL_%=;\n\t"                                                  \
        "WD_%=:\n\t}" :: "r"(mb), "r"(ph) : "memory")

#ifdef TC_OK
#define TC_ALLOC(sm, n)  asm volatile("tcgen05.alloc.cta_group::1.sync.aligned.shared::cta.b32 [%0], %1;" :: "r"(sm), "r"(n) : "memory")
#define TC_DEALLOC(t, n) asm volatile("tcgen05.dealloc.cta_group::1.sync.aligned.b32 %0, %1;" :: "r"(t), "r"(n))
#define TC_RELINQ()      asm volatile("tcgen05.relinquish_alloc_permit.cta_group::1.sync.aligned;")
#define TC_COMMIT(mb)    asm volatile("tcgen05.commit.cta_group::1.mbarrier::arrive::one.shared::cluster.b64 [%0];" :: "r"(mb) : "memory")
#define TC_FENCE_AFTER() asm volatile("tcgen05.fence::after_thread_sync;" ::: "memory")
#define TC_WAIT_LD()     asm volatile("tcgen05.wait::ld.sync.aligned;" ::: "memory")
#define FENCE_ASYNC()    asm volatile("fence.proxy.async.shared::cta;" ::: "memory")
#define LDTM_X32(r, a)                                                        \
    asm volatile("tcgen05.ld.sync.aligned.32x32b.x32.b32 "                    \
        "{%0,%1,%2,%3,%4,%5,%6,%7,%8,%9,%10,%11,%12,%13,%14,%15,"             \
        "%16,%17,%18,%19,%20,%21,%22,%23,%24,%25,%26,%27,%28,%29,%30,%31},[%32];" \
        : "=r"((r)[0]),"=r"((r)[1]),"=r"((r)[2]),"=r"((r)[3]),                \
          "=r"((r)[4]),"=r"((r)[5]),"=r"((r)[6]),"=r"((r)[7]),                \
          "=r"((r)[8]),"=r"((r)[9]),"=r"((r)[10]),"=r"((r)[11]),              \
          "=r"((r)[12]),"=r"((r)[13]),"=r"((r)[14]),"=r"((r)[15]),            \
          "=r"((r)[16]),"=r"((r)[17]),"=r"((r)[18]),"=r"((r)[19]),            \
          "=r"((r)[20]),"=r"((r)[21]),"=r"((r)[22]),"=r"((r)[23]),            \
          "=r"((r)[24]),"=r"((r)[25]),"=r"((r)[26]),"=r"((r)[27]),            \
          "=r"((r)[28]),"=r"((r)[29]),"=r"((r)[30]),"=r"((r)[31]) : "r"(a))

__device__ __forceinline__ uint64_t desc_k(uint32_t a) {     // SW128 K-major
    return (uint64_t(2) << 61) | (uint64_t(1) << 46) | (uint64_t(64) << 32) |
           (uint64_t(1) << 16) | ((uint64_t)(a >> 4) & 0x3FFF);
}
#define IDESC32 ((1u<<4)|(2u<<7)|(2u<<10)|(4u<<17)|(8u<<24))
#define IDESC64 ((1u<<4)|(2u<<7)|(2u<<10)|(8u<<17)|(8u<<24))
__device__ __forceinline__ void mma_n32(uint32_t d, uint64_t ad, uint64_t bd, uint32_t acc) {
    asm volatile(
        "{\n\t.reg .pred p;\n\tsetp.ne.u32 p, %4, 0;\n\t"
        "tcgen05.mma.cta_group::1.kind::tf32 [%0], %1, %2, %3, {%5,%5,%5,%5}, p;\n\t}"
        :: "r"(d), "l"(ad), "l"(bd), "r"(IDESC32), "r"(acc), "r"(0u) : "memory");
}
__device__ __forceinline__ void mma_n64(uint32_t d, uint64_t ad, uint64_t bd, uint32_t acc) {
    asm volatile(
        "{\n\t.reg .pred p;\n\tsetp.ne.u32 p, %4, 0;\n\t"
        "tcgen05.mma.cta_group::1.kind::tf32 [%0], %1, %2, %3, {%5,%5,%5,%5}, p;\n\t}"
        :: "r"(d), "l"(ad), "l"(bd), "r"(IDESC64), "r"(acc), "r"(0u) : "memory");
}
#endif

// ---------------- tiled-layout helpers ----------------
__device__ __forceinline__ float wt_read(const float* wt, int NB, int KK, int e, int n, int k) {
    size_t tile = ((size_t)e * NB + (n >> 7)) * KK + (k >> 5);
    uint32_t inner = SW128((uint32_t)(((n & 127) << 7) + ((k & 31) << 2)));
    return *(const float*)((const char*)wt + tile * 16384 + inner);
}
__device__ __forceinline__ char* act_addr(int ps, int k) {
    size_t tile = (size_t)(ps >> 7) * KT2 + (k >> 5);
    uint32_t inner = SW128((uint32_t)(((ps & 127) << 7) + ((k & 31) << 2)));
    return (char*)g_act + tile * 16384 + inner;
}
__device__ __forceinline__ float act_read(int ps, int k) {
    return *(const float*)act_addr(ps, k);
}

// ---------------- self-test ----------------
__device__ __forceinline__ float tva(int m, int k) {
    return f2tf(0.01f * (float)((m * 7 + k * 13) % 31 - 15));
}
__device__ __forceinline__ float tvb(int n, int k) {
    return f2tf(0.02f * (float)((n * 5 + k * 3) % 29 - 14));
}
__global__ void selftest_kernel() {
#ifdef TC_OK
    __shared__ __align__(1024) float sma[4096];
    __shared__ __align__(1024) float smb[1024];
    __shared__ uint32_t s_tmem[1];
    __shared__ __align__(8) uint64_t s_mbar[1];
    __shared__ float s_d, s_r;
    int tid = threadIdx.x, wid = tid >> 5, lane = tid & 31;

    if (wid == 0) { TC_ALLOC(smem_u32(s_tmem), 128); TC_RELINQ(); }
    if (tid == 0) { MBAR_INIT(smem_u32(s_mbar), 1); s_d = 0.f; s_r = 0.f; }
    for (int idx = tid; idx < 4096; idx += 128) {
        int m = idx >> 5, k = idx & 31;
        *(float*)((char*)sma + SW128((uint32_t)(m * 128 + k * 4))) = tva(m, k);
    }
    for (int idx = tid; idx < 1024; idx += 128) {
        int n = idx >> 5, k = idx & 31;
        *(float*)((char*)smb + SW128((uint32_t)(n * 128 + k * 4))) = tvb(n, k);
    }
    __syncthreads();
    uint32_t tmem = s_tmem[0], mb = smem_u32(s_mbar);
    if (tid == 0) {
        FENCE_ASYNC();
        uint64_t ad = desc_k(smem_u32(sma)), bd = desc_k(smem_u32(smb));
#pragma unroll
        for (int ks = 0; ks < 4; ++ks)
            mma_n32(tmem, ad + ks * 2, bd + ks * 2, ks > 0 ? 1u : 0u);
        TC_COMMIT(mb);
    }
    __syncthreads();
    MBAR_WAIT(mb, 0);
    TC_FENCE_AFTER();
    uint32_t r[32];
    LDTM_X32(r, tmem);
    TC_WAIT_LD();
    int m = wid * 32 + lane;
    float d = 0.f, rf = 0.f;
#pragma unroll 4
    for (int n = 0; n < 32; ++n) {
        float ref = 0.f;
        for (int k = 0; k < 32; ++k) ref += tva(m, k) * tvb(n, k);
        d  += fabsf(__uint_as_float(r[n]) - ref);
        rf += fabsf(ref);
    }
    atomicAdd(&s_d, d); atomicAdd(&s_r, rf);
    __syncthreads();
    if (tid == 0) g_tc_ok = (s_d <= 0.01f * s_r + 1e-3f) ? 1 : 0;
    __syncthreads();
    if (wid == 0) TC_DEALLOC(tmem, 128);
#else
    if (threadIdx.x == 0) g_tc_ok = 0;
#endif
}

// ---------------- prep ----------------
__global__ void rnd_kernel(const float4* __restrict__ src, float4* __restrict__ dst, int n4) {
    int i = blockIdx.x * blockDim.x + threadIdx.x, st = gridDim.x * blockDim.x;
    for (; i < n4; i += st) {
        float4 v = src[i];
        v.x = f2tf(v.x); v.y = f2tf(v.y); v.z = f2tf(v.z); v.w = f2tf(v.w);
        dst[i] = v;
    }
}
__global__ void tile_kernel(const float* __restrict__ src, float* __restrict__ dst,
                            int K, int N, int NB, int KK) {
    if (g_tc_ok == 0) return;
    __shared__ float t[32][33];
    int e = blockIdx.z;
    int k0 = blockIdx.x * 32, n0 = blockIdx.y * 32;
    int r = threadIdx.x >> 3, c4 = (threadIdx.x & 7) << 2;
    float4 v = *(const float4*)(src + ((size_t)e * K + k0 + r) * N + n0 + c4);
    t[r][c4] = v.x; t[r][c4 + 1] = v.y; t[r][c4 + 2] = v.z; t[r][c4 + 3] = v.w;
    __syncthreads();
    int n = n0 + r;
    size_t tile = ((size_t)e * NB + (n >> 7)) * KK + (k0 >> 5);
    uint32_t inner = SW128((uint32_t)(((n & 127) << 7) + (c4 << 2)));
    float4 o;
    o.x = f2tf(t[c4    ][r]);
    o.y = f2tf(t[c4 + 1][r]);
    o.z = f2tf(t[c4 + 2][r]);
    o.w = f2tf(t[c4 + 3][r]);
    *(float4*)((char*)dst + tile * 16384 + inner) = o;
}
__global__ void init_kernel() { if (threadIdx.x < NEXP) g_counts[threadIdx.x] = 0; }

__global__ void route_kernel(const float* __restrict__ logits) {
    int t = blockIdx.x * blockDim.x + threadIdx.x;
    if (t >= TOKENS) return;
    float l[NEXP];
    const float* lp = logits + (size_t)t * NEXP;
#pragma unroll
    for (int i = 0; i < NEXP; ++i) l[i] = lp[i];
    float val[TOPK]; int sel[TOPK];
#pragma unroll
    for (int k = 0; k < TOPK; ++k) {
        float best = -1e30f; int bi = 0;
#pragma unroll
        for (int i = 0; i < NEXP; ++i)
            if (l[i] > best) { best = l[i]; bi = i; }
        val[k] = best; sel[k] = bi; l[bi] = -1e30f;
    }
    float m = val[0], s = 0.f, w[TOPK];
#pragma unroll
    for (int k = 0; k < TOPK; ++k) { w[k] = __expf(val[k] - m); s += w[k]; }
    float inv = 1.f / s;
#pragma unroll
    for (int k = 0; k < TOPK; ++k) {
        g_pair_e[t * TOPK + k] = sel[k];
        g_pair_w[t * TOPK + k] = w[k] * inv;
        atomicAdd(&g_counts[sel[k]], 1);
    }
}
__global__ void scan_kernel() {
    if (threadIdx.x == 0) {
        int acc = 0, pacc = 0;
        for (int e = 0; e < NEXP; ++e) {
            g_offsets[e] = acc; g_cursor[e] = acc;
            g_poff[e] = pacc;
            acc += g_counts[e];
            pacc += (g_counts[e] + 127) & ~127;
        }
        g_offsets[NEXP] = acc;
        g_poff[NEXP] = pacc;
    }
}
__global__ void scatter_kernel() {
    int p = blockIdx.x * blockDim.x + threadIdx.x;
    if (p >= NPAIRS) return;
    int slot = atomicAdd(&g_cursor[g_pair_e[p]], 1);
    g_row_token[slot]  = p >> 3;
    g_row_weight[slot] = g_pair_w[p];
    g_s2p[slot] = p;
}
__global__ void gather_kernel(const float* __restrict__ hidden) {
    if (g_tc_ok == 0) return;
    int pb = blockIdx.x, kk = blockIdx.y;
    __shared__ int s_e;
    if (threadIdx.x == 0) {
        int e = 0;
        while (e < NEXP && !(g_poff[e] <= pb * 128 && pb * 128 < g_poff[e + 1])) ++e;
        s_e = e;
    }
    __syncthreads();
    int e = s_e;
    if (e >= NEXP) return;
    int off = g_offsets[e], cnt = g_counts[e];
    char* tile = (char*)g_hs + ((size_t)pb * KT1 + kk) * 16384;
#pragma unroll
    for (int j = 0; j < 4; ++j) {
        int f = threadIdx.x + j * 256;
        int row = f >> 3, c = f & 7;
        int lidx = pb * 128 + row - g_poff[e];
        if (lidx > cnt - 1) lidx = cnt - 1;
        int token = g_row_token[off + lidx];
        float4 v = *(const float4*)(hidden + (size_t)token * HIDDEN + kk * 32 + c * 4);
        v.x = f2tf(v.x); v.y = f2tf(v.y); v.z = f2tf(v.z); v.w = f2tf(v.w);
        *(float4*)(tile + SW128((uint32_t)(row * 128 + c * 16))) = v;
    }
}

// ============ tcgen05 GEMM1: M=256, N=128, producer/consumer warps ========
__global__ void __launch_bounds__(256, 1)
gemm1_tc() {
#ifdef TC_OK
    if (g_tc_ok == 0) return;
    int e = blockIdx.z;
    int off = g_offsets[e], cnt = g_offsets[e + 1] - off;
    int m0 = blockIdx.x * 256;
    if (m0 >= cnt) return;
    int nb = blockIdx.y;
    int n0 = nb * 128;

    extern __shared__ char dyn[];
    uint32_t sbase = (smem_u32(dyn) + 1023u) & ~1023u;
    __shared__ uint32_t s_tmem[1];
    __shared__ __align__(8) uint64_t s_full[3], s_mdone[3], s_fin[1];
    int tid = threadIdx.x, wid = tid >> 5, lane = tid & 31;

    if (wid == 0) { TC_ALLOC(smem_u32(s_tmem), 512); TC_RELINQ(); }
    if (tid == 0) {
#pragma unroll
        for (int i = 0; i < 3; ++i) {
            MBAR_INIT(smem_u32(&s_full[i]), 1);
            MBAR_INIT(smem_u32(&s_mdone[i]), 1);
        }
        MBAR_INIT(smem_u32(s_fin), 1);
    }
    __syncthreads();
    uint32_t tmem = s_tmem[0];
    int pb0 = (g_poff[e] + m0) >> 7;
    int pb1 = pb0 + 1; if (pb1 > PBMAX - 1) pb1 = PBMAX - 1;

    if (tid == 32) {   // -------- producer warp: issue all bulk loads --------
        uint32_t full[3]  = { smem_u32(&s_full[0]),  smem_u32(&s_full[1]),  smem_u32(&s_full[2])  };
        uint32_t mdone[3] = { smem_u32(&s_mdone[0]), smem_u32(&s_mdone[1]), smem_u32(&s_mdone[2]) };
        const char* a0 = (const char*)g_hs + ((size_t)pb0 * KT1) * 16384;
        const char* a1 = (const char*)g_hs + ((size_t)pb1 * KT1) * 16384;
        const char* tg = (const char*)g_wtg + (((size_t)e * 6 + nb) * KT1) * 16384;
        const char* tu = (const char*)g_wtu + (((size_t)e * 6 + nb) * KT1) * 16384;
        for (int kt = 0; kt < KT1; ++kt) {
            int s = kt % 3;
            if (kt >= 3) MBAR_WAIT(mdone[s], (kt / 3 - 1) & 1);
            MBAR_ARRIVE_TX(full[s], 65536u);
            uint32_t sb = sbase + s * STG;
            BULK_G2S(sb,           a0 + (size_t)kt * 16384, 16384u, full[s]);
            BULK_G2S(sb + 16384u,  a1 + (size_t)kt * 16384, 16384u, full[s]);
            BULK_G2S(sb + 32768u,  tg + (size_t)kt * 16384, 16384u, full[s]);
            BULK_G2S(sb + 49152u,  tu + (size_t)kt * 16384, 16384u, full[s]);
        }
    }
    if (tid == 0) {    // -------- consumer: MMA dispatch only --------
        uint32_t full[3]  = { smem_u32(&s_full[0]),  smem_u32(&s_full[1]),  smem_u32(&s_full[2])  };
        uint32_t mdone[3] = { smem_u32(&s_mdone[0]), smem_u32(&s_mdone[1]), smem_u32(&s_mdone[2]) };
        for (int kt = 0; kt < KT1; ++kt) {
            int s = kt % 3;
            MBAR_WAIT(full[s], (kt / 3) & 1);
            FENCE_ASYNC();
            uint32_t sb = sbase + s * STG;
            uint64_t ad = desc_k(sb);
            uint64_t bg = desc_k(sb + 32768u), bu = desc_k(sb + 49152u);
#pragma unroll
            for (int ks = 0; ks < 4; ++ks) {
                uint32_t acc = (kt > 0 || ks > 0) ? 1u : 0u;
#pragma unroll
                for (int mh = 0; mh < 2; ++mh) {
                    uint64_t amd = ad + mh * 1024 + ks * 2;
#pragma unroll
                    for (int j = 0; j < 2; ++j) {
                        mma_n64(tmem + mh * 256 + j * 64,       amd, bg + j * 512 + ks * 2, acc);
                        mma_n64(tmem + mh * 256 + 128 + j * 64, amd, bu + j * 512 + ks * 2, acc);
                    }
                }
            }
            TC_COMMIT(mdone[s]);
        }
        TC_COMMIT(smem_u32(s_fin));          // fires when ALL prior MMAs done
        MBAR_WAIT(smem_u32(s_fin), 0);       // fresh barrier: no phase aliasing
    }
    __syncthreads();
    TC_FENCE_AFTER();

    // epilogue: swiglu -> g_act (TILED layout)
    int mh = wid >> 2, sp = wid & 3;
    int row = mh * 128 + sp * 32 + lane;
    bool valid = (m0 + row) < cnt;
    int ps = g_poff[e] + m0 + row;
    size_t tb0 = (size_t)(ps >> 7) * KT2 * 16384;
    uint32_t rinner = (uint32_t)((ps & 127) << 7);
    uint32_t tmb = tmem + mh * 256;
#pragma unroll
    for (int cb = 0; cb < 4; ++cb) {
        int c0 = cb * 32;
        uint32_t rg[32], ru[32];
        LDTM_X32(rg, tmb + c0);
        LDTM_X32(ru, tmb + 128 + c0);
        TC_WAIT_LD();
        if (valid) {
            char* tile = (char*)g_act + tb0 + (size_t)((n0 + c0) >> 5) * 16384;
#pragma unroll
            for (int i = 0; i < 32; i += 4) {
                float4 v;
#pragma unroll
                for (int q = 0; q < 4; ++q) {
                    float g = __uint_as_float(rg[i + q]);
                    float u = __uint_as_float(ru[i + q]);
                    ((float*)&v)[q] = f2tf(g / (1.f + __expf(-g)) * u);
                }
                *(float4*)(tile + SW128(rinner + i * 4)) = v;
            }
        }
    }
    __syncthreads();
    if (wid == 0) TC_DEALLOC(tmem, 512);
#endif
}

// ============ tcgen05 GEMM2: M=256, N=256, producer/consumer warps ========
__global__ void __launch_bounds__(256, 1)
gemm2_tc() {
#ifdef TC_OK
    if (g_ok1 == 0) return;
    int e = blockIdx.z;
    int off = g_offsets[e], cnt = g_offsets[e + 1] - off;
    int m0 = blockIdx.x * 256;
    if (m0 >= cnt) return;
    int nb0 = blockIdx.y * 2;
    int n0 = nb0 * 128;

    extern __shared__ char dyn[];
    uint32_t sbase = (smem_u32(dyn) + 1023u) & ~1023u;
    __shared__ uint32_t s_tmem[1];
    __shared__ __align__(8) uint64_t s_full[3], s_mdone[3], s_fin[1];
    int tid = threadIdx.x, wid = tid >> 5, lane = tid & 31;

    if (wid == 0) { TC_ALLOC(smem_u32(s_tmem), 512); TC_RELINQ(); }
    if (tid == 0) {
#pragma unroll
        for (int i = 0; i < 3; ++i) {
            MBAR_INIT(smem_u32(&s_full[i]), 1);
            MBAR_INIT(smem_u32(&s_mdone[i]), 1);
        }
        MBAR_INIT(smem_u32(s_fin), 1);
    }
    __syncthreads();
    uint32_t tmem = s_tmem[0];
    int pb0 = (g_poff[e] + m0) >> 7;
    int pb1 = pb0 + 1; if (pb1 > PBMAX - 1) pb1 = PBMAX - 1;

    if (tid == 32) {   // producer
        uint32_t full[3]  = { smem_u32(&s_full[0]),  smem_u32(&s_full[1]),  smem_u32(&s_full[2])  };
        uint32_t mdone[3] = { smem_u32(&s_mdone[0]), smem_u32(&s_mdone[1]), smem_u32(&s_mdone[2]) };
        const char* a0 = (const char*)g_act + ((size_t)pb0 * KT2) * 16384;
        const char* a1 = (const char*)g_act + ((size_t)pb1 * KT2) * 16384;
        const char* b0p = (const char*)g_wtd + (((size_t)e * 16 + nb0)     * KT2) * 16384;
        const char* b1p = (const char*)g_wtd + (((size_t)e * 16 + nb0 + 1) * KT2) * 16384;
        for (int kt = 0; kt < KT2; ++kt) {
            int s = kt % 3;
            if (kt >= 3) MBAR_WAIT(mdone[s], (kt / 3 - 1) & 1);
            MBAR_ARRIVE_TX(full[s], 65536u);
            uint32_t sb = sbase + s * STG;
            BULK_G2S(sb,          a0  + (size_t)kt * 16384, 16384u, full[s]);
            BULK_G2S(sb + 16384u, a1  + (size_t)kt * 16384, 16384u, full[s]);
            BULK_G2S(sb + 32768u, b0p + (size_t)kt * 16384, 16384u, full[s]);
            BULK_G2S(sb + 49152u, b1p + (size_t)kt * 16384, 16384u, full[s]);
        }
    }
    if (tid == 0) {    // consumer
        uint32_t full[3]  = { smem_u32(&s_full[0]),  smem_u32(&s_full[1]),  smem_u32(&s_full[2])  };
        uint32_t mdone[3] = { smem_u32(&s_mdone[0]), smem_u32(&s_mdone[1]), smem_u32(&s_mdone[2]) };
        for (int kt = 0; kt < KT2; ++kt) {
            int s = kt % 3;
            MBAR_WAIT(full[s], (kt / 3) & 1);
            FENCE_ASYNC();
            uint32_t sb = sbase + s * STG;
            uint64_t ad = desc_k(sb);
            uint64_t b0 = desc_k(sb + 32768u), b1 = desc_k(sb + 49152u);
#pragma unroll
            for (int ks = 0; ks < 4; ++ks) {
                uint32_t acc = (kt > 0 || ks > 0) ? 1u : 0u;
#pragma unroll
                for (int mh = 0; mh < 2; ++mh) {
                    uint64_t amd = ad + mh * 1024 + ks * 2;
#pragma unroll
                    for (int j = 0; j < 4; ++j) {
                        uint64_t bd = (j < 2) ? (b0 + j * 512 + ks * 2)
                                              : (b1 + (j - 2) * 512 + ks * 2);
                        mma_n64(tmem + mh * 256 + j * 64, amd, bd, acc);
                    }
                }
            }
            TC_COMMIT(mdone[s]);
        }
        TC_COMMIT(smem_u32(s_fin));
        MBAR_WAIT(smem_u32(s_fin), 0);
    }
    __syncthreads();
    TC_FENCE_AFTER();

    int mh = wid >> 2, sp = wid & 3;
    int row = mh * 128 + sp * 32 + lane;
    bool valid = (m0 + row) < cnt;
    int slot = off + m0 + row; if (slot > NPAIRS - 1) slot = NPAIRS - 1;
    float w = g_row_weight[slot];
    float* dst = g_pout + (size_t)g_s2p[slot] * HIDDEN + n0;
    uint32_t tmb = tmem + mh * 256;
#pragma unroll
    for (int cb = 0; cb < 8; ++cb) {
        int c0 = cb * 32;
        uint32_t r[32];
        LDTM_X32(r, tmb + c0);
        TC_WAIT_LD();
        if (valid) {
#pragma unroll
            for (int i = 0; i < 32; i += 4) {
                float4 v;
                ((float*)&v)[0] = __uint_as_float(r[i])     * w;
                ((float*)&v)[1] = __uint_as_float(r[i + 1]) * w;
                ((float*)&v)[2] = __uint_as_float(r[i + 2]) * w;
                ((float*)&v)[3] = __uint_as_float(r[i + 3]) * w;
                *(float4*)(dst + c0 + i) = v;
            }
        }
    }
    __syncthreads();
    if (wid == 0) TC_DEALLOC(tmem, 512);
#endif
}

// ---------------- verifiers: rows 0 AND 150 ----------------
__global__ void verify1_kernel() {
    if (g_tc_ok == 0) { if (threadIdx.x == 0) g_ok1 = 0; return; }
    __shared__ float sd[2], sr[2];
    int e = 0;
    while (g_offsets[e + 1] < 1) ++e;
    int cnt = g_offsets[e + 1] - g_offsets[e];
    int w = threadIdx.x >> 5, lane = threadIdx.x & 31;
    int r = (w == 0) ? 0 : (cnt > 150 ? 150 : cnt - 1);
    int tok = g_row_token[g_offsets[e] + r];
    const float* h = g_hid + (size_t)tok * HIDDEN;
    int j = lane * 24;
    float ag = 0.f, au = 0.f;
    for (int k = 0; k < HIDDEN; ++k) {
        ag += h[k] * wt_read(g_wtg, 6, KT1, e, j, k);
        au += h[k] * wt_read(g_wtu, 6, KT1, e, j, k);
    }
    float ref = f2tf(ag / (1.f + expf(-ag)) * au);
    float d = fabsf(act_read(g_poff[e] + r, j) - ref), rf = fabsf(ref);
#pragma unroll
    for (int o = 16; o; o >>= 1) {
        d  += __shfl_xor_sync(~0u, d, o);
        rf += __shfl_xor_sync(~0u, rf, o);
    }
    if (lane == 0) { sd[w] = d; sr[w] = rf; }
    __syncthreads();
    if (threadIdx.x == 0)
        g_ok1 = (sd[0] + sd[1] <= 0.02f * (sr[0] + sr[1]) + 1e-2f) ? 1 : 0;
}
__global__ void verify2_kernel() {
    if (g_ok1 == 0) { if (threadIdx.x == 0) g_ok2 = 0; return; }
    __shared__ float sd[2], sr[2];
    int e = 0;
    while (g_offsets[e + 1] < 1) ++e;
    int cnt = g_offsets[e + 1] - g_offsets[e];
    int w = threadIdx.x >> 5, lane = threadIdx.x & 31;
    int r = (w == 0) ? 0 : (cnt > 150 ? 150 : cnt - 1);
    int slot = g_offsets[e] + r;
    int p = g_s2p[slot];
    float wgt = g_row_weight[slot];
    int ps = g_poff[e] + r;
    int n = lane * 64;
    float acc = 0.f;
    for (int k = 0; k < INTER; ++k)
        acc += act_read(ps, k) * wt_read(g_wtd, 16, KT2, e, n, k);
    float ref = acc * wgt;
    float d = fabsf(g_pout[(size_t)p * HIDDEN + n] - ref), rf = fabsf(ref);
#pragma unroll
    for (int o = 16; o; o >>= 1) {
        d  += __shfl_xor_sync(~0u, d, o);
        rf += __shfl_xor_sync(~0u, rf, o);
    }
    if (lane == 0) { sd[w] = d; sr[w] = rf; }
    __syncthreads();
    if (threadIdx.x == 0)
        g_ok2 = (sd[0] + sd[1] <= 0.02f * (sr[0] + sr[1]) + 1e-2f) ? 1 : 0;
}

// ================= legacy mma.sync fallback (TILED g_act) =================
#define MMA_TF32(c, a, b)                                                     \
    asm volatile(                                                             \
        "mma.sync.aligned.m16n8k8.row.col.f32.tf32.tf32.f32 "                 \
        "{%0,%1,%2,%3},{%4,%5,%6,%7},{%8,%9},{%0,%1,%2,%3};"                  \
        : "+f"((c)[0]), "+f"((c)[1]), "+f"((c)[2]), "+f"((c)[3])              \
        : "r"((a)[0]), "r"((a)[1]), "r"((a)[2]), "r"((a)[3]),                 \
          "r"((b)[0]), "r"((b)[1]))

__global__ void __launch_bounds__(256, 2)
gemm1_legacy(const float* __restrict__ gate_w, const float* __restrict__ up_w) {
    if (g_ok1) return;
    int e = blockIdx.z;
    int off = g_offsets[e], cnt = g_offsets[e + 1] - off;
    int m0 = blockIdx.x * 128;
    if (m0 >= cnt) return;
    int n0 = blockIdx.y * 64;

    __shared__ float sA [2][128][20];
    __shared__ float sBg[2][16][68];
    __shared__ float sBu[2][16][68];

    int tid = threadIdx.x;
    const size_t wbase = (size_t)e * HIDDEN * INTER;
    int maxslot = off + cnt - 1;

    const float* asrc[2]; int arowi[2], akc[2];
#pragma unroll
    for (int j = 0; j < 2; ++j) {
        int c = tid + j * 256;
        int row = c >> 2, kc = (c & 3) << 2;
        int slot = off + m0 + row; if (slot > maxslot) slot = maxslot;
        asrc[j] = g_hid + (size_t)g_row_token[slot] * HIDDEN + kc;
        arowi[j] = row; akc[j] = kc;
    }
    int bkr = tid >> 4, bnc = (tid & 15) << 2;
    const float* gsrc = gate_w + wbase + (size_t)bkr * INTER + n0 + bnc;
    const float* usrc = up_w   + wbase + (size_t)bkr * INTER + n0 + bnc;

    auto load_tile = [&](int s, int k0) {
#pragma unroll
        for (int j = 0; j < 2; ++j)
            CP16(smem_u32(&sA[s][arowi[j]][akc[j]]), asrc[j] + k0);
        CP16(smem_u32(&sBg[s][bkr][bnc]), gsrc + (size_t)k0 * INTER);
        CP16(smem_u32(&sBu[s][bkr][bnc]), usrc + (size_t)k0 * INTER);
    };

    float cg[2][4][4] = {}, cu[2][4][4] = {};
    int warp = tid >> 5, lane = tid & 31;
    int wm = warp >> 1, wn = warp & 1;
    int gid = lane >> 2, tig = lane & 3;

    load_tile(0, 0); CP_COMMIT;
    const int KT = HIDDEN / 16;
    for (int kt = 0; kt < KT; ++kt) {
        int s = kt & 1;
        if (kt + 1 < KT) { load_tile(s ^ 1, (kt + 1) * 16); CP_COMMIT; CP_WAIT(1); }
        else             { CP_WAIT(0); }
        __syncthreads();
#pragma unroll
        for (int ks = 0; ks < 2; ++ks) {
            int k8 = ks * 8;
            uint32_t af[2][4];
#pragma unroll
            for (int mt = 0; mt < 2; ++mt) {
                int r = wm * 32 + mt * 16;
                af[mt][0] = f2tfu(sA[s][r + gid    ][k8 + tig    ]);
                af[mt][1] = f2tfu(sA[s][r + gid + 8][k8 + tig    ]);
                af[mt][2] = f2tfu(sA[s][r + gid    ][k8 + tig + 4]);
                af[mt][3] = f2tfu(sA[s][r + gid + 8][k8 + tig + 4]);
            }
            uint32_t bg[4][2], bu[4][2];
#pragma unroll
            for (int nt = 0; nt < 4; ++nt) {
                int cix = wn * 32 + nt * 8 + gid;
                bg[nt][0] = f2tfu(sBg[s][k8 + tig    ][cix]);
                bg[nt][1] = f2tfu(sBg[s][k8 + tig + 4][cix]);
                bu[nt][0] = f2tfu(sBu[s][k8 + tig    ][cix]);
                bu[nt][1] = f2tfu(sBu[s][k8 + tig + 4][cix]);
            }
#pragma unroll
            for (int mt = 0; mt < 2; ++mt)
#pragma unroll
                for (int nt = 0; nt < 4; ++nt) {
                    MMA_TF32(cg[mt][nt], af[mt], bg[nt]);
                    MMA_TF32(cu[mt][nt], af[mt], bu[nt]);
                }
        }
        __syncthreads();
    }
#pragma unroll
    for (int mt = 0; mt < 2; ++mt) {
#pragma unroll
        for (int i = 0; i < 4; ++i) {
            int row  = wm * 32 + mt * 16 + gid + ((i >> 1) << 3);
            int srow = m0 + row;
            if (srow >= cnt) continue;
            int ps = g_poff[e] + srow;
#pragma unroll
            for (int nt = 0; nt < 4; ++nt) {
                int k = n0 + wn * 32 + nt * 8 + 2 * tig + (i & 1);
                float g = cg[mt][nt][i], u = cu[mt][nt][i];
                *(float*)act_addr(ps, k) = f2tf(g / (1.f + __expf(-g)) * u);
            }
        }
    }
}

__global__ void __launch_bounds__(256, 2)
gemm2_legacy(const float* __restrict__ down_w) {
    if (g_ok2) return;
    int e = blockIdx.z;
    int off = g_offsets[e], cnt = g_offsets[e + 1] - off;
    int m0 = blockIdx.x * 128;
    if (m0 >= cnt) return;
    int n0 = blockIdx.y * 128;

    __shared__ float sA[2][128][20];
    __shared__ float sB[2][16][132];

    int tid = threadIdx.x;
    const size_t wbase = (size_t)e * INTER * HIDDEN;

    int aps[2], akc2[2], arowi[2];
#pragma unroll
    for (int j = 0; j < 2; ++j) {
        int c = tid + j * 256;
        int row = c >> 2, kc = (c & 3) << 2;
        aps[j] = g_poff[e] + m0 + row;
        arowi[j] = row; akc2[j] = kc;
    }
    const float* bsrc[2]; int bkri[2], bnci[2];
#pragma unroll
    for (int j = 0; j < 2; ++j) {
        int c = tid + j * 256;
        int kr = c >> 5, nc = (c & 31) << 2;
        bsrc[j] = down_w + wbase + (size_t)kr * HIDDEN + n0 + nc;
        bkri[j] = kr; bnci[j] = nc;
    }
    auto load_tile = [&](int s, int k0) {
#pragma unroll
        for (int j = 0; j < 2; ++j)
            CP16(smem_u32(&sA[s][arowi[j]][akc2[j]]), act_addr(aps[j], k0 + akc2[j]));
#pragma unroll
        for (int j = 0; j < 2; ++j)
            CP16(smem_u32(&sB[s][bkri[j]][bnci[j]]), bsrc[j] + (size_t)k0 * HIDDEN);
    };

    float acc[2][8][4] = {};
    int warp = tid >> 5, lane = tid & 31;
    int wm = warp >> 1, wn = warp & 1;
    int gid = lane >> 2, tig = lane & 3;

    load_tile(0, 0); CP_COMMIT;
    const int KT = INTER / 16;
    for (int kt = 0; kt < KT; ++kt) {
        int s = kt & 1;
        if (kt + 1 < KT) { load_tile(s ^ 1, (kt + 1) * 16); CP_COMMIT; CP_WAIT(1); }
        else             { CP_WAIT(0); }
        __syncthreads();
#pragma unroll
        for (int ks = 0; ks < 2; ++ks) {
            int k8 = ks * 8;
            uint32_t af[2][4];
#pragma unroll
            for (int mt = 0; mt < 2; ++mt) {
                int r = wm * 32 + mt * 16;
                af[mt][0] = f2tfu(sA[s][r + gid    ][k8 + tig    ]);
                af[mt][1] = f2tfu(sA[s][r + gid + 8][k8 + tig    ]);
                af[mt][2] = f2tfu(sA[s][r + gid    ][k8 + tig + 4]);
                af[mt][3] = f2tfu(sA[s][r + gid + 8][k8 + tig + 4]);
            }
            uint32_t bf[8][2];
#pragma unroll
            for (int nt = 0; nt < 8; ++nt) {
                int cix = wn * 64 + nt * 8 + gid;
                bf[nt][0] = f2tfu(sB[s][k8 + tig    ][cix]);
                bf[nt][1] = f2tfu(sB[s][k8 + tig + 4][cix]);
            }
#pragma unroll
            for (int mt = 0; mt < 2; ++mt)
#pragma unroll
                for (int nt = 0; nt < 8; ++nt)
                    MMA_TF32(acc[mt][nt], af[mt], bf[nt]);
        }
        __syncthreads();
    }
#pragma unroll
    for (int mt = 0; mt < 2; ++mt) {
#pragma unroll
        for (int i = 0; i < 4; ++i) {
            int row  = wm * 32 + mt * 16 + gid + ((i >> 1) << 3);
            int srow = m0 + row;
            if (srow >= cnt) continue;
            int slot = off + srow;
            float w  = g_row_weight[slot];
            float* orow = g_pout + (size_t)g_s2p[slot] * HIDDEN + n0 + wn * 64;
#pragma unroll
            for (int nt = 0; nt < 8; ++nt)
                orow[nt * 8 + 2 * tig + (i & 1)] = acc[mt][nt][i] * w;
        }
    }
}

// ---------------- combine ----------------
__global__ void combine_kernel(float* __restrict__ out) {
    int t = blockIdx.x, c = threadIdx.x;
    const float* base = g_pout + (size_t)t * TOPK * HIDDEN + c * 4;
    float4 acc = make_float4(0.f, 0.f, 0.f, 0.f);
#pragma unroll
    for (int k = 0; k < TOPK; ++k) {
        float4 v = *(const float4*)(base + (size_t)k * HIDDEN);
        acc.x += v.x; acc.y += v.y; acc.z += v.z; acc.w += v.w;
    }
    *(float4*)(out + (size_t)t * HIDDEN + c * 4) = acc;
}

// ---------------- launch ----------------
extern "C" void kernel_launch(void* const* d_in, const int* in_sizes, int n_in,
                              void* d_out, int out_size) {
    const float* hidden = (const float*)d_in[0];
    const float* logits = (const float*)d_in[1];
    const float* gate   = (const float*)d_in[2];
    const float* up     = (const float*)d_in[3];
    const float* down   = (const float*)d_in[4];
    float* out = (float*)d_out;

    cudaFuncSetAttribute(gemm1_tc, cudaFuncAttributeMaxDynamicSharedMemorySize, 3 * STG + 1024);
    cudaFuncSetAttribute(gemm2_tc, cudaFuncAttributeMaxDynamicSharedMemorySize, 3 * STG + 1024);

    float *wtg, *wtu, *wtd, *rh;
    cudaGetSymbolAddress((void**)&wtg, g_wtg);
    cudaGetSymbolAddress((void**)&wtu, g_wtu);
    cudaGetSymbolAddress((void**)&wtd, g_wtd);
    cudaGetSymbolAddress((void**)&rh,  g_hid);

    selftest_kernel <<<1, 128>>>();
    rnd_kernel      <<<2048, 512>>>((const float4*)hidden, (float4*)rh, TOKENS * HIDDEN / 4);
    tile_kernel     <<<dim3(HIDDEN / 32, INTER / 32, NEXP), 256>>>(gate, wtg, HIDDEN, INTER, 6, KT1);
    tile_kernel     <<<dim3(HIDDEN / 32, INTER / 32, NEXP), 256>>>(up,   wtu, HIDDEN, INTER, 6, KT1);
    tile_kernel     <<<dim3(INTER / 32, HIDDEN / 32, NEXP), 256>>>(down, wtd, INTER, HIDDEN, 16, KT2);
    init_kernel     <<<1, 64>>>();
    route_kernel    <<<TOKENS / 256, 256>>>(logits);
    scan_kernel     <<<1, 32>>>();
    scatter_kernel  <<<NPAIRS / 256, 256>>>();
    gather_kernel   <<<dim3(PBMAX, KT1), 256>>>(hidden);
    gemm1_tc        <<<dim3(MCAP / 256, INTER / 128, NEXP), 256, 3 * STG + 1024>>>();
    verify1_kernel  <<<1, 64>>>();
    gemm1_legacy    <<<dim3(MCAP / 128, INTER / 64,  NEXP), 256>>>(gate, up);
    gemm2_tc        <<<dim3(MCAP / 256, HIDDEN / 256, NEXP), 256, 3 * STG + 1024>>>();
    verify2_kernel  <<<1, 64>>>();
    gemm2_legacy    <<<dim3(MCAP / 128, HIDDEN / 128, NEXP), 256>>>(down);
    combine_kernel  <<<TOKENS, 512>>>(out);
}

// round 12
// speedup vs baseline: 1.7711x; 1.1846x over previous
#include <cuda_runtime.h>
#include <cstdint>

#if defined(__CUDA_ARCH_FEAT_SM103_ALL) || defined(__CUDA_ARCH_FEAT_SM100_ALL) || defined(__CUDA_ARCH_FEAT_SM101_ALL)
#define TC_OK 1
#endif

#define TOKENS 4096
#define HIDDEN 2048
#define INTER  768
#define NEXP   64
#define TOPK   8
#define NPAIRS (TOKENS*TOPK)
#define MCAP   2048
#define BK     32
#define STG    49152        // stage: A 16KB + B 2x16KB
#define KT1    (HIDDEN/BK)  // 64
#define KT2    (INTER/BK)   // 24
#define WSZ    100663296
#define PBMAX  320

__device__ int   g_tc_ok;
__device__ int   g_ok1;
__device__ int   g_ok2;
__device__ int   g_counts[NEXP];
__device__ int   g_offsets[NEXP+1];
__device__ int   g_poff[NEXP+1];
__device__ int   g_cursor[NEXP];
__device__ int   g_pair_e[NPAIRS];
__device__ float g_pair_w[NPAIRS];
__device__ int   g_row_token[NPAIRS];
__device__ float g_row_weight[NPAIRS];
__device__ int   g_s2p[NPAIRS];
__device__ float g_act[(size_t)PBMAX * 128 * INTER];    // tiled [pb][kk24][16KB]
__device__ float g_pout[(size_t)NPAIRS * HIDDEN];
__device__ float g_hid[(size_t)TOKENS * HIDDEN];
__device__ float g_hs[(size_t)PBMAX * 128 * HIDDEN];    // gathered A, tiled [pb][kk64][16KB]
__device__ float g_wtg[WSZ];   // gate^T tiled [e][nb6][kk64][16KB]
__device__ float g_wtu[WSZ];
__device__ float g_wtd[WSZ];   // down^T tiled [e][nb16][kk24][16KB]

__device__ __forceinline__ uint32_t smem_u32(const void* p) {
    return (uint32_t)__cvta_generic_to_shared(p);
}
__device__ __forceinline__ float f2tf(float x) {
    uint32_t r;
    asm("cvt.rna.tf32.f32 %0, %1;" : "=r"(r) : "f"(x));
    return __uint_as_float(r);
}
__device__ __forceinline__ uint32_t f2tfu(float x) {
    uint32_t r;
    asm("cvt.rna.tf32.f32 %0, %1;" : "=r"(r) : "f"(x));
    return r;
}
#define SW128(o) ((o) ^ (((o) >> 3) & 0x70))
#define CP16(d, s) asm volatile("cp.async.cg.shared.global [%0], [%1], 16;\n" :: "r"(d), "l"(s))
#define CP_COMMIT  asm volatile("cp.async.commit_group;\n")
#define CP_WAIT(n) asm volatile("cp.async.wait_group %0;\n" :: "n"(n))
#define MBAR_INIT(mb, c) asm volatile("mbarrier.init.shared.b64 [%0], %1;" :: "r"(mb), "r"(c) : "memory")
#define MBAR_ARRIVE_TX(mb, tx) asm volatile("mbarrier.arrive.expect_tx.shared.b64 _, [%0], %1;" :: "r"(mb), "r"(tx) : "memory")
#define BULK_G2S(dst, src, sz, mb)                                            \
    asm volatile("cp.async.bulk.shared::cluster.global.mbarrier::complete_tx::bytes [%0], [%1], %2, [%3];" \
                 :: "r"(dst), "l"(src), "r"(sz), "r"(mb) : "memory")
#define MBAR_WAIT(mb, ph)                                                     \
    asm volatile("{\n\t.reg .pred P1;\n\t"                                    \
        "WL_%=:\n\t"                                                          \
        "mbarrier.try_wait.parity.acquire.cta.shared::cta.b64 P1, [%0], %1, 0x989680;\n\t" \
        "@P1 bra.uni WD_%=;\n\t"                                              \
        "bra.uni WL_%=;\n\t"                                                  \
        "WD_%=:\n\t}" :: "r"(mb), "r"(ph) : "memory")

#ifdef TC_OK
#define TC_ALLOC(sm, n)  asm volatile("tcgen05.alloc.cta_group::1.sync.aligned.shared::cta.b32 [%0], %1;" :: "r"(sm), "r"(n) : "memory")
#define TC_DEALLOC(t, n) asm volatile("tcgen05.dealloc.cta_group::1.sync.aligned.b32 %0, %1;" :: "r"(t), "r"(n))
#define TC_RELINQ()      asm volatile("tcgen05.relinquish_alloc_permit.cta_group::1.sync.aligned;")
#define TC_COMMIT(mb)    asm volatile("tcgen05.commit.cta_group::1.mbarrier::arrive::one.shared::cluster.b64 [%0];" :: "r"(mb) : "memory")
#define TC_FENCE_AFTER() asm volatile("tcgen05.fence::after_thread_sync;" ::: "memory")
#define TC_WAIT_LD()     asm volatile("tcgen05.wait::ld.sync.aligned;" ::: "memory")
#define FENCE_ASYNC()    asm volatile("fence.proxy.async.shared::cta;" ::: "memory")
#define LDTM_X32(r, a)                                                        \
    asm volatile("tcgen05.ld.sync.aligned.32x32b.x32.b32 "                    \
        "{%0,%1,%2,%3,%4,%5,%6,%7,%8,%9,%10,%11,%12,%13,%14,%15,"             \
        "%16,%17,%18,%19,%20,%21,%22,%23,%24,%25,%26,%27,%28,%29,%30,%31},[%32];" \
        : "=r"((r)[0]),"=r"((r)[1]),"=r"((r)[2]),"=r"((r)[3]),                \
          "=r"((r)[4]),"=r"((r)[5]),"=r"((r)[6]),"=r"((r)[7]),                \
          "=r"((r)[8]),"=r"((r)[9]),"=r"((r)[10]),"=r"((r)[11]),              \
          "=r"((r)[12]),"=r"((r)[13]),"=r"((r)[14]),"=r"((r)[15]),            \
          "=r"((r)[16]),"=r"((r)[17]),"=r"((r)[18]),"=r"((r)[19]),            \
          "=r"((r)[20]),"=r"((r)[21]),"=r"((r)[22]),"=r"((r)[23]),            \
          "=r"((r)[24]),"=r"((r)[25]),"=r"((r)[26]),"=r"((r)[27]),            \
          "=r"((r)[28]),"=r"((r)[29]),"=r"((r)[30]),"=r"((r)[31]) : "r"(a))

__device__ __forceinline__ uint64_t desc_k(uint32_t a) {     // SW128 K-major
    return (uint64_t(2) << 61) | (uint64_t(1) << 46) | (uint64_t(64) << 32) |
           (uint64_t(1) << 16) | ((uint64_t)(a >> 4) & 0x3FFF);
}
#define IDESC32 ((1u<<4)|(2u<<7)|(2u<<10)|(4u<<17)|(8u<<24))
#define IDESC64 ((1u<<4)|(2u<<7)|(2u<<10)|(8u<<17)|(8u<<24))
__device__ __forceinline__ void mma_n32(uint32_t d, uint64_t ad, uint64_t bd, uint32_t acc) {
    asm volatile(
        "{\n\t.reg .pred p;\n\tsetp.ne.u32 p, %4, 0;\n\t"
        "tcgen05.mma.cta_group::1.kind::tf32 [%0], %1, %2, %3, {%5,%5,%5,%5}, p;\n\t}"
        :: "r"(d), "l"(ad), "l"(bd), "r"(IDESC32), "r"(acc), "r"(0u) : "memory");
}
__device__ __forceinline__ void mma_n64(uint32_t d, uint64_t ad, uint64_t bd, uint32_t acc) {
    asm volatile(
        "{\n\t.reg .pred p;\n\tsetp.ne.u32 p, %4, 0;\n\t"
        "tcgen05.mma.cta_group::1.kind::tf32 [%0], %1, %2, %3, {%5,%5,%5,%5}, p;\n\t}"
        :: "r"(d), "l"(ad), "l"(bd), "r"(IDESC64), "r"(acc), "r"(0u) : "memory");
}
#endif

// ---------------- tiled-layout helpers ----------------
__device__ __forceinline__ float wt_read(const float* wt, int NB, int KK, int e, int n, int k) {
    size_t tile = ((size_t)e * NB + (n >> 7)) * KK + (k >> 5);
    uint32_t inner = SW128((uint32_t)(((n & 127) << 7) + ((k & 31) << 2)));
    return *(const float*)((const char*)wt + tile * 16384 + inner);
}
__device__ __forceinline__ char* act_addr(int ps, int k) {
    size_t tile = (size_t)(ps >> 7) * KT2 + (k >> 5);
    uint32_t inner = SW128((uint32_t)(((ps & 127) << 7) + ((k & 31) << 2)));
    return (char*)g_act + tile * 16384 + inner;
}
__device__ __forceinline__ float act_read(int ps, int k) {
    return *(const float*)act_addr(ps, k);
}

// ---------------- self-test ----------------
__device__ __forceinline__ float tva(int m, int k) {
    return f2tf(0.01f * (float)((m * 7 + k * 13) % 31 - 15));
}
__device__ __forceinline__ float tvb(int n, int k) {
    return f2tf(0.02f * (float)((n * 5 + k * 3) % 29 - 14));
}
__global__ void selftest_kernel() {
#ifdef TC_OK
    __shared__ __align__(1024) float sma[4096];
    __shared__ __align__(1024) float smb[1024];
    __shared__ uint32_t s_tmem[1];
    __shared__ __align__(8) uint64_t s_mbar[1];
    __shared__ float s_d, s_r;
    int tid = threadIdx.x, wid = tid >> 5, lane = tid & 31;

    if (wid == 0) { TC_ALLOC(smem_u32(s_tmem), 128); TC_RELINQ(); }
    if (tid == 0) { MBAR_INIT(smem_u32(s_mbar), 1); s_d = 0.f; s_r = 0.f; }
    for (int idx = tid; idx < 4096; idx += 128) {
        int m = idx >> 5, k = idx & 31;
        *(float*)((char*)sma + SW128((uint32_t)(m * 128 + k * 4))) = tva(m, k);
    }
    for (int idx = tid; idx < 1024; idx += 128) {
        int n = idx >> 5, k = idx & 31;
        *(float*)((char*)smb + SW128((uint32_t)(n * 128 + k * 4))) = tvb(n, k);
    }
    __syncthreads();
    uint32_t tmem = s_tmem[0], mb = smem_u32(s_mbar);
    if (tid == 0) {
        FENCE_ASYNC();
        uint64_t ad = desc_k(smem_u32(sma)), bd = desc_k(smem_u32(smb));
#pragma unroll
        for (int ks = 0; ks < 4; ++ks)
            mma_n32(tmem, ad + ks * 2, bd + ks * 2, ks > 0 ? 1u : 0u);
        TC_COMMIT(mb);
    }
    __syncthreads();
    MBAR_WAIT(mb, 0);
    TC_FENCE_AFTER();
    uint32_t r[32];
    LDTM_X32(r, tmem);
    TC_WAIT_LD();
    int m = wid * 32 + lane;
    float d = 0.f, rf = 0.f;
#pragma unroll 4
    for (int n = 0; n < 32; ++n) {
        float ref = 0.f;
        for (int k = 0; k < 32; ++k) ref += tva(m, k) * tvb(n, k);
        d  += fabsf(__uint_as_float(r[n]) - ref);
        rf += fabsf(ref);
    }
    atomicAdd(&s_d, d); atomicAdd(&s_r, rf);
    __syncthreads();
    if (tid == 0) g_tc_ok = (s_d <= 0.01f * s_r + 1e-3f) ? 1 : 0;
    __syncthreads();
    if (wid == 0) TC_DEALLOC(tmem, 128);
#else
    if (threadIdx.x == 0) g_tc_ok = 0;
#endif
}

// ---------------- prep ----------------
__global__ void rnd_kernel(const float4* __restrict__ src, float4* __restrict__ dst, int n4) {
    int i = blockIdx.x * blockDim.x + threadIdx.x, st = gridDim.x * blockDim.x;
    for (; i < n4; i += st) {
        float4 v = src[i];
        v.x = f2tf(v.x); v.y = f2tf(v.y); v.z = f2tf(v.z); v.w = f2tf(v.w);
        dst[i] = v;
    }
}
__global__ void tile_kernel(const float* __restrict__ src, float* __restrict__ dst,
                            int K, int N, int NB, int KK) {
    if (g_tc_ok == 0) return;
    __shared__ float t[32][33];
    int e = blockIdx.z;
    int k0 = blockIdx.x * 32, n0 = blockIdx.y * 32;
    int r = threadIdx.x >> 3, c4 = (threadIdx.x & 7) << 2;
    float4 v = *(const float4*)(src + ((size_t)e * K + k0 + r) * N + n0 + c4);
    t[r][c4] = v.x; t[r][c4 + 1] = v.y; t[r][c4 + 2] = v.z; t[r][c4 + 3] = v.w;
    __syncthreads();
    int n = n0 + r;
    size_t tile = ((size_t)e * NB + (n >> 7)) * KK + (k0 >> 5);
    uint32_t inner = SW128((uint32_t)(((n & 127) << 7) + (c4 << 2)));
    float4 o;
    o.x = f2tf(t[c4    ][r]);
    o.y = f2tf(t[c4 + 1][r]);
    o.z = f2tf(t[c4 + 2][r]);
    o.w = f2tf(t[c4 + 3][r]);
    *(float4*)((char*)dst + tile * 16384 + inner) = o;
}
__global__ void init_kernel() { if (threadIdx.x < NEXP) g_counts[threadIdx.x] = 0; }

__global__ void route_kernel(const float* __restrict__ logits) {
    int t = blockIdx.x * blockDim.x + threadIdx.x;
    if (t >= TOKENS) return;
    float l[NEXP];
    const float* lp = logits + (size_t)t * NEXP;
#pragma unroll
    for (int i = 0; i < NEXP; ++i) l[i] = lp[i];
    float val[TOPK]; int sel[TOPK];
#pragma unroll
    for (int k = 0; k < TOPK; ++k) {
        float best = -1e30f; int bi = 0;
#pragma unroll
        for (int i = 0; i < NEXP; ++i)
            if (l[i] > best) { best = l[i]; bi = i; }
        val[k] = best; sel[k] = bi; l[bi] = -1e30f;
    }
    float m = val[0], s = 0.f, w[TOPK];
#pragma unroll
    for (int k = 0; k < TOPK; ++k) { w[k] = __expf(val[k] - m); s += w[k]; }
    float inv = 1.f / s;
#pragma unroll
    for (int k = 0; k < TOPK; ++k) {
        g_pair_e[t * TOPK + k] = sel[k];
        g_pair_w[t * TOPK + k] = w[k] * inv;
        atomicAdd(&g_counts[sel[k]], 1);
    }
}
__global__ void scan_kernel() {
    if (threadIdx.x == 0) {
        int acc = 0, pacc = 0;
        for (int e = 0; e < NEXP; ++e) {
            g_offsets[e] = acc; g_cursor[e] = acc;
            g_poff[e] = pacc;
            acc += g_counts[e];
            pacc += (g_counts[e] + 127) & ~127;
        }
        g_offsets[NEXP] = acc;
        g_poff[NEXP] = pacc;
    }
}
__global__ void scatter_kernel() {
    int p = blockIdx.x * blockDim.x + threadIdx.x;
    if (p >= NPAIRS) return;
    int slot = atomicAdd(&g_cursor[g_pair_e[p]], 1);
    g_row_token[slot]  = p >> 3;
    g_row_weight[slot] = g_pair_w[p];
    g_s2p[slot] = p;
}
__global__ void gather_kernel(const float* __restrict__ hidden) {
    if (g_tc_ok == 0) return;
    int pb = blockIdx.x, kk = blockIdx.y;
    __shared__ int s_e;
    if (threadIdx.x == 0) {
        int e = 0;
        while (e < NEXP && !(g_poff[e] <= pb * 128 && pb * 128 < g_poff[e + 1])) ++e;
        s_e = e;
    }
    __syncthreads();
    int e = s_e;
    if (e >= NEXP) return;
    int off = g_offsets[e], cnt = g_counts[e];
    char* tile = (char*)g_hs + ((size_t)pb * KT1 + kk) * 16384;
#pragma unroll
    for (int j = 0; j < 4; ++j) {
        int f = threadIdx.x + j * 256;
        int row = f >> 3, c = f & 7;
        int lidx = pb * 128 + row - g_poff[e];
        if (lidx > cnt - 1) lidx = cnt - 1;
        int token = g_row_token[off + lidx];
        float4 v = *(const float4*)(hidden + (size_t)token * HIDDEN + kk * 32 + c * 4);
        v.x = f2tf(v.x); v.y = f2tf(v.y); v.z = f2tf(v.z); v.w = f2tf(v.w);
        *(float4*)(tile + SW128((uint32_t)(row * 128 + c * 16))) = v;
    }
}

// ==== tcgen05 GEMM1: M=128, N=128 (gate+up), 2-stage, 2 CTAs/SM ====
__global__ void __launch_bounds__(256, 2)
gemm1_tc() {
#ifdef TC_OK
    if (g_tc_ok == 0) return;
    int e = blockIdx.z;
    int off = g_offsets[e], cnt = g_offsets[e + 1] - off;
    int m0 = blockIdx.x * 128;
    if (m0 >= cnt) return;
    int nb = blockIdx.y;
    int n0 = nb * 128;

    extern __shared__ char dyn[];
    uint32_t sbase = (smem_u32(dyn) + 1023u) & ~1023u;
    __shared__ uint32_t s_tmem[1];
    __shared__ __align__(8) uint64_t s_full[2], s_mdone[2], s_fin[1];
    int tid = threadIdx.x, wid = tid >> 5, lane = tid & 31;

    if (wid == 0) { TC_ALLOC(smem_u32(s_tmem), 256); TC_RELINQ(); }
    if (tid == 0) {
#pragma unroll
        for (int i = 0; i < 2; ++i) {
            MBAR_INIT(smem_u32(&s_full[i]), 1);
            MBAR_INIT(smem_u32(&s_mdone[i]), 1);
        }
        MBAR_INIT(smem_u32(s_fin), 1);
    }
    __syncthreads();
    uint32_t tmem = s_tmem[0];
    int pb = (g_poff[e] + m0) >> 7;

    if (tid == 32) {   // producer warp: all bulk loads
        uint32_t full[2]  = { smem_u32(&s_full[0]),  smem_u32(&s_full[1])  };
        uint32_t mdone[2] = { smem_u32(&s_mdone[0]), smem_u32(&s_mdone[1]) };
        const char* a0 = (const char*)g_hs + ((size_t)pb * KT1) * 16384;
        const char* tg = (const char*)g_wtg + (((size_t)e * 6 + nb) * KT1) * 16384;
        const char* tu = (const char*)g_wtu + (((size_t)e * 6 + nb) * KT1) * 16384;
        for (int kt = 0; kt < KT1; ++kt) {
            int s = kt & 1;
            if (kt >= 2) MBAR_WAIT(mdone[s], (kt / 2 - 1) & 1);
            MBAR_ARRIVE_TX(full[s], 49152u);
            uint32_t sb = sbase + s * STG;
            BULK_G2S(sb,           a0 + (size_t)kt * 16384, 16384u, full[s]);
            BULK_G2S(sb + 16384u,  tg + (size_t)kt * 16384, 16384u, full[s]);
            BULK_G2S(sb + 32768u,  tu + (size_t)kt * 16384, 16384u, full[s]);
        }
    }
    if (tid == 0) {    // consumer: MMA dispatch only
        uint32_t full[2]  = { smem_u32(&s_full[0]),  smem_u32(&s_full[1])  };
        uint32_t mdone[2] = { smem_u32(&s_mdone[0]), smem_u32(&s_mdone[1]) };
        for (int kt = 0; kt < KT1; ++kt) {
            int s = kt & 1;
            MBAR_WAIT(full[s], (kt / 2) & 1);
            FENCE_ASYNC();
            uint32_t sb = sbase + s * STG;
            uint64_t ad = desc_k(sb);
            uint64_t bg = desc_k(sb + 16384u), bu = desc_k(sb + 32768u);
#pragma unroll
            for (int ks = 0; ks < 4; ++ks) {
                uint32_t acc = (kt > 0 || ks > 0) ? 1u : 0u;
#pragma unroll
                for (int j = 0; j < 2; ++j) {
                    mma_n64(tmem + j * 64,       ad + ks * 2, bg + j * 512 + ks * 2, acc);
                    mma_n64(tmem + 128 + j * 64, ad + ks * 2, bu + j * 512 + ks * 2, acc);
                }
            }
            TC_COMMIT(mdone[s]);
        }
        TC_COMMIT(smem_u32(s_fin));
        MBAR_WAIT(smem_u32(s_fin), 0);
    }
    __syncthreads();
    TC_FENCE_AFTER();

    // epilogue: 8 warps = 4 subpartitions x 2 col-halves; swiglu -> g_act tiled
    int sp = wid & 3, ch = wid >> 2;
    int row = sp * 32 + lane;
    bool valid = (m0 + row) < cnt;
    int ps = g_poff[e] + m0 + row;
    size_t tb0 = (size_t)(ps >> 7) * KT2 * 16384;
    uint32_t rinner = (uint32_t)((ps & 127) << 7);
#pragma unroll
    for (int cb = 0; cb < 2; ++cb) {
        int c0 = ch * 64 + cb * 32;
        uint32_t rg[32], ru[32];
        LDTM_X32(rg, tmem + c0);
        LDTM_X32(ru, tmem + 128 + c0);
        TC_WAIT_LD();
        if (valid) {
            char* tile = (char*)g_act + tb0 + (size_t)((n0 + c0) >> 5) * 16384;
#pragma unroll
            for (int i = 0; i < 32; i += 4) {
                float4 v;
#pragma unroll
                for (int q = 0; q < 4; ++q) {
                    float g = __uint_as_float(rg[i + q]);
                    float u = __uint_as_float(ru[i + q]);
                    ((float*)&v)[q] = f2tf(g / (1.f + __expf(-g)) * u);
                }
                *(float4*)(tile + SW128(rinner + i * 4)) = v;
            }
        }
    }
    __syncthreads();
    if (wid == 0) TC_DEALLOC(tmem, 256);
#endif
}

// ==== tcgen05 GEMM2: M=128, N=256, 2-stage, 2 CTAs/SM ====
__global__ void __launch_bounds__(256, 2)
gemm2_tc() {
#ifdef TC_OK
    if (g_ok1 == 0) return;
    int e = blockIdx.z;
    int off = g_offsets[e], cnt = g_offsets[e + 1] - off;
    int m0 = blockIdx.x * 128;
    if (m0 >= cnt) return;
    int nb0 = blockIdx.y * 2;
    int n0 = nb0 * 128;

    extern __shared__ char dyn[];
    uint32_t sbase = (smem_u32(dyn) + 1023u) & ~1023u;
    __shared__ uint32_t s_tmem[1];
    __shared__ __align__(8) uint64_t s_full[2], s_mdone[2], s_fin[1];
    int tid = threadIdx.x, wid = tid >> 5, lane = tid & 31;

    if (wid == 0) { TC_ALLOC(smem_u32(s_tmem), 256); TC_RELINQ(); }
    if (tid == 0) {
#pragma unroll
        for (int i = 0; i < 2; ++i) {
            MBAR_INIT(smem_u32(&s_full[i]), 1);
            MBAR_INIT(smem_u32(&s_mdone[i]), 1);
        }
        MBAR_INIT(smem_u32(s_fin), 1);
    }
    __syncthreads();
    uint32_t tmem = s_tmem[0];
    int pb = (g_poff[e] + m0) >> 7;

    if (tid == 32) {   // producer
        uint32_t full[2]  = { smem_u32(&s_full[0]),  smem_u32(&s_full[1])  };
        uint32_t mdone[2] = { smem_u32(&s_mdone[0]), smem_u32(&s_mdone[1]) };
        const char* a0 = (const char*)g_act + ((size_t)pb * KT2) * 16384;
        const char* b0p = (const char*)g_wtd + (((size_t)e * 16 + nb0)     * KT2) * 16384;
        const char* b1p = (const char*)g_wtd + (((size_t)e * 16 + nb0 + 1) * KT2) * 16384;
        for (int kt = 0; kt < KT2; ++kt) {
            int s = kt & 1;
            if (kt >= 2) MBAR_WAIT(mdone[s], (kt / 2 - 1) & 1);
            MBAR_ARRIVE_TX(full[s], 49152u);
            uint32_t sb = sbase + s * STG;
            BULK_G2S(sb,          a0  + (size_t)kt * 16384, 16384u, full[s]);
            BULK_G2S(sb + 16384u, b0p + (size_t)kt * 16384, 16384u, full[s]);
            BULK_G2S(sb + 32768u, b1p + (size_t)kt * 16384, 16384u, full[s]);
        }
    }
    if (tid == 0) {    // consumer
        uint32_t full[2]  = { smem_u32(&s_full[0]),  smem_u32(&s_full[1])  };
        uint32_t mdone[2] = { smem_u32(&s_mdone[0]), smem_u32(&s_mdone[1]) };
        for (int kt = 0; kt < KT2; ++kt) {
            int s = kt & 1;
            MBAR_WAIT(full[s], (kt / 2) & 1);
            FENCE_ASYNC();
            uint32_t sb = sbase + s * STG;
            uint64_t ad = desc_k(sb);
            uint64_t b0 = desc_k(sb + 16384u), b1 = desc_k(sb + 32768u);
#pragma unroll
            for (int ks = 0; ks < 4; ++ks) {
                uint32_t acc = (kt > 0 || ks > 0) ? 1u : 0u;
#pragma unroll
                for (int j = 0; j < 4; ++j) {
                    uint64_t bd = (j < 2) ? (b0 + j * 512 + ks * 2)
                                          : (b1 + (j - 2) * 512 + ks * 2);
                    mma_n64(tmem + j * 64, ad + ks * 2, bd, acc);
                }
            }
            TC_COMMIT(mdone[s]);
        }
        TC_COMMIT(smem_u32(s_fin));
        MBAR_WAIT(smem_u32(s_fin), 0);
    }
    __syncthreads();
    TC_FENCE_AFTER();

    int sp = wid & 3, ch = wid >> 2;
    int row = sp * 32 + lane;
    bool valid = (m0 + row) < cnt;
    int slot = off + m0 + row; if (slot > NPAIRS - 1) slot = NPAIRS - 1;
    float w = g_row_weight[slot];
    float* dst = g_pout + (size_t)g_s2p[slot] * HIDDEN + n0;
#pragma unroll
    for (int cb = 0; cb < 4; ++cb) {
        int c0 = ch * 128 + cb * 32;
        uint32_t r[32];
        LDTM_X32(r, tmem + c0);
        TC_WAIT_LD();
        if (valid) {
#pragma unroll
            for (int i = 0; i < 32; i += 4) {
                float4 v;
                ((float*)&v)[0] = __uint_as_float(r[i])     * w;
                ((float*)&v)[1] = __uint_as_float(r[i + 1]) * w;
                ((float*)&v)[2] = __uint_as_float(r[i + 2]) * w;
                ((float*)&v)[3] = __uint_as_float(r[i + 3]) * w;
                *(float4*)(dst + c0 + i) = v;
            }
        }
    }
    __syncthreads();
    if (wid == 0) TC_DEALLOC(tmem, 256);
#endif
}

// ---------------- verifiers: rows 0 AND 150 ----------------
__global__ void verify1_kernel() {
    if (g_tc_ok == 0) { if (threadIdx.x == 0) g_ok1 = 0; return; }
    __shared__ float sd[2], sr[2];
    int e = 0;
    while (g_offsets[e + 1] < 1) ++e;
    int cnt = g_offsets[e + 1] - g_offsets[e];
    int w = threadIdx.x >> 5, lane = threadIdx.x & 31;
    int r = (w == 0) ? 0 : (cnt > 150 ? 150 : cnt - 1);
    int tok = g_row_token[g_offsets[e] + r];
    const float* h = g_hid + (size_t)tok * HIDDEN;
    int j = lane * 24;
    float ag = 0.f, au = 0.f;
    for (int k = 0; k < HIDDEN; ++k) {
        ag += h[k] * wt_read(g_wtg, 6, KT1, e, j, k);
        au += h[k] * wt_read(g_wtu, 6, KT1, e, j, k);
    }
    float ref = f2tf(ag / (1.f + expf(-ag)) * au);
    float d = fabsf(act_read(g_poff[e] + r, j) - ref), rf = fabsf(ref);
#pragma unroll
    for (int o = 16; o; o >>= 1) {
        d  += __shfl_xor_sync(~0u, d, o);
        rf += __shfl_xor_sync(~0u, rf, o);
    }
    if (lane == 0) { sd[w] = d; sr[w] = rf; }
    __syncthreads();
    if (threadIdx.x == 0)
        g_ok1 = (sd[0] + sd[1] <= 0.02f * (sr[0] + sr[1]) + 1e-2f) ? 1 : 0;
}
__global__ void verify2_kernel() {
    if (g_ok1 == 0) { if (threadIdx.x == 0) g_ok2 = 0; return; }
    __shared__ float sd[2], sr[2];
    int e = 0;
    while (g_offsets[e + 1] < 1) ++e;
    int cnt = g_offsets[e + 1] - g_offsets[e];
    int w = threadIdx.x >> 5, lane = threadIdx.x & 31;
    int r = (w == 0) ? 0 : (cnt > 150 ? 150 : cnt - 1);
    int slot = g_offsets[e] + r;
    int p = g_s2p[slot];
    float wgt = g_row_weight[slot];
    int ps = g_poff[e] + r;
    int n = lane * 64;
    float acc = 0.f;
    for (int k = 0; k < INTER; ++k)
        acc += act_read(ps, k) * wt_read(g_wtd, 16, KT2, e, n, k);
    float ref = acc * wgt;
    float d = fabsf(g_pout[(size_t)p * HIDDEN + n] - ref), rf = fabsf(ref);
#pragma unroll
    for (int o = 16; o; o >>= 1) {
        d  += __shfl_xor_sync(~0u, d, o);
        rf += __shfl_xor_sync(~0u, rf, o);
    }
    if (lane == 0) { sd[w] = d; sr[w] = rf; }
    __syncthreads();
    if (threadIdx.x == 0)
        g_ok2 = (sd[0] + sd[1] <= 0.02f * (sr[0] + sr[1]) + 1e-2f) ? 1 : 0;
}

// ================= legacy mma.sync fallback (TILED g_act) =================
#define MMA_TF32(c, a, b)                                                     \
    asm volatile(                                                             \
        "mma.sync.aligned.m16n8k8.row.col.f32.tf32.tf32.f32 "                 \
        "{%0,%1,%2,%3},{%4,%5,%6,%7},{%8,%9},{%0,%1,%2,%3};"                  \
        : "+f"((c)[0]), "+f"((c)[1]), "+f"((c)[2]), "+f"((c)[3])              \
        : "r"((a)[0]), "r"((a)[1]), "r"((a)[2]), "r"((a)[3]),                 \
          "r"((b)[0]), "r"((b)[1]))

__global__ void __launch_bounds__(256, 2)
gemm1_legacy(const float* __restrict__ gate_w, const float* __restrict__ up_w) {
    if (g_ok1) return;
    int e = blockIdx.z;
    int off = g_offsets[e], cnt = g_offsets[e + 1] - off;
    int m0 = blockIdx.x * 128;
    if (m0 >= cnt) return;
    int n0 = blockIdx.y * 64;

    __shared__ float sA [2][128][20];
    __shared__ float sBg[2][16][68];
    __shared__ float sBu[2][16][68];

    int tid = threadIdx.x;
    const size_t wbase = (size_t)e * HIDDEN * INTER;
    int maxslot = off + cnt - 1;

    const float* asrc[2]; int arowi[2], akc[2];
#pragma unroll
    for (int j = 0; j < 2; ++j) {
        int c = tid + j * 256;
        int row = c >> 2, kc = (c & 3) << 2;
        int slot = off + m0 + row; if (slot > maxslot) slot = maxslot;
        asrc[j] = g_hid + (size_t)g_row_token[slot] * HIDDEN + kc;
        arowi[j] = row; akc[j] = kc;
    }
    int bkr = tid >> 4, bnc = (tid & 15) << 2;
    const float* gsrc = gate_w + wbase + (size_t)bkr * INTER + n0 + bnc;
    const float* usrc = up_w   + wbase + (size_t)bkr * INTER + n0 + bnc;

    auto load_tile = [&](int s, int k0) {
#pragma unroll
        for (int j = 0; j < 2; ++j)
            CP16(smem_u32(&sA[s][arowi[j]][akc[j]]), asrc[j] + k0);
        CP16(smem_u32(&sBg[s][bkr][bnc]), gsrc + (size_t)k0 * INTER);
        CP16(smem_u32(&sBu[s][bkr][bnc]), usrc + (size_t)k0 * INTER);
    };

    float cg[2][4][4] = {}, cu[2][4][4] = {};
    int warp = tid >> 5, lane = tid & 31;
    int wm = warp >> 1, wn = warp & 1;
    int gid = lane >> 2, tig = lane & 3;

    load_tile(0, 0); CP_COMMIT;
    const int KT = HIDDEN / 16;
    for (int kt = 0; kt < KT; ++kt) {
        int s = kt & 1;
        if (kt + 1 < KT) { load_tile(s ^ 1, (kt + 1) * 16); CP_COMMIT; CP_WAIT(1); }
        else             { CP_WAIT(0); }
        __syncthreads();
#pragma unroll
        for (int ks = 0; ks < 2; ++ks) {
            int k8 = ks * 8;
            uint32_t af[2][4];
#pragma unroll
            for (int mt = 0; mt < 2; ++mt) {
                int r = wm * 32 + mt * 16;
                af[mt][0] = f2tfu(sA[s][r + gid    ][k8 + tig    ]);
                af[mt][1] = f2tfu(sA[s][r + gid + 8][k8 + tig    ]);
                af[mt][2] = f2tfu(sA[s][r + gid    ][k8 + tig + 4]);
                af[mt][3] = f2tfu(sA[s][r + gid + 8][k8 + tig + 4]);
            }
            uint32_t bg[4][2], bu[4][2];
#pragma unroll
            for (int nt = 0; nt < 4; ++nt) {
                int cix = wn * 32 + nt * 8 + gid;
                bg[nt][0] = f2tfu(sBg[s][k8 + tig    ][cix]);
                bg[nt][1] = f2tfu(sBg[s][k8 + tig + 4][cix]);
                bu[nt][0] = f2tfu(sBu[s][k8 + tig    ][cix]);
                bu[nt][1] = f2tfu(sBu[s][k8 + tig + 4][cix]);
            }
#pragma unroll
            for (int mt = 0; mt < 2; ++mt)
#pragma unroll
                for (int nt = 0; nt < 4; ++nt) {
                    MMA_TF32(cg[mt][nt], af[mt], bg[nt]);
                    MMA_TF32(cu[mt][nt], af[mt], bu[nt]);
                }
        }
        __syncthreads();
    }
#pragma unroll
    for (int mt = 0; mt < 2; ++mt) {
#pragma unroll
        for (int i = 0; i < 4; ++i) {
            int row  = wm * 32 + mt * 16 + gid + ((i >> 1) << 3);
            int srow = m0 + row;
            if (srow >= cnt) continue;
            int ps = g_poff[e] + srow;
#pragma unroll
            for (int nt = 0; nt < 4; ++nt) {
                int k = n0 + wn * 32 + nt * 8 + 2 * tig + (i & 1);
                float g = cg[mt][nt][i], u = cu[mt][nt][i];
                *(float*)act_addr(ps, k) = f2tf(g / (1.f + __expf(-g)) * u);
            }
        }
    }
}

__global__ void __launch_bounds__(256, 2)
gemm2_legacy(const float* __restrict__ down_w) {
    if (g_ok2) return;
    int e = blockIdx.z;
    int off = g_offsets[e], cnt = g_offsets[e + 1] - off;
    int m0 = blockIdx.x * 128;
    if (m0 >= cnt) return;
    int n0 = blockIdx.y * 128;

    __shared__ float sA[2][128][20];
    __shared__ float sB[2][16][132];

    int tid = threadIdx.x;
    const size_t wbase = (size_t)e * INTER * HIDDEN;

    int aps[2], akc2[2], arowi[2];
#pragma unroll
    for (int j = 0; j < 2; ++j) {
        int c = tid + j * 256;
        int row = c >> 2, kc = (c & 3) << 2;
        aps[j] = g_poff[e] + m0 + row;
        arowi[j] = row; akc2[j] = kc;
    }
    const float* bsrc[2]; int bkri[2], bnci[2];
#pragma unroll
    for (int j = 0; j < 2; ++j) {
        int c = tid + j * 256;
        int kr = c >> 5, nc = (c & 31) << 2;
        bsrc[j] = down_w + wbase + (size_t)kr * HIDDEN + n0 + nc;
        bkri[j] = kr; bnci[j] = nc;
    }
    auto load_tile = [&](int s, int k0) {
#pragma unroll
        for (int j = 0; j < 2; ++j)
            CP16(smem_u32(&sA[s][arowi[j]][akc2[j]]), act_addr(aps[j], k0 + akc2[j]));
#pragma unroll
        for (int j = 0; j < 2; ++j)
            CP16(smem_u32(&sB[s][bkri[j]][bnci[j]]), bsrc[j] + (size_t)k0 * HIDDEN);
    };

    float acc[2][8][4] = {};
    int warp = tid >> 5, lane = tid & 31;
    int wm = warp >> 1, wn = warp & 1;
    int gid = lane >> 2, tig = lane & 3;

    load_tile(0, 0); CP_COMMIT;
    const int KT = INTER / 16;
    for (int kt = 0; kt < KT; ++kt) {
        int s = kt & 1;
        if (kt + 1 < KT) { load_tile(s ^ 1, (kt + 1) * 16); CP_COMMIT; CP_WAIT(1); }
        else             { CP_WAIT(0); }
        __syncthreads();
#pragma unroll
        for (int ks = 0; ks < 2; ++ks) {
            int k8 = ks * 8;
            uint32_t af[2][4];
#pragma unroll
            for (int mt = 0; mt < 2; ++mt) {
                int r = wm * 32 + mt * 16;
                af[mt][0] = f2tfu(sA[s][r + gid    ][k8 + tig    ]);
                af[mt][1] = f2tfu(sA[s][r + gid + 8][k8 + tig    ]);
                af[mt][2] = f2tfu(sA[s][r + gid    ][k8 + tig + 4]);
                af[mt][3] = f2tfu(sA[s][r + gid + 8][k8 + tig + 4]);
            }
            uint32_t bf[8][2];
#pragma unroll
            for (int nt = 0; nt < 8; ++nt) {
                int cix = wn * 64 + nt * 8 + gid;
                bf[nt][0] = f2tfu(sB[s][k8 + tig    ][cix]);
                bf[nt][1] = f2tfu(sB[s][k8 + tig + 4][cix]);
            }
#pragma unroll
            for (int mt = 0; mt < 2; ++mt)
#pragma unroll
                for (int nt = 0; nt < 8; ++nt)
                    MMA_TF32(acc[mt][nt], af[mt], bf[nt]);
        }
        __syncthreads();
    }
#pragma unroll
    for (int mt = 0; mt < 2; ++mt) {
#pragma unroll
        for (int i = 0; i < 4; ++i) {
            int row  = wm * 32 + mt * 16 + gid + ((i >> 1) << 3);
            int srow = m0 + row;
            if (srow >= cnt) continue;
            int slot = off + srow;
            float w  = g_row_weight[slot];
            float* orow = g_pout + (size_t)g_s2p[slot] * HIDDEN + n0 + wn * 64;
#pragma unroll
            for (int nt = 0; nt < 8; ++nt)
                orow[nt * 8 + 2 * tig + (i & 1)] = acc[mt][nt][i] * w;
        }
    }
}

// ---------------- combine ----------------
__global__ void combine_kernel(float* __restrict__ out) {
    int t = blockIdx.x, c = threadIdx.x;
    const float* base = g_pout + (size_t)t * TOPK * HIDDEN + c * 4;
    float4 acc = make_float4(0.f, 0.f, 0.f, 0.f);
#pragma unroll
    for (int k = 0; k < TOPK; ++k) {
        float4 v = *(const float4*)(base + (size_t)k * HIDDEN);
        acc.x += v.x; acc.y += v.y; acc.z += v.z; acc.w += v.w;
    }
    *(float4*)(out + (size_t)t * HIDDEN + c * 4) = acc;
}

// ---------------- launch ----------------
extern "C" void kernel_launch(void* const* d_in, const int* in_sizes, int n_in,
                              void* d_out, int out_size) {
    const float* hidden = (const float*)d_in[0];
    const float* logits = (const float*)d_in[1];
    const float* gate   = (const float*)d_in[2];
    const float* up     = (const float*)d_in[3];
    const float* down   = (const float*)d_in[4];
    float* out = (float*)d_out;

    cudaFuncSetAttribute(gemm1_tc, cudaFuncAttributeMaxDynamicSharedMemorySize, 2 * STG + 1024);
    cudaFuncSetAttribute(gemm2_tc, cudaFuncAttributeMaxDynamicSharedMemorySize, 2 * STG + 1024);

    float *wtg, *wtu, *wtd, *rh;
    cudaGetSymbolAddress((void**)&wtg, g_wtg);
    cudaGetSymbolAddress((void**)&wtu, g_wtu);
    cudaGetSymbolAddress((void**)&wtd, g_wtd);
    cudaGetSymbolAddress((void**)&rh,  g_hid);

    selftest_kernel <<<1, 128>>>();
    rnd_kernel      <<<2048, 512>>>((const float4*)hidden, (float4*)rh, TOKENS * HIDDEN / 4);
    tile_kernel     <<<dim3(HIDDEN / 32, INTER / 32, NEXP), 256>>>(gate, wtg, HIDDEN, INTER, 6, KT1);
    tile_kernel     <<<dim3(HIDDEN / 32, INTER / 32, NEXP), 256>>>(up,   wtu, HIDDEN, INTER, 6, KT1);
    tile_kernel     <<<dim3(INTER / 32, HIDDEN / 32, NEXP), 256>>>(down, wtd, INTER, HIDDEN, 16, KT2);
    init_kernel     <<<1, 64>>>();
    route_kernel    <<<TOKENS / 256, 256>>>(logits);
    scan_kernel     <<<1, 32>>>();
    scatter_kernel  <<<NPAIRS / 256, 256>>>();
    gather_kernel   <<<dim3(PBMAX, KT1), 256>>>(hidden);
    gemm1_tc        <<<dim3(MCAP / 128, INTER / 128, NEXP), 256, 2 * STG + 1024>>>();
    verify1_kernel  <<<1, 64>>>();
    gemm1_legacy    <<<dim3(MCAP / 128, INTER / 64,  NEXP), 256>>>(gate, up);
    gemm2_tc        <<<dim3(MCAP / 128, HIDDEN / 256, NEXP), 256, 2 * STG + 1024>>>();
    verify2_kernel  <<<1, 64>>>();
    gemm2_legacy    <<<dim3(MCAP / 128, HIDDEN / 128, NEXP), 256>>>(down);
    combine_kernel  <<<TOKENS, 512>>>(out);
}

// round 13
// speedup vs baseline: 1.8950x; 1.0700x over previous
#include <cuda_runtime.h>
#include <cstdint>

#if defined(__CUDA_ARCH_FEAT_SM103_ALL) || defined(__CUDA_ARCH_FEAT_SM100_ALL) || defined(__CUDA_ARCH_FEAT_SM101_ALL)
#define TC_OK 1
#endif

#define TOKENS 4096
#define HIDDEN 2048
#define INTER  768
#define NEXP   64
#define TOPK   8
#define NPAIRS (TOKENS*TOPK)
#define MCAP   2048
#define BK     32
#define STG    49152        // stage: A 16KB + B 2x16KB
#define KT1    (HIDDEN/BK)  // 64
#define KT2    (INTER/BK)   // 24
#define WSZ    100663296
#define PBMAX  320

__device__ int   g_tc_ok;
__device__ int   g_ok1;
__device__ int   g_ok2;
__device__ int   g_counts[NEXP];
__device__ int   g_offsets[NEXP+1];
__device__ int   g_poff[NEXP+1];
__device__ int   g_cursor[NEXP];
__device__ int   g_pair_e[NPAIRS];
__device__ float g_pair_w[NPAIRS];
__device__ int   g_row_token[NPAIRS];
__device__ float g_row_weight[NPAIRS];
__device__ int   g_s2p[NPAIRS];
__device__ float g_act[(size_t)PBMAX * 128 * INTER];    // tiled [pb][kk24][16KB]
__device__ float g_pout[(size_t)NPAIRS * HIDDEN];
__device__ float g_hs[(size_t)PBMAX * 128 * HIDDEN];    // gathered A, tiled [pb][kk64][16KB]
__device__ float g_wtg[WSZ];   // gate^T tiled [e][nb6][kk64][16KB]
__device__ float g_wtu[WSZ];
__device__ float g_wtd[WSZ];   // down^T tiled [e][nb16][kk24][16KB]

__device__ __forceinline__ uint32_t smem_u32(const void* p) {
    return (uint32_t)__cvta_generic_to_shared(p);
}
__device__ __forceinline__ float f2tf(float x) {
    uint32_t r;
    asm("cvt.rna.tf32.f32 %0, %1;" : "=r"(r) : "f"(x));
    return __uint_as_float(r);
}
__device__ __forceinline__ uint32_t f2tfu(float x) {
    uint32_t r;
    asm("cvt.rna.tf32.f32 %0, %1;" : "=r"(r) : "f"(x));
    return r;
}
#define SW128(o) ((o) ^ (((o) >> 3) & 0x70))
#define CP16(d, s) asm volatile("cp.async.cg.shared.global [%0], [%1], 16;\n" :: "r"(d), "l"(s))
#define CP_COMMIT  asm volatile("cp.async.commit_group;\n")
#define CP_WAIT(n) asm volatile("cp.async.wait_group %0;\n" :: "n"(n))
#define MBAR_INIT(mb, c) asm volatile("mbarrier.init.shared.b64 [%0], %1;" :: "r"(mb), "r"(c) : "memory")
#define MBAR_ARRIVE_TX(mb, tx) asm volatile("mbarrier.arrive.expect_tx.shared.b64 _, [%0], %1;" :: "r"(mb), "r"(tx) : "memory")
#define BULK_G2S(dst, src, sz, mb)                                            \
    asm volatile("cp.async.bulk.shared::cluster.global.mbarrier::complete_tx::bytes [%0], [%1], %2, [%3];" \
                 :: "r"(dst), "l"(src), "r"(sz), "r"(mb) : "memory")
#define MBAR_WAIT(mb, ph)                                                     \
    asm volatile("{\n\t.reg .pred P1;\n\t"                                    \
        "WL_%=:\n\t"                                                          \
        "mbarrier.try_wait.parity.acquire.cta.shared::cta.b64 P1, [%0], %1, 0x989680;\n\t" \
        "@P1 bra.uni WD_%=;\n\t"                                              \
        "bra.uni WL_%=;\n\t"                                                  \
        "WD_%=:\n\t}" :: "r"(mb), "r"(ph) : "memory")

#ifdef TC_OK
#define TC_ALLOC(sm, n)  asm volatile("tcgen05.alloc.cta_group::1.sync.aligned.shared::cta.b32 [%0], %1;" :: "r"(sm), "r"(n) : "memory")
#define TC_DEALLOC(t, n) asm volatile("tcgen05.dealloc.cta_group::1.sync.aligned.b32 %0, %1;" :: "r"(t), "r"(n))
#define TC_RELINQ()      asm volatile("tcgen05.relinquish_alloc_permit.cta_group::1.sync.aligned;")
#define TC_COMMIT(mb)    asm volatile("tcgen05.commit.cta_group::1.mbarrier::arrive::one.shared::cluster.b64 [%0];" :: "r"(mb) : "memory")
#define TC_FENCE_AFTER() asm volatile("tcgen05.fence::after_thread_sync;" ::: "memory")
#define TC_WAIT_LD()     asm volatile("tcgen05.wait::ld.sync.aligned;" ::: "memory")
#define FENCE_ASYNC()    asm volatile("fence.proxy.async.shared::cta;" ::: "memory")
#define LDTM_X32(r, a)                                                        \
    asm volatile("tcgen05.ld.sync.aligned.32x32b.x32.b32 "                    \
        "{%0,%1,%2,%3,%4,%5,%6,%7,%8,%9,%10,%11,%12,%13,%14,%15,"             \
        "%16,%17,%18,%19,%20,%21,%22,%23,%24,%25,%26,%27,%28,%29,%30,%31},[%32];" \
        : "=r"((r)[0]),"=r"((r)[1]),"=r"((r)[2]),"=r"((r)[3]),                \
          "=r"((r)[4]),"=r"((r)[5]),"=r"((r)[6]),"=r"((r)[7]),                \
          "=r"((r)[8]),"=r"((r)[9]),"=r"((r)[10]),"=r"((r)[11]),              \
          "=r"((r)[12]),"=r"((r)[13]),"=r"((r)[14]),"=r"((r)[15]),            \
          "=r"((r)[16]),"=r"((r)[17]),"=r"((r)[18]),"=r"((r)[19]),            \
          "=r"((r)[20]),"=r"((r)[21]),"=r"((r)[22]),"=r"((r)[23]),            \
          "=r"((r)[24]),"=r"((r)[25]),"=r"((r)[26]),"=r"((r)[27]),            \
          "=r"((r)[28]),"=r"((r)[29]),"=r"((r)[30]),"=r"((r)[31]) : "r"(a))

__device__ __forceinline__ uint64_t desc_k(uint32_t a) {     // SW128 K-major
    return (uint64_t(2) << 61) | (uint64_t(1) << 46) | (uint64_t(64) << 32) |
           (uint64_t(1) << 16) | ((uint64_t)(a >> 4) & 0x3FFF);
}
#define IDESC32 ((1u<<4)|(2u<<7)|(2u<<10)|(4u<<17)|(8u<<24))
#define IDESC64 ((1u<<4)|(2u<<7)|(2u<<10)|(8u<<17)|(8u<<24))
__device__ __forceinline__ void mma_n32(uint32_t d, uint64_t ad, uint64_t bd, uint32_t acc) {
    asm volatile(
        "{\n\t.reg .pred p;\n\tsetp.ne.u32 p, %4, 0;\n\t"
        "tcgen05.mma.cta_group::1.kind::tf32 [%0], %1, %2, %3, {%5,%5,%5,%5}, p;\n\t}"
        :: "r"(d), "l"(ad), "l"(bd), "r"(IDESC32), "r"(acc), "r"(0u) : "memory");
}
__device__ __forceinline__ void mma_n64(uint32_t d, uint64_t ad, uint64_t bd, uint32_t acc) {
    asm volatile(
        "{\n\t.reg .pred p;\n\tsetp.ne.u32 p, %4, 0;\n\t"
        "tcgen05.mma.cta_group::1.kind::tf32 [%0], %1, %2, %3, {%5,%5,%5,%5}, p;\n\t}"
        :: "r"(d), "l"(ad), "l"(bd), "r"(IDESC64), "r"(acc), "r"(0u) : "memory");
}
#endif

// ---------------- tiled-layout helpers ----------------
__device__ __forceinline__ float wt_read(const float* wt, int NB, int KK, int e, int n, int k) {
    size_t tile = ((size_t)e * NB + (n >> 7)) * KK + (k >> 5);
    uint32_t inner = SW128((uint32_t)(((n & 127) << 7) + ((k & 31) << 2)));
    return *(const float*)((const char*)wt + tile * 16384 + inner);
}
__device__ __forceinline__ char* act_addr(int ps, int k) {
    size_t tile = (size_t)(ps >> 7) * KT2 + (k >> 5);
    uint32_t inner = SW128((uint32_t)(((ps & 127) << 7) + ((k & 31) << 2)));
    return (char*)g_act + tile * 16384 + inner;
}
__device__ __forceinline__ float act_read(int ps, int k) {
    return *(const float*)act_addr(ps, k);
}

// ---------------- self-test ----------------
__device__ __forceinline__ float tva(int m, int k) {
    return f2tf(0.01f * (float)((m * 7 + k * 13) % 31 - 15));
}
__device__ __forceinline__ float tvb(int n, int k) {
    return f2tf(0.02f * (float)((n * 5 + k * 3) % 29 - 14));
}
__global__ void selftest_kernel() {
#ifdef TC_OK
    __shared__ __align__(1024) float sma[4096];
    __shared__ __align__(1024) float smb[1024];
    __shared__ uint32_t s_tmem[1];
    __shared__ __align__(8) uint64_t s_mbar[1];
    __shared__ float s_d, s_r;
    int tid = threadIdx.x, wid = tid >> 5, lane = tid & 31;

    if (wid == 0) { TC_ALLOC(smem_u32(s_tmem), 128); TC_RELINQ(); }
    if (tid == 0) { MBAR_INIT(smem_u32(s_mbar), 1); s_d = 0.f; s_r = 0.f; }
    for (int idx = tid; idx < 4096; idx += 128) {
        int m = idx >> 5, k = idx & 31;
        *(float*)((char*)sma + SW128((uint32_t)(m * 128 + k * 4))) = tva(m, k);
    }
    for (int idx = tid; idx < 1024; idx += 128) {
        int n = idx >> 5, k = idx & 31;
        *(float*)((char*)smb + SW128((uint32_t)(n * 128 + k * 4))) = tvb(n, k);
    }
    __syncthreads();
    uint32_t tmem = s_tmem[0], mb = smem_u32(s_mbar);
    if (tid == 0) {
        FENCE_ASYNC();
        uint64_t ad = desc_k(smem_u32(sma)), bd = desc_k(smem_u32(smb));
#pragma unroll
        for (int ks = 0; ks < 4; ++ks)
            mma_n32(tmem, ad + ks * 2, bd + ks * 2, ks > 0 ? 1u : 0u);
        TC_COMMIT(mb);
    }
    __syncthreads();
    MBAR_WAIT(mb, 0);
    TC_FENCE_AFTER();
    uint32_t r[32];
    LDTM_X32(r, tmem);
    TC_WAIT_LD();
    int m = wid * 32 + lane;
    float d = 0.f, rf = 0.f;
#pragma unroll 4
    for (int n = 0; n < 32; ++n) {
        float ref = 0.f;
        for (int k = 0; k < 32; ++k) ref += tva(m, k) * tvb(n, k);
        d  += fabsf(__uint_as_float(r[n]) - ref);
        rf += fabsf(ref);
    }
    atomicAdd(&s_d, d); atomicAdd(&s_r, rf);
    __syncthreads();
    if (tid == 0) g_tc_ok = (s_d <= 0.01f * s_r + 1e-3f) ? 1 : 0;
    __syncthreads();
    if (wid == 0) TC_DEALLOC(tmem, 128);
#else
    if (threadIdx.x == 0) g_tc_ok = 0;
#endif
}

// ---------------- prep ----------------
// 2 k-subtiles per block (k-span 64)
__global__ void tile_kernel(const float* __restrict__ src, float* __restrict__ dst,
                            int K, int N, int NB, int KK) {
    if (g_tc_ok == 0) return;
    __shared__ float t[32][33];
    int e = blockIdx.z;
    int k0 = blockIdx.x * 64, n0 = blockIdx.y * 32;
    int r = threadIdx.x >> 3, c4 = (threadIdx.x & 7) << 2;
    int n = n0 + r;
#pragma unroll
    for (int h = 0; h < 2; ++h) {
        int kk0 = k0 + h * 32;
        float4 v = *(const float4*)(src + ((size_t)e * K + kk0 + r) * N + n0 + c4);
        t[r][c4] = v.x; t[r][c4 + 1] = v.y; t[r][c4 + 2] = v.z; t[r][c4 + 3] = v.w;
        __syncthreads();
        size_t tile = ((size_t)e * NB + (n >> 7)) * KK + (kk0 >> 5);
        uint32_t inner = SW128((uint32_t)(((n & 127) << 7) + (c4 << 2)));
        float4 o;
        o.x = f2tf(t[c4    ][r]);
        o.y = f2tf(t[c4 + 1][r]);
        o.z = f2tf(t[c4 + 2][r]);
        o.w = f2tf(t[c4 + 3][r]);
        *(float4*)((char*)dst + tile * 16384 + inner) = o;
        __syncthreads();
    }
}
__global__ void init_kernel() { if (threadIdx.x < NEXP) g_counts[threadIdx.x] = 0; }

__global__ void route_kernel(const float* __restrict__ logits) {
    int t = blockIdx.x * blockDim.x + threadIdx.x;
    if (t >= TOKENS) return;
    float l[NEXP];
    const float* lp = logits + (size_t)t * NEXP;
#pragma unroll
    for (int i = 0; i < NEXP; ++i) l[i] = lp[i];
    float val[TOPK]; int sel[TOPK];
#pragma unroll
    for (int k = 0; k < TOPK; ++k) {
        float best = -1e30f; int bi = 0;
#pragma unroll
        for (int i = 0; i < NEXP; ++i)
            if (l[i] > best) { best = l[i]; bi = i; }
        val[k] = best; sel[k] = bi; l[bi] = -1e30f;
    }
    float m = val[0], s = 0.f, w[TOPK];
#pragma unroll
    for (int k = 0; k < TOPK; ++k) { w[k] = __expf(val[k] - m); s += w[k]; }
    float inv = 1.f / s;
#pragma unroll
    for (int k = 0; k < TOPK; ++k) {
        g_pair_e[t * TOPK + k] = sel[k];
        g_pair_w[t * TOPK + k] = w[k] * inv;
        atomicAdd(&g_counts[sel[k]], 1);
    }
}
__global__ void scan_kernel() {
    if (threadIdx.x == 0) {
        int acc = 0, pacc = 0;
        for (int e = 0; e < NEXP; ++e) {
            g_offsets[e] = acc; g_cursor[e] = acc;
            g_poff[e] = pacc;
            acc += g_counts[e];
            pacc += (g_counts[e] + 127) & ~127;
        }
        g_offsets[NEXP] = acc;
        g_poff[NEXP] = pacc;
    }
}
__global__ void scatter_kernel() {
    int p = blockIdx.x * blockDim.x + threadIdx.x;
    if (p >= NPAIRS) return;
    int slot = atomicAdd(&g_cursor[g_pair_e[p]], 1);
    g_row_token[slot]  = p >> 3;
    g_row_weight[slot] = g_pair_w[p];
    g_s2p[slot] = p;
}
__global__ void gather_kernel(const float* __restrict__ hidden) {
    if (g_tc_ok == 0) return;
    int pb = blockIdx.x, kk = blockIdx.y;
    __shared__ int s_e;
    if (threadIdx.x == 0) {
        int e = 0;
        while (e < NEXP && !(g_poff[e] <= pb * 128 && pb * 128 < g_poff[e + 1])) ++e;
        s_e = e;
    }
    __syncthreads();
    int e = s_e;
    if (e >= NEXP) return;
    int off = g_offsets[e], cnt = g_counts[e];
    char* tile = (char*)g_hs + ((size_t)pb * KT1 + kk) * 16384;
#pragma unroll
    for (int j = 0; j < 4; ++j) {
        int f = threadIdx.x + j * 256;
        int row = f >> 3, c = f & 7;
        int lidx = pb * 128 + row - g_poff[e];
        if (lidx > cnt - 1) lidx = cnt - 1;
        int token = g_row_token[off + lidx];
        float4 v = *(const float4*)(hidden + (size_t)token * HIDDEN + kk * 32 + c * 4);
        v.x = f2tf(v.x); v.y = f2tf(v.y); v.z = f2tf(v.z); v.w = f2tf(v.w);
        *(float4*)(tile + SW128((uint32_t)(row * 128 + c * 16))) = v;
    }
}

// ==== tcgen05 GEMM1: M=128, N=128 (gate+up), 2-stage, 2 CTAs/SM ====
__global__ void __launch_bounds__(256, 2)
gemm1_tc() {
#ifdef TC_OK
    if (g_tc_ok == 0) return;
    int e = blockIdx.z;
    int off = g_offsets[e], cnt = g_offsets[e + 1] - off;
    int m0 = blockIdx.x * 128;
    if (m0 >= cnt) return;
    int nb = blockIdx.y;
    int n0 = nb * 128;

    extern __shared__ char dyn[];
    uint32_t sbase = (smem_u32(dyn) + 1023u) & ~1023u;
    __shared__ uint32_t s_tmem[1];
    __shared__ __align__(8) uint64_t s_full[2], s_mdone[2], s_fin[1];
    int tid = threadIdx.x, wid = tid >> 5, lane = tid & 31;

    if (wid == 0) { TC_ALLOC(smem_u32(s_tmem), 256); TC_RELINQ(); }
    if (tid == 0) {
#pragma unroll
        for (int i = 0; i < 2; ++i) {
            MBAR_INIT(smem_u32(&s_full[i]), 1);
            MBAR_INIT(smem_u32(&s_mdone[i]), 1);
        }
        MBAR_INIT(smem_u32(s_fin), 1);
    }
    __syncthreads();
    uint32_t tmem = s_tmem[0];
    int pb = (g_poff[e] + m0) >> 7;

    if (tid == 32) {   // producer warp
        uint32_t full[2]  = { smem_u32(&s_full[0]),  smem_u32(&s_full[1])  };
        uint32_t mdone[2] = { smem_u32(&s_mdone[0]), smem_u32(&s_mdone[1]) };
        const char* a0 = (const char*)g_hs + ((size_t)pb * KT1) * 16384;
        const char* tg = (const char*)g_wtg + (((size_t)e * 6 + nb) * KT1) * 16384;
        const char* tu = (const char*)g_wtu + (((size_t)e * 6 + nb) * KT1) * 16384;
        for (int kt = 0; kt < KT1; ++kt) {
            int s = kt & 1;
            if (kt >= 2) MBAR_WAIT(mdone[s], (kt / 2 - 1) & 1);
            MBAR_ARRIVE_TX(full[s], 49152u);
            uint32_t sb = sbase + s * STG;
            BULK_G2S(sb,           a0 + (size_t)kt * 16384, 16384u, full[s]);
            BULK_G2S(sb + 16384u,  tg + (size_t)kt * 16384, 16384u, full[s]);
            BULK_G2S(sb + 32768u,  tu + (size_t)kt * 16384, 16384u, full[s]);
        }
    }
    if (tid == 0) {    // consumer
        uint32_t full[2]  = { smem_u32(&s_full[0]),  smem_u32(&s_full[1])  };
        uint32_t mdone[2] = { smem_u32(&s_mdone[0]), smem_u32(&s_mdone[1]) };
        for (int kt = 0; kt < KT1; ++kt) {
            int s = kt & 1;
            MBAR_WAIT(full[s], (kt / 2) & 1);
            FENCE_ASYNC();
            uint32_t sb = sbase + s * STG;
            uint64_t ad = desc_k(sb);
            uint64_t bg = desc_k(sb + 16384u), bu = desc_k(sb + 32768u);
#pragma unroll
            for (int ks = 0; ks < 4; ++ks) {
                uint32_t acc = (kt > 0 || ks > 0) ? 1u : 0u;
#pragma unroll
                for (int j = 0; j < 2; ++j) {
                    mma_n64(tmem + j * 64,       ad + ks * 2, bg + j * 512 + ks * 2, acc);
                    mma_n64(tmem + 128 + j * 64, ad + ks * 2, bu + j * 512 + ks * 2, acc);
                }
            }
            TC_COMMIT(mdone[s]);
        }
        TC_COMMIT(smem_u32(s_fin));
        MBAR_WAIT(smem_u32(s_fin), 0);
    }
    __syncthreads();
    TC_FENCE_AFTER();

    int sp = wid & 3, ch = wid >> 2;
    int row = sp * 32 + lane;
    bool valid = (m0 + row) < cnt;
    int ps = g_poff[e] + m0 + row;
    size_t tb0 = (size_t)(ps >> 7) * KT2 * 16384;
    uint32_t rinner = (uint32_t)((ps & 127) << 7);
#pragma unroll
    for (int cb = 0; cb < 2; ++cb) {
        int c0 = ch * 64 + cb * 32;
        uint32_t rg[32], ru[32];
        LDTM_X32(rg, tmem + c0);
        LDTM_X32(ru, tmem + 128 + c0);
        TC_WAIT_LD();
        if (valid) {
            char* tile = (char*)g_act + tb0 + (size_t)((n0 + c0) >> 5) * 16384;
#pragma unroll
            for (int i = 0; i < 32; i += 4) {
                float4 v;
#pragma unroll
                for (int q = 0; q < 4; ++q) {
                    float g = __uint_as_float(rg[i + q]);
                    float u = __uint_as_float(ru[i + q]);
                    ((float*)&v)[q] = f2tf(g / (1.f + __expf(-g)) * u);
                }
                *(float4*)(tile + SW128(rinner + i * 4)) = v;
            }
        }
    }
    __syncthreads();
    if (wid == 0) TC_DEALLOC(tmem, 256);
#endif
}

// ==== tcgen05 GEMM2: M=128, N=256, 2-stage, 2 CTAs/SM ====
__global__ void __launch_bounds__(256, 2)
gemm2_tc() {
#ifdef TC_OK
    if (g_ok1 == 0) return;
    int e = blockIdx.z;
    int off = g_offsets[e], cnt = g_offsets[e + 1] - off;
    int m0 = blockIdx.x * 128;
    if (m0 >= cnt) return;
    int nb0 = blockIdx.y * 2;
    int n0 = nb0 * 128;

    extern __shared__ char dyn[];
    uint32_t sbase = (smem_u32(dyn) + 1023u) & ~1023u;
    __shared__ uint32_t s_tmem[1];
    __shared__ __align__(8) uint64_t s_full[2], s_mdone[2], s_fin[1];
    int tid = threadIdx.x, wid = tid >> 5, lane = tid & 31;

    if (wid == 0) { TC_ALLOC(smem_u32(s_tmem), 256); TC_RELINQ(); }
    if (tid == 0) {
#pragma unroll
        for (int i = 0; i < 2; ++i) {
            MBAR_INIT(smem_u32(&s_full[i]), 1);
            MBAR_INIT(smem_u32(&s_mdone[i]), 1);
        }
        MBAR_INIT(smem_u32(s_fin), 1);
    }
    __syncthreads();
    uint32_t tmem = s_tmem[0];
    int pb = (g_poff[e] + m0) >> 7;

    if (tid == 32) {   // producer
        uint32_t full[2]  = { smem_u32(&s_full[0]),  smem_u32(&s_full[1])  };
        uint32_t mdone[2] = { smem_u32(&s_mdone[0]), smem_u32(&s_mdone[1]) };
        const char* a0 = (const char*)g_act + ((size_t)pb * KT2) * 16384;
        const char* b0p = (const char*)g_wtd + (((size_t)e * 16 + nb0)     * KT2) * 16384;
        const char* b1p = (const char*)g_wtd + (((size_t)e * 16 + nb0 + 1) * KT2) * 16384;
        for (int kt = 0; kt < KT2; ++kt) {
            int s = kt & 1;
            if (kt >= 2) MBAR_WAIT(mdone[s], (kt / 2 - 1) & 1);
            MBAR_ARRIVE_TX(full[s], 49152u);
            uint32_t sb = sbase + s * STG;
            BULK_G2S(sb,          a0  + (size_t)kt * 16384, 16384u, full[s]);
            BULK_G2S(sb + 16384u, b0p + (size_t)kt * 16384, 16384u, full[s]);
            BULK_G2S(sb + 32768u, b1p + (size_t)kt * 16384, 16384u, full[s]);
        }
    }
    if (tid == 0) {    // consumer
        uint32_t full[2]  = { smem_u32(&s_full[0]),  smem_u32(&s_full[1])  };
        uint32_t mdone[2] = { smem_u32(&s_mdone[0]), smem_u32(&s_mdone[1]) };
        for (int kt = 0; kt < KT2; ++kt) {
            int s = kt & 1;
            MBAR_WAIT(full[s], (kt / 2) & 1);
            FENCE_ASYNC();
            uint32_t sb = sbase + s * STG;
            uint64_t ad = desc_k(sb);
            uint64_t b0 = desc_k(sb + 16384u), b1 = desc_k(sb + 32768u);
#pragma unroll
            for (int ks = 0; ks < 4; ++ks) {
                uint32_t acc = (kt > 0 || ks > 0) ? 1u : 0u;
#pragma unroll
                for (int j = 0; j < 4; ++j) {
                    uint64_t bd = (j < 2) ? (b0 + j * 512 + ks * 2)
                                          : (b1 + (j - 2) * 512 + ks * 2);
                    mma_n64(tmem + j * 64, ad + ks * 2, bd, acc);
                }
            }
            TC_COMMIT(mdone[s]);
        }
        TC_COMMIT(smem_u32(s_fin));
        MBAR_WAIT(smem_u32(s_fin), 0);
    }
    __syncthreads();
    TC_FENCE_AFTER();

    int sp = wid & 3, ch = wid >> 2;
    int row = sp * 32 + lane;
    bool valid = (m0 + row) < cnt;
    int slot = off + m0 + row; if (slot > NPAIRS - 1) slot = NPAIRS - 1;
    float w = g_row_weight[slot];
    float* dst = g_pout + (size_t)g_s2p[slot] * HIDDEN + n0;
#pragma unroll
    for (int cb = 0; cb < 4; ++cb) {
        int c0 = ch * 128 + cb * 32;
        uint32_t r[32];
        LDTM_X32(r, tmem + c0);
        TC_WAIT_LD();
        if (valid) {
#pragma unroll
            for (int i = 0; i < 32; i += 4) {
                float4 v;
                ((float*)&v)[0] = __uint_as_float(r[i])     * w;
                ((float*)&v)[1] = __uint_as_float(r[i + 1]) * w;
                ((float*)&v)[2] = __uint_as_float(r[i + 2]) * w;
                ((float*)&v)[3] = __uint_as_float(r[i + 3]) * w;
                *(float4*)(dst + c0 + i) = v;
            }
        }
    }
    __syncthreads();
    if (wid == 0) TC_DEALLOC(tmem, 256);
#endif
}

// ---------------- verifiers: rows 0 AND 150 ----------------
__global__ void verify1_kernel(const float* __restrict__ hidden) {
    if (g_tc_ok == 0) { if (threadIdx.x == 0) g_ok1 = 0; return; }
    __shared__ float sd[2], sr[2];
    int e = 0;
    while (g_offsets[e + 1] < 1) ++e;
    int cnt = g_offsets[e + 1] - g_offsets[e];
    int w = threadIdx.x >> 5, lane = threadIdx.x & 31;
    int r = (w == 0) ? 0 : (cnt > 150 ? 150 : cnt - 1);
    int tok = g_row_token[g_offsets[e] + r];
    const float* h = hidden + (size_t)tok * HIDDEN;
    int j = lane * 24;
    float ag = 0.f, au = 0.f;
    for (int k = 0; k < HIDDEN; ++k) {
        float hv = f2tf(h[k]);
        ag += hv * wt_read(g_wtg, 6, KT1, e, j, k);
        au += hv * wt_read(g_wtu, 6, KT1, e, j, k);
    }
    float ref = f2tf(ag / (1.f + expf(-ag)) * au);
    float d = fabsf(act_read(g_poff[e] + r, j) - ref), rf = fabsf(ref);
#pragma unroll
    for (int o = 16; o; o >>= 1) {
        d  += __shfl_xor_sync(~0u, d, o);
        rf += __shfl_xor_sync(~0u, rf, o);
    }
    if (lane == 0) { sd[w] = d; sr[w] = rf; }
    __syncthreads();
    if (threadIdx.x == 0)
        g_ok1 = (sd[0] + sd[1] <= 0.02f * (sr[0] + sr[1]) + 1e-2f) ? 1 : 0;
}
__global__ void verify2_kernel() {
    if (g_ok1 == 0) { if (threadIdx.x == 0) g_ok2 = 0; return; }
    __shared__ float sd[2], sr[2];
    int e = 0;
    while (g_offsets[e + 1] < 1) ++e;
    int cnt = g_offsets[e + 1] - g_offsets[e];
    int w = threadIdx.x >> 5, lane = threadIdx.x & 31;
    int r = (w == 0) ? 0 : (cnt > 150 ? 150 : cnt - 1);
    int slot = g_offsets[e] + r;
    int p = g_s2p[slot];
    float wgt = g_row_weight[slot];
    int ps = g_poff[e] + r;
    int n = lane * 64;
    float acc = 0.f;
    for (int k = 0; k < INTER; ++k)
        acc += act_read(ps, k) * wt_read(g_wtd, 16, KT2, e, n, k);
    float ref = acc * wgt;
    float d = fabsf(g_pout[(size_t)p * HIDDEN + n] - ref), rf = fabsf(ref);
#pragma unroll
    for (int o = 16; o; o >>= 1) {
        d  += __shfl_xor_sync(~0u, d, o);
        rf += __shfl_xor_sync(~0u, rf, o);
    }
    if (lane == 0) { sd[w] = d; sr[w] = rf; }
    __syncthreads();
    if (threadIdx.x == 0)
        g_ok2 = (sd[0] + sd[1] <= 0.02f * (sr[0] + sr[1]) + 1e-2f) ? 1 : 0;
}

// ================= legacy mma.sync fallback (TILED g_act) =================
#define MMA_TF32(c, a, b)                                                     \
    asm volatile(                                                             \
        "mma.sync.aligned.m16n8k8.row.col.f32.tf32.tf32.f32 "                 \
        "{%0,%1,%2,%3},{%4,%5,%6,%7},{%8,%9},{%0,%1,%2,%3};"                  \
        : "+f"((c)[0]), "+f"((c)[1]), "+f"((c)[2]), "+f"((c)[3])              \
        : "r"((a)[0]), "r"((a)[1]), "r"((a)[2]), "r"((a)[3]),                 \
          "r"((b)[0]), "r"((b)[1]))

__global__ void __launch_bounds__(256, 2)
gemm1_legacy(const float* __restrict__ hidden,
             const float* __restrict__ gate_w, const float* __restrict__ up_w) {
    if (g_ok1) return;
    int e = blockIdx.z;
    int off = g_offsets[e], cnt = g_offsets[e + 1] - off;
    int m0 = blockIdx.x * 128;
    if (m0 >= cnt) return;
    int n0 = blockIdx.y * 64;

    __shared__ float sA [2][128][20];
    __shared__ float sBg[2][16][68];
    __shared__ float sBu[2][16][68];

    int tid = threadIdx.x;
    const size_t wbase = (size_t)e * HIDDEN * INTER;
    int maxslot = off + cnt - 1;

    const float* asrc[2]; int arowi[2], akc[2];
#pragma unroll
    for (int j = 0; j < 2; ++j) {
        int c = tid + j * 256;
        int row = c >> 2, kc = (c & 3) << 2;
        int slot = off + m0 + row; if (slot > maxslot) slot = maxslot;
        asrc[j] = hidden + (size_t)g_row_token[slot] * HIDDEN + kc;
        arowi[j] = row; akc[j] = kc;
    }
    int bkr = tid >> 4, bnc = (tid & 15) << 2;
    const float* gsrc = gate_w + wbase + (size_t)bkr * INTER + n0 + bnc;
    const float* usrc = up_w   + wbase + (size_t)bkr * INTER + n0 + bnc;

    auto load_tile = [&](int s, int k0) {
#pragma unroll
        for (int j = 0; j < 2; ++j)
            CP16(smem_u32(&sA[s][arowi[j]][akc[j]]), asrc[j] + k0);
        CP16(smem_u32(&sBg[s][bkr][bnc]), gsrc + (size_t)k0 * INTER);
        CP16(smem_u32(&sBu[s][bkr][bnc]), usrc + (size_t)k0 * INTER);
    };

    float cg[2][4][4] = {}, cu[2][4][4] = {};
    int warp = tid >> 5, lane = tid & 31;
    int wm = warp >> 1, wn = warp & 1;
    int gid = lane >> 2, tig = lane & 3;

    load_tile(0, 0); CP_COMMIT;
    const int KT = HIDDEN / 16;
    for (int kt = 0; kt < KT; ++kt) {
        int s = kt & 1;
        if (kt + 1 < KT) { load_tile(s ^ 1, (kt + 1) * 16); CP_COMMIT; CP_WAIT(1); }
        else             { CP_WAIT(0); }
        __syncthreads();
#pragma unroll
        for (int ks = 0; ks < 2; ++ks) {
            int k8 = ks * 8;
            uint32_t af[2][4];
#pragma unroll
            for (int mt = 0; mt < 2; ++mt) {
                int r = wm * 32 + mt * 16;
                af[mt][0] = f2tfu(sA[s][r + gid    ][k8 + tig    ]);
                af[mt][1] = f2tfu(sA[s][r + gid + 8][k8 + tig    ]);
                af[mt][2] = f2tfu(sA[s][r + gid    ][k8 + tig + 4]);
                af[mt][3] = f2tfu(sA[s][r + gid + 8][k8 + tig + 4]);
            }
            uint32_t bg[4][2], bu[4][2];
#pragma unroll
            for (int nt = 0; nt < 4; ++nt) {
                int cix = wn * 32 + nt * 8 + gid;
                bg[nt][0] = f2tfu(sBg[s][k8 + tig    ][cix]);
                bg[nt][1] = f2tfu(sBg[s][k8 + tig + 4][cix]);
                bu[nt][0] = f2tfu(sBu[s][k8 + tig    ][cix]);
                bu[nt][1] = f2tfu(sBu[s][k8 + tig + 4][cix]);
            }
#pragma unroll
            for (int mt = 0; mt < 2; ++mt)
#pragma unroll
                for (int nt = 0; nt < 4; ++nt) {
                    MMA_TF32(cg[mt][nt], af[mt], bg[nt]);
                    MMA_TF32(cu[mt][nt], af[mt], bu[nt]);
                }
        }
        __syncthreads();
    }
#pragma unroll
    for (int mt = 0; mt < 2; ++mt) {
#pragma unroll
        for (int i = 0; i < 4; ++i) {
            int row  = wm * 32 + mt * 16 + gid + ((i >> 1) << 3);
            int srow = m0 + row;
            if (srow >= cnt) continue;
            int ps = g_poff[e] + srow;
#pragma unroll
            for (int nt = 0; nt < 4; ++nt) {
                int k = n0 + wn * 32 + nt * 8 + 2 * tig + (i & 1);
                float g = cg[mt][nt][i], u = cu[mt][nt][i];
                *(float*)act_addr(ps, k) = f2tf(g / (1.f + __expf(-g)) * u);
            }
        }
    }
}

__global__ void __launch_bounds__(256, 2)
gemm2_legacy(const float* __restrict__ down_w) {
    if (g_ok2) return;
    int e = blockIdx.z;
    int off = g_offsets[e], cnt = g_offsets[e + 1] - off;
    int m0 = blockIdx.x * 128;
    if (m0 >= cnt) return;
    int n0 = blockIdx.y * 128;

    __shared__ float sA[2][128][20];
    __shared__ float sB[2][16][132];

    int tid = threadIdx.x;
    const size_t wbase = (size_t)e * INTER * HIDDEN;

    int aps[2], akc2[2], arowi[2];
#pragma unroll
    for (int j = 0; j < 2; ++j) {
        int c = tid + j * 256;
        int row = c >> 2, kc = (c & 3) << 2;
        aps[j] = g_poff[e] + m0 + row;
        arowi[j] = row; akc2[j] = kc;
    }
    const float* bsrc[2]; int bkri[2], bnci[2];
#pragma unroll
    for (int j = 0; j < 2; ++j) {
        int c = tid + j * 256;
        int kr = c >> 5, nc = (c & 31) << 2;
        bsrc[j] = down_w + wbase + (size_t)kr * HIDDEN + n0 + nc;
        bkri[j] = kr; bnci[j] = nc;
    }
    auto load_tile = [&](int s, int k0) {
#pragma unroll
        for (int j = 0; j < 2; ++j)
            CP16(smem_u32(&sA[s][arowi[j]][akc2[j]]), act_addr(aps[j], k0 + akc2[j]));
#pragma unroll
        for (int j = 0; j < 2; ++j)
            CP16(smem_u32(&sB[s][bkri[j]][bnci[j]]), bsrc[j] + (size_t)k0 * HIDDEN);
    };

    float acc[2][8][4] = {};
    int warp = tid >> 5, lane = tid & 31;
    int wm = warp >> 1, wn = warp & 1;
    int gid = lane >> 2, tig = lane & 3;

    load_tile(0, 0); CP_COMMIT;
    const int KT = INTER / 16;
    for (int kt = 0; kt < KT; ++kt) {
        int s = kt & 1;
        if (kt + 1 < KT) { load_tile(s ^ 1, (kt + 1) * 16); CP_COMMIT; CP_WAIT(1); }
        else             { CP_WAIT(0); }
        __syncthreads();
#pragma unroll
        for (int ks = 0; ks < 2; ++ks) {
            int k8 = ks * 8;
            uint32_t af[2][4];
#pragma unroll
            for (int mt = 0; mt < 2; ++mt) {
                int r = wm * 32 + mt * 16;
                af[mt][0] = f2tfu(sA[s][r + gid    ][k8 + tig    ]);
                af[mt][1] = f2tfu(sA[s][r + gid + 8][k8 + tig    ]);
                af[mt][2] = f2tfu(sA[s][r + gid    ][k8 + tig + 4]);
                af[mt][3] = f2tfu(sA[s][r + gid + 8][k8 + tig + 4]);
            }
            uint32_t bf[8][2];
#pragma unroll
            for (int nt = 0; nt < 8; ++nt) {
                int cix = wn * 64 + nt * 8 + gid;
                bf[nt][0] = f2tfu(sB[s][k8 + tig    ][cix]);
                bf[nt][1] = f2tfu(sB[s][k8 + tig + 4][cix]);
            }
#pragma unroll
            for (int mt = 0; mt < 2; ++mt)
#pragma unroll
                for (int nt = 0; nt < 8; ++nt)
                    MMA_TF32(acc[mt][nt], af[mt], bf[nt]);
        }
        __syncthreads();
    }
#pragma unroll
    for (int mt = 0; mt < 2; ++mt) {
#pragma unroll
        for (int i = 0; i < 4; ++i) {
            int row  = wm * 32 + mt * 16 + gid + ((i >> 1) << 3);
            int srow = m0 + row;
            if (srow >= cnt) continue;
            int slot = off + srow;
            float w  = g_row_weight[slot];
            float* orow = g_pout + (size_t)g_s2p[slot] * HIDDEN + n0 + wn * 64;
#pragma unroll
            for (int nt = 0; nt < 8; ++nt)
                orow[nt * 8 + 2 * tig + (i & 1)] = acc[mt][nt][i] * w;
        }
    }
}

// ---------------- combine ----------------
__global__ void combine_kernel(float* __restrict__ out) {
    int t = blockIdx.x, c = threadIdx.x;
    const float* base = g_pout + (size_t)t * TOPK * HIDDEN + c * 4;
    float4 acc = make_float4(0.f, 0.f, 0.f, 0.f);
#pragma unroll
    for (int k = 0; k < TOPK; ++k) {
        float4 v = *(const float4*)(base + (size_t)k * HIDDEN);
        acc.x += v.x; acc.y += v.y; acc.z += v.z; acc.w += v.w;
    }
    *(float4*)(out + (size_t)t * HIDDEN + c * 4) = acc;
}

// ---------------- launch ----------------
extern "C" void kernel_launch(void* const* d_in, const int* in_sizes, int n_in,
                              void* d_out, int out_size) {
    const float* hidden = (const float*)d_in[0];
    const float* logits = (const float*)d_in[1];
    const float* gate   = (const float*)d_in[2];
    const float* up     = (const float*)d_in[3];
    const float* down   = (const float*)d_in[4];
    float* out = (float*)d_out;

    static cudaStream_t s2 = nullptr;
    static cudaEvent_t evF = nullptr, evJ = nullptr;
    if (s2 == nullptr) {   // first (non-captured) correctness call
        cudaStreamCreateWithFlags(&s2, cudaStreamNonBlocking);
        cudaEventCreateWithFlags(&evF, cudaEventDisableTiming);
        cudaEventCreateWithFlags(&evJ, cudaEventDisableTiming);
        cudaFuncSetAttribute(gemm1_tc, cudaFuncAttributeMaxDynamicSharedMemorySize, 2 * STG + 1024);
        cudaFuncSetAttribute(gemm2_tc, cudaFuncAttributeMaxDynamicSharedMemorySize, 2 * STG + 1024);
    }

    float *wtg, *wtu, *wtd;
    cudaGetSymbolAddress((void**)&wtg, g_wtg);
    cudaGetSymbolAddress((void**)&wtu, g_wtu);
    cudaGetSymbolAddress((void**)&wtd, g_wtd);

    selftest_kernel <<<1, 128>>>();

    // fork: routing chain on s2, overlapped with the weight tile pass
    cudaEventRecord(evF, 0);
    cudaStreamWaitEvent(s2, evF, 0);
    init_kernel     <<<1, 64, 0, s2>>>();
    route_kernel    <<<TOKENS / 256, 256, 0, s2>>>(logits);
    scan_kernel     <<<1, 32, 0, s2>>>();
    scatter_kernel  <<<NPAIRS / 256, 256, 0, s2>>>();
    gather_kernel   <<<dim3(PBMAX, KT1), 256, 0, s2>>>(hidden);
    cudaEventRecord(evJ, s2);

    // main stream: weight tiling
    tile_kernel     <<<dim3(HIDDEN / 64, INTER / 32, NEXP), 256>>>(gate, wtg, HIDDEN, INTER, 6, KT1);
    tile_kernel     <<<dim3(HIDDEN / 64, INTER / 32, NEXP), 256>>>(up,   wtu, HIDDEN, INTER, 6, KT1);
    tile_kernel     <<<dim3(INTER / 64, HIDDEN / 32, NEXP), 256>>>(down, wtd, INTER, HIDDEN, 16, KT2);

    cudaStreamWaitEvent(0, evJ, 0);   // join before GEMM1
    gemm1_tc        <<<dim3(MCAP / 128, INTER / 128, NEXP), 256, 2 * STG + 1024>>>();
    verify1_kernel  <<<1, 64>>>(hidden);
    gemm1_legacy    <<<dim3(MCAP / 128, INTER / 64,  NEXP), 256>>>(hidden, gate, up);
    gemm2_tc        <<<dim3(MCAP / 128, HIDDEN / 256, NEXP), 256, 2 * STG + 1024>>>();
    verify2_kernel  <<<1, 64>>>();
    gemm2_legacy    <<<dim3(MCAP / 128, HIDDEN / 128, NEXP), 256>>>(down);
    combine_kernel  <<<TOKENS, 512>>>(out);
}

// round 14
// speedup vs baseline: 1.8996x; 1.0024x over previous
#include <cuda_runtime.h>
#include <cstdint>

#if defined(__CUDA_ARCH_FEAT_SM103_ALL) || defined(__CUDA_ARCH_FEAT_SM100_ALL) || defined(__CUDA_ARCH_FEAT_SM101_ALL)
#define TC_OK 1
#endif

#define TOKENS 4096
#define HIDDEN 2048
#define INTER  768
#define NEXP   64
#define TOPK   8
#define NPAIRS (TOKENS*TOPK)
#define MCAP   2048
#define BK     32
#define STG    49152        // stage: A 16KB + B 2x16KB
#define KT1    (HIDDEN/BK)  // 64
#define KT2    (INTER/BK)   // 24
#define WSZ    100663296
#define PBMAX  320

__device__ int   g_tc_ok;
__device__ int   g_ok1;
__device__ int   g_ok2;
__device__ int   g_counts[NEXP];
__device__ int   g_offsets[NEXP+1];
__device__ int   g_poff[NEXP+1];
__device__ int   g_cursor[NEXP];
__device__ int   g_pair_e[NPAIRS];
__device__ float g_pair_w[NPAIRS];
__device__ int   g_row_token[NPAIRS];
__device__ float g_row_weight[NPAIRS];
__device__ int   g_s2p[NPAIRS];
__device__ float g_act[(size_t)PBMAX * 128 * INTER];    // tiled [pb][kk24][16KB]
__device__ float g_pout[(size_t)NPAIRS * HIDDEN];
__device__ float g_hs[(size_t)PBMAX * 128 * HIDDEN];    // gathered A, tiled [pb][kk64][16KB]
__device__ float g_wtg[WSZ];   // gate^T tiled [e][nb6][kk64][16KB]
__device__ float g_wtu[WSZ];
__device__ float g_wtd[WSZ];   // down^T tiled [e][nb16][kk24][16KB]

__device__ __forceinline__ uint32_t smem_u32(const void* p) {
    return (uint32_t)__cvta_generic_to_shared(p);
}
__device__ __forceinline__ float f2tf(float x) {
    uint32_t r;
    asm("cvt.rna.tf32.f32 %0, %1;" : "=r"(r) : "f"(x));
    return __uint_as_float(r);
}
__device__ __forceinline__ uint32_t f2tfu(float x) {
    uint32_t r;
    asm("cvt.rna.tf32.f32 %0, %1;" : "=r"(r) : "f"(x));
    return r;
}
#define SW128(o) ((o) ^ (((o) >> 3) & 0x70))
#define CP16(d, s) asm volatile("cp.async.cg.shared.global [%0], [%1], 16;\n" :: "r"(d), "l"(s))
#define CP_COMMIT  asm volatile("cp.async.commit_group;\n")
#define CP_WAIT(n) asm volatile("cp.async.wait_group %0;\n" :: "n"(n))
#define MBAR_INIT(mb, c) asm volatile("mbarrier.init.shared.b64 [%0], %1;" :: "r"(mb), "r"(c) : "memory")
#define MBAR_ARRIVE_TX(mb, tx) asm volatile("mbarrier.arrive.expect_tx.shared.b64 _, [%0], %1;" :: "r"(mb), "r"(tx) : "memory")
#define BULK_G2S(dst, src, sz, mb)                                            \
    asm volatile("cp.async.bulk.shared::cluster.global.mbarrier::complete_tx::bytes [%0], [%1], %2, [%3];" \
                 :: "r"(dst), "l"(src), "r"(sz), "r"(mb) : "memory")
#define MBAR_WAIT(mb, ph)                                                     \
    asm volatile("{\n\t.reg .pred P1;\n\t"                                    \
        "WL_%=:\n\t"                                                          \
        "mbarrier.try_wait.parity.acquire.cta.shared::cta.b64 P1, [%0], %1, 0x989680;\n\t" \
        "@P1 bra.uni WD_%=;\n\t"                                              \
        "bra.uni WL_%=;\n\t"                                                  \
        "WD_%=:\n\t}" :: "r"(mb), "r"(ph) : "memory")

#ifdef TC_OK
#define TC_ALLOC(sm, n)  asm volatile("tcgen05.alloc.cta_group::1.sync.aligned.shared::cta.b32 [%0], %1;" :: "r"(sm), "r"(n) : "memory")
#define TC_DEALLOC(t, n) asm volatile("tcgen05.dealloc.cta_group::1.sync.aligned.b32 %0, %1;" :: "r"(t), "r"(n))
#define TC_RELINQ()      asm volatile("tcgen05.relinquish_alloc_permit.cta_group::1.sync.aligned;")
#define TC_COMMIT(mb)    asm volatile("tcgen05.commit.cta_group::1.mbarrier::arrive::one.shared::cluster.b64 [%0];" :: "r"(mb) : "memory")
#define TC_FENCE_AFTER() asm volatile("tcgen05.fence::after_thread_sync;" ::: "memory")
#define TC_WAIT_LD()     asm volatile("tcgen05.wait::ld.sync.aligned;" ::: "memory")
#define FENCE_ASYNC()    asm volatile("fence.proxy.async.shared::cta;" ::: "memory")
#define LDTM_X32(r, a)                                                        \
    asm volatile("tcgen05.ld.sync.aligned.32x32b.x32.b32 "                    \
        "{%0,%1,%2,%3,%4,%5,%6,%7,%8,%9,%10,%11,%12,%13,%14,%15,"             \
        "%16,%17,%18,%19,%20,%21,%22,%23,%24,%25,%26,%27,%28,%29,%30,%31},[%32];" \
        : "=r"((r)[0]),"=r"((r)[1]),"=r"((r)[2]),"=r"((r)[3]),                \
          "=r"((r)[4]),"=r"((r)[5]),"=r"((r)[6]),"=r"((r)[7]),                \
          "=r"((r)[8]),"=r"((r)[9]),"=r"((r)[10]),"=r"((r)[11]),              \
          "=r"((r)[12]),"=r"((r)[13]),"=r"((r)[14]),"=r"((r)[15]),            \
          "=r"((r)[16]),"=r"((r)[17]),"=r"((r)[18]),"=r"((r)[19]),            \
          "=r"((r)[20]),"=r"((r)[21]),"=r"((r)[22]),"=r"((r)[23]),            \
          "=r"((r)[24]),"=r"((r)[25]),"=r"((r)[26]),"=r"((r)[27]),            \
          "=r"((r)[28]),"=r"((r)[29]),"=r"((r)[30]),"=r"((r)[31]) : "r"(a))

__device__ __forceinline__ uint64_t desc_k(uint32_t a) {     // SW128 K-major
    return (uint64_t(2) << 61) | (uint64_t(1) << 46) | (uint64_t(64) << 32) |
           (uint64_t(1) << 16) | ((uint64_t)(a >> 4) & 0x3FFF);
}
#define IDESC32 ((1u<<4)|(2u<<7)|(2u<<10)|(4u<<17)|(8u<<24))
#define IDESC64 ((1u<<4)|(2u<<7)|(2u<<10)|(8u<<17)|(8u<<24))
__device__ __forceinline__ void mma_n32(uint32_t d, uint64_t ad, uint64_t bd, uint32_t acc) {
    asm volatile(
        "{\n\t.reg .pred p;\n\tsetp.ne.u32 p, %4, 0;\n\t"
        "tcgen05.mma.cta_group::1.kind::tf32 [%0], %1, %2, %3, {%5,%5,%5,%5}, p;\n\t}"
        :: "r"(d), "l"(ad), "l"(bd), "r"(IDESC32), "r"(acc), "r"(0u) : "memory");
}
__device__ __forceinline__ void mma_n64(uint32_t d, uint64_t ad, uint64_t bd, uint32_t acc) {
    asm volatile(
        "{\n\t.reg .pred p;\n\tsetp.ne.u32 p, %4, 0;\n\t"
        "tcgen05.mma.cta_group::1.kind::tf32 [%0], %1, %2, %3, {%5,%5,%5,%5}, p;\n\t}"
        :: "r"(d), "l"(ad), "l"(bd), "r"(IDESC64), "r"(acc), "r"(0u) : "memory");
}
#endif

// ---------------- tiled-layout helpers ----------------
__device__ __forceinline__ float wt_read(const float* wt, int NB, int KK, int e, int n, int k) {
    size_t tile = ((size_t)e * NB + (n >> 7)) * KK + (k >> 5);
    uint32_t inner = SW128((uint32_t)(((n & 127) << 7) + ((k & 31) << 2)));
    return *(const float*)((const char*)wt + tile * 16384 + inner);
}
__device__ __forceinline__ char* act_addr(int ps, int k) {
    size_t tile = (size_t)(ps >> 7) * KT2 + (k >> 5);
    uint32_t inner = SW128((uint32_t)(((ps & 127) << 7) + ((k & 31) << 2)));
    return (char*)g_act + tile * 16384 + inner;
}
__device__ __forceinline__ float act_read(int ps, int k) {
    return *(const float*)act_addr(ps, k);
}

// ---------------- self-test ----------------
__device__ __forceinline__ float tva(int m, int k) {
    return f2tf(0.01f * (float)((m * 7 + k * 13) % 31 - 15));
}
__device__ __forceinline__ float tvb(int n, int k) {
    return f2tf(0.02f * (float)((n * 5 + k * 3) % 29 - 14));
}
__global__ void selftest_kernel() {
#ifdef TC_OK
    __shared__ __align__(1024) float sma[4096];
    __shared__ __align__(1024) float smb[1024];
    __shared__ uint32_t s_tmem[1];
    __shared__ __align__(8) uint64_t s_mbar[1];
    __shared__ float s_d, s_r;
    int tid = threadIdx.x, wid = tid >> 5, lane = tid & 31;

    if (wid == 0) { TC_ALLOC(smem_u32(s_tmem), 128); TC_RELINQ(); }
    if (tid == 0) { MBAR_INIT(smem_u32(s_mbar), 1); s_d = 0.f; s_r = 0.f; }
    for (int idx = tid; idx < 4096; idx += 128) {
        int m = idx >> 5, k = idx & 31;
        *(float*)((char*)sma + SW128((uint32_t)(m * 128 + k * 4))) = tva(m, k);
    }
    for (int idx = tid; idx < 1024; idx += 128) {
        int n = idx >> 5, k = idx & 31;
        *(float*)((char*)smb + SW128((uint32_t)(n * 128 + k * 4))) = tvb(n, k);
    }
    __syncthreads();
    uint32_t tmem = s_tmem[0], mb = smem_u32(s_mbar);
    if (tid == 0) {
        FENCE_ASYNC();
        uint64_t ad = desc_k(smem_u32(sma)), bd = desc_k(smem_u32(smb));
#pragma unroll
        for (int ks = 0; ks < 4; ++ks)
            mma_n32(tmem, ad + ks * 2, bd + ks * 2, ks > 0 ? 1u : 0u);
        TC_COMMIT(mb);
    }
    __syncthreads();
    MBAR_WAIT(mb, 0);
    TC_FENCE_AFTER();
    uint32_t r[32];
    LDTM_X32(r, tmem);
    TC_WAIT_LD();
    int m = wid * 32 + lane;
    float d = 0.f, rf = 0.f;
#pragma unroll 4
    for (int n = 0; n < 32; ++n) {
        float ref = 0.f;
        for (int k = 0; k < 32; ++k) ref += tva(m, k) * tvb(n, k);
        d  += fabsf(__uint_as_float(r[n]) - ref);
        rf += fabsf(ref);
    }
    atomicAdd(&s_d, d); atomicAdd(&s_r, rf);
    __syncthreads();
    if (tid == 0) g_tc_ok = (s_d <= 0.01f * s_r + 1e-3f) ? 1 : 0;
    __syncthreads();
    if (wid == 0) TC_DEALLOC(tmem, 128);
#else
    if (threadIdx.x == 0) g_tc_ok = 0;
#endif
}

// ---------------- prep ----------------
// 2 k-subtiles per block (k-span 64)
__global__ void tile_kernel(const float* __restrict__ src, float* __restrict__ dst,
                            int K, int N, int NB, int KK) {
    if (g_tc_ok == 0) return;
    __shared__ float t[32][33];
    int e = blockIdx.z;
    int k0 = blockIdx.x * 64, n0 = blockIdx.y * 32;
    int r = threadIdx.x >> 3, c4 = (threadIdx.x & 7) << 2;
    int n = n0 + r;
#pragma unroll
    for (int h = 0; h < 2; ++h) {
        int kk0 = k0 + h * 32;
        float4 v = *(const float4*)(src + ((size_t)e * K + kk0 + r) * N + n0 + c4);
        t[r][c4] = v.x; t[r][c4 + 1] = v.y; t[r][c4 + 2] = v.z; t[r][c4 + 3] = v.w;
        __syncthreads();
        size_t tile = ((size_t)e * NB + (n >> 7)) * KK + (kk0 >> 5);
        uint32_t inner = SW128((uint32_t)(((n & 127) << 7) + (c4 << 2)));
        float4 o;
        o.x = f2tf(t[c4    ][r]);
        o.y = f2tf(t[c4 + 1][r]);
        o.z = f2tf(t[c4 + 2][r]);
        o.w = f2tf(t[c4 + 3][r]);
        *(float4*)((char*)dst + tile * 16384 + inner) = o;
        __syncthreads();
    }
}
__global__ void init_kernel() { if (threadIdx.x < NEXP) g_counts[threadIdx.x] = 0; }

__global__ void route_kernel(const float* __restrict__ logits) {
    int t = blockIdx.x * blockDim.x + threadIdx.x;
    if (t >= TOKENS) return;
    float l[NEXP];
    const float* lp = logits + (size_t)t * NEXP;
#pragma unroll
    for (int i = 0; i < NEXP; ++i) l[i] = lp[i];
    float val[TOPK]; int sel[TOPK];
#pragma unroll
    for (int k = 0; k < TOPK; ++k) {
        float best = -1e30f; int bi = 0;
#pragma unroll
        for (int i = 0; i < NEXP; ++i)
            if (l[i] > best) { best = l[i]; bi = i; }
        val[k] = best; sel[k] = bi; l[bi] = -1e30f;
    }
    float m = val[0], s = 0.f, w[TOPK];
#pragma unroll
    for (int k = 0; k < TOPK; ++k) { w[k] = __expf(val[k] - m); s += w[k]; }
    float inv = 1.f / s;
#pragma unroll
    for (int k = 0; k < TOPK; ++k) {
        g_pair_e[t * TOPK + k] = sel[k];
        g_pair_w[t * TOPK + k] = w[k] * inv;
        atomicAdd(&g_counts[sel[k]], 1);
    }
}
__global__ void scan_kernel() {
    if (threadIdx.x == 0) {
        int acc = 0, pacc = 0;
        for (int e = 0; e < NEXP; ++e) {
            g_offsets[e] = acc; g_cursor[e] = acc;
            g_poff[e] = pacc;
            acc += g_counts[e];
            pacc += (g_counts[e] + 127) & ~127;
        }
        g_offsets[NEXP] = acc;
        g_poff[NEXP] = pacc;
    }
}
__global__ void scatter_kernel() {
    int p = blockIdx.x * blockDim.x + threadIdx.x;
    if (p >= NPAIRS) return;
    int slot = atomicAdd(&g_cursor[g_pair_e[p]], 1);
    g_row_token[slot]  = p >> 3;
    g_row_weight[slot] = g_pair_w[p];
    g_s2p[slot] = p;
}
__global__ void gather_kernel(const float* __restrict__ hidden) {
    if (g_tc_ok == 0) return;
    int pb = blockIdx.x, kk = blockIdx.y;
    __shared__ int s_e;
    if (threadIdx.x == 0) {
        int e = 0;
        while (e < NEXP && !(g_poff[e] <= pb * 128 && pb * 128 < g_poff[e + 1])) ++e;
        s_e = e;
    }
    __syncthreads();
    int e = s_e;
    if (e >= NEXP) return;
    int off = g_offsets[e], cnt = g_counts[e];
    char* tile = (char*)g_hs + ((size_t)pb * KT1 + kk) * 16384;
#pragma unroll
    for (int j = 0; j < 4; ++j) {
        int f = threadIdx.x + j * 256;
        int row = f >> 3, c = f & 7;
        int lidx = pb * 128 + row - g_poff[e];
        if (lidx > cnt - 1) lidx = cnt - 1;
        int token = g_row_token[off + lidx];
        float4 v = *(const float4*)(hidden + (size_t)token * HIDDEN + kk * 32 + c * 4);
        v.x = f2tf(v.x); v.y = f2tf(v.y); v.z = f2tf(v.z); v.w = f2tf(v.w);
        *(float4*)(tile + SW128((uint32_t)(row * 128 + c * 16))) = v;
    }
}

// ==== tcgen05 GEMM1: M=128, N=128 (gate+up), 2-stage, 2 CTAs/SM ====
__global__ void __launch_bounds__(256, 2)
gemm1_tc() {
#ifdef TC_OK
    if (g_tc_ok == 0) return;
    int e = blockIdx.z;
    int off = g_offsets[e], cnt = g_offsets[e + 1] - off;
    int m0 = blockIdx.x * 128;
    if (m0 >= cnt) return;
    int nb = blockIdx.y;
    int n0 = nb * 128;

    extern __shared__ char dyn[];
    uint32_t sbase = (smem_u32(dyn) + 1023u) & ~1023u;
    __shared__ uint32_t s_tmem[1];
    __shared__ __align__(8) uint64_t s_full[2], s_mdone[2], s_fin[1];
    int tid = threadIdx.x, wid = tid >> 5, lane = tid & 31;

    if (wid == 0) { TC_ALLOC(smem_u32(s_tmem), 256); TC_RELINQ(); }
    if (tid == 0) {
#pragma unroll
        for (int i = 0; i < 2; ++i) {
            MBAR_INIT(smem_u32(&s_full[i]), 1);
            MBAR_INIT(smem_u32(&s_mdone[i]), 1);
        }
        MBAR_INIT(smem_u32(s_fin), 1);
    }
    __syncthreads();
    uint32_t tmem = s_tmem[0];
    int pb = (g_poff[e] + m0) >> 7;

    if (tid == 32) {   // producer warp
        uint32_t full[2]  = { smem_u32(&s_full[0]),  smem_u32(&s_full[1])  };
        uint32_t mdone[2] = { smem_u32(&s_mdone[0]), smem_u32(&s_mdone[1]) };
        const char* a0 = (const char*)g_hs + ((size_t)pb * KT1) * 16384;
        const char* tg = (const char*)g_wtg + (((size_t)e * 6 + nb) * KT1) * 16384;
        const char* tu = (const char*)g_wtu + (((size_t)e * 6 + nb) * KT1) * 16384;
        for (int kt = 0; kt < KT1; ++kt) {
            int s = kt & 1;
            if (kt >= 2) MBAR_WAIT(mdone[s], (kt / 2 - 1) & 1);
            MBAR_ARRIVE_TX(full[s], 49152u);
            uint32_t sb = sbase + s * STG;
            BULK_G2S(sb,           a0 + (size_t)kt * 16384, 16384u, full[s]);
            BULK_G2S(sb + 16384u,  tg + (size_t)kt * 16384, 16384u, full[s]);
            BULK_G2S(sb + 32768u,  tu + (size_t)kt * 16384, 16384u, full[s]);
        }
    }
    if (tid == 0) {    // consumer
        uint32_t full[2]  = { smem_u32(&s_full[0]),  smem_u32(&s_full[1])  };
        uint32_t mdone[2] = { smem_u32(&s_mdone[0]), smem_u32(&s_mdone[1]) };
        for (int kt = 0; kt < KT1; ++kt) {
            int s = kt & 1;
            MBAR_WAIT(full[s], (kt / 2) & 1);
            FENCE_ASYNC();
            uint32_t sb = sbase + s * STG;
            uint64_t ad = desc_k(sb);
            uint64_t bg = desc_k(sb + 16384u), bu = desc_k(sb + 32768u);
#pragma unroll
            for (int ks = 0; ks < 4; ++ks) {
                uint32_t acc = (kt > 0 || ks > 0) ? 1u : 0u;
#pragma unroll
                for (int j = 0; j < 2; ++j) {
                    mma_n64(tmem + j * 64,       ad + ks * 2, bg + j * 512 + ks * 2, acc);
                    mma_n64(tmem + 128 + j * 64, ad + ks * 2, bu + j * 512 + ks * 2, acc);
                }
            }
            TC_COMMIT(mdone[s]);
        }
        TC_COMMIT(smem_u32(s_fin));
        MBAR_WAIT(smem_u32(s_fin), 0);
    }
    __syncthreads();
    TC_FENCE_AFTER();

    int sp = wid & 3, ch = wid >> 2;
    int row = sp * 32 + lane;
    bool valid = (m0 + row) < cnt;
    int ps = g_poff[e] + m0 + row;
    size_t tb0 = (size_t)(ps >> 7) * KT2 * 16384;
    uint32_t rinner = (uint32_t)((ps & 127) << 7);
#pragma unroll
    for (int cb = 0; cb < 2; ++cb) {
        int c0 = ch * 64 + cb * 32;
        uint32_t rg[32], ru[32];
        LDTM_X32(rg, tmem + c0);
        LDTM_X32(ru, tmem + 128 + c0);
        TC_WAIT_LD();
        if (valid) {
            char* tile = (char*)g_act + tb0 + (size_t)((n0 + c0) >> 5) * 16384;
#pragma unroll
            for (int i = 0; i < 32; i += 4) {
                float4 v;
#pragma unroll
                for (int q = 0; q < 4; ++q) {
                    float g = __uint_as_float(rg[i + q]);
                    float u = __uint_as_float(ru[i + q]);
                    ((float*)&v)[q] = f2tf(g / (1.f + __expf(-g)) * u);
                }
                *(float4*)(tile + SW128(rinner + i * 4)) = v;
            }
        }
    }
    __syncthreads();
    if (wid == 0) TC_DEALLOC(tmem, 256);
#endif
}

// ==== tcgen05 GEMM2: M=128, N=256, 2-stage, 2 CTAs/SM ====
__global__ void __launch_bounds__(256, 2)
gemm2_tc() {
#ifdef TC_OK
    if (g_ok1 == 0) return;
    int e = blockIdx.z;
    int off = g_offsets[e], cnt = g_offsets[e + 1] - off;
    int m0 = blockIdx.x * 128;
    if (m0 >= cnt) return;
    int nb0 = blockIdx.y * 2;
    int n0 = nb0 * 128;

    extern __shared__ char dyn[];
    uint32_t sbase = (smem_u32(dyn) + 1023u) & ~1023u;
    __shared__ uint32_t s_tmem[1];
    __shared__ __align__(8) uint64_t s_full[2], s_mdone[2], s_fin[1];
    int tid = threadIdx.x, wid = tid >> 5, lane = tid & 31;

    if (wid == 0) { TC_ALLOC(smem_u32(s_tmem), 256); TC_RELINQ(); }
    if (tid == 0) {
#pragma unroll
        for (int i = 0; i < 2; ++i) {
            MBAR_INIT(smem_u32(&s_full[i]), 1);
            MBAR_INIT(smem_u32(&s_mdone[i]), 1);
        }
        MBAR_INIT(smem_u32(s_fin), 1);
    }
    __syncthreads();
    uint32_t tmem = s_tmem[0];
    int pb = (g_poff[e] + m0) >> 7;

    if (tid == 32) {   // producer
        uint32_t full[2]  = { smem_u32(&s_full[0]),  smem_u32(&s_full[1])  };
        uint32_t mdone[2] = { smem_u32(&s_mdone[0]), smem_u32(&s_mdone[1]) };
        const char* a0 = (const char*)g_act + ((size_t)pb * KT2) * 16384;
        const char* b0p = (const char*)g_wtd + (((size_t)e * 16 + nb0)     * KT2) * 16384;
        const char* b1p = (const char*)g_wtd + (((size_t)e * 16 + nb0 + 1) * KT2) * 16384;
        for (int kt = 0; kt < KT2; ++kt) {
            int s = kt & 1;
            if (kt >= 2) MBAR_WAIT(mdone[s], (kt / 2 - 1) & 1);
            MBAR_ARRIVE_TX(full[s], 49152u);
            uint32_t sb = sbase + s * STG;
            BULK_G2S(sb,          a0  + (size_t)kt * 16384, 16384u, full[s]);
            BULK_G2S(sb + 16384u, b0p + (size_t)kt * 16384, 16384u, full[s]);
            BULK_G2S(sb + 32768u, b1p + (size_t)kt * 16384, 16384u, full[s]);
        }
    }
    if (tid == 0) {    // consumer
        uint32_t full[2]  = { smem_u32(&s_full[0]),  smem_u32(&s_full[1])  };
        uint32_t mdone[2] = { smem_u32(&s_mdone[0]), smem_u32(&s_mdone[1]) };
        for (int kt = 0; kt < KT2; ++kt) {
            int s = kt & 1;
            MBAR_WAIT(full[s], (kt / 2) & 1);
            FENCE_ASYNC();
            uint32_t sb = sbase + s * STG;
            uint64_t ad = desc_k(sb);
            uint64_t b0 = desc_k(sb + 16384u), b1 = desc_k(sb + 32768u);
#pragma unroll
            for (int ks = 0; ks < 4; ++ks) {
                uint32_t acc = (kt > 0 || ks > 0) ? 1u : 0u;
#pragma unroll
                for (int j = 0; j < 4; ++j) {
                    uint64_t bd = (j < 2) ? (b0 + j * 512 + ks * 2)
                                          : (b1 + (j - 2) * 512 + ks * 2);
                    mma_n64(tmem + j * 64, ad + ks * 2, bd, acc);
                }
            }
            TC_COMMIT(mdone[s]);
        }
        TC_COMMIT(smem_u32(s_fin));
        MBAR_WAIT(smem_u32(s_fin), 0);
    }
    __syncthreads();
    TC_FENCE_AFTER();

    int sp = wid & 3, ch = wid >> 2;
    int row = sp * 32 + lane;
    bool valid = (m0 + row) < cnt;
    int slot = off + m0 + row; if (slot > NPAIRS - 1) slot = NPAIRS - 1;
    float w = g_row_weight[slot];
    float* dst = g_pout + (size_t)g_s2p[slot] * HIDDEN + n0;
#pragma unroll
    for (int cb = 0; cb < 4; ++cb) {
        int c0 = ch * 128 + cb * 32;
        uint32_t r[32];
        LDTM_X32(r, tmem + c0);
        TC_WAIT_LD();
        if (valid) {
#pragma unroll
            for (int i = 0; i < 32; i += 4) {
                float4 v;
                ((float*)&v)[0] = __uint_as_float(r[i])     * w;
                ((float*)&v)[1] = __uint_as_float(r[i + 1]) * w;
                ((float*)&v)[2] = __uint_as_float(r[i + 2]) * w;
                ((float*)&v)[3] = __uint_as_float(r[i + 3]) * w;
                *(float4*)(dst + c0 + i) = v;
            }
        }
    }
    __syncthreads();
    if (wid == 0) TC_DEALLOC(tmem, 256);
#endif
}

// ---------------- verifiers: rows 0 AND 150 ----------------
__global__ void verify1_kernel(const float* __restrict__ hidden) {
    if (g_tc_ok == 0) { if (threadIdx.x == 0) g_ok1 = 0; return; }
    __shared__ float sd[2], sr[2];
    int e = 0;
    while (g_offsets[e + 1] < 1) ++e;
    int cnt = g_offsets[e + 1] - g_offsets[e];
    int w = threadIdx.x >> 5, lane = threadIdx.x & 31;
    int r = (w == 0) ? 0 : (cnt > 150 ? 150 : cnt - 1);
    int tok = g_row_token[g_offsets[e] + r];
    const float* h = hidden + (size_t)tok * HIDDEN;
    int j = lane * 24;
    float ag = 0.f, au = 0.f;
    for (int k = 0; k < HIDDEN; ++k) {
        float hv = f2tf(h[k]);
        ag += hv * wt_read(g_wtg, 6, KT1, e, j, k);
        au += hv * wt_read(g_wtu, 6, KT1, e, j, k);
    }
    float ref = f2tf(ag / (1.f + expf(-ag)) * au);
    float d = fabsf(act_read(g_poff[e] + r, j) - ref), rf = fabsf(ref);
#pragma unroll
    for (int o = 16; o; o >>= 1) {
        d  += __shfl_xor_sync(~0u, d, o);
        rf += __shfl_xor_sync(~0u, rf, o);
    }
    if (lane == 0) { sd[w] = d; sr[w] = rf; }
    __syncthreads();
    if (threadIdx.x == 0)
        g_ok1 = (sd[0] + sd[1] <= 0.02f * (sr[0] + sr[1]) + 1e-2f) ? 1 : 0;
}
__global__ void verify2_kernel() {
    if (g_ok1 == 0) { if (threadIdx.x == 0) g_ok2 = 0; return; }
    __shared__ float sd[2], sr[2];
    int e = 0;
    while (g_offsets[e + 1] < 1) ++e;
    int cnt = g_offsets[e + 1] - g_offsets[e];
    int w = threadIdx.x >> 5, lane = threadIdx.x & 31;
    int r = (w == 0) ? 0 : (cnt > 150 ? 150 : cnt - 1);
    int slot = g_offsets[e] + r;
    int p = g_s2p[slot];
    float wgt = g_row_weight[slot];
    int ps = g_poff[e] + r;
    int n = lane * 64;
    float acc = 0.f;
    for (int k = 0; k < INTER; ++k)
        acc += act_read(ps, k) * wt_read(g_wtd, 16, KT2, e, n, k);
    float ref = acc * wgt;
    float d = fabsf(g_pout[(size_t)p * HIDDEN + n] - ref), rf = fabsf(ref);
#pragma unroll
    for (int o = 16; o; o >>= 1) {
        d  += __shfl_xor_sync(~0u, d, o);
        rf += __shfl_xor_sync(~0u, rf, o);
    }
    if (lane == 0) { sd[w] = d; sr[w] = rf; }
    __syncthreads();
    if (threadIdx.x == 0)
        g_ok2 = (sd[0] + sd[1] <= 0.02f * (sr[0] + sr[1]) + 1e-2f) ? 1 : 0;
}

// ================= legacy mma.sync fallback (TILED g_act) =================
#define MMA_TF32(c, a, b)                                                     \
    asm volatile(                                                             \
        "mma.sync.aligned.m16n8k8.row.col.f32.tf32.tf32.f32 "                 \
        "{%0,%1,%2,%3},{%4,%5,%6,%7},{%8,%9},{%0,%1,%2,%3};"                  \
        : "+f"((c)[0]), "+f"((c)[1]), "+f"((c)[2]), "+f"((c)[3])              \
        : "r"((a)[0]), "r"((a)[1]), "r"((a)[2]), "r"((a)[3]),                 \
          "r"((b)[0]), "r"((b)[1]))

__global__ void __launch_bounds__(256, 2)
gemm1_legacy(const float* __restrict__ hidden,
             const float* __restrict__ gate_w, const float* __restrict__ up_w) {
    if (g_ok1) return;
    int e = blockIdx.z;
    int off = g_offsets[e], cnt = g_offsets[e + 1] - off;
    int m0 = blockIdx.x * 128;
    if (m0 >= cnt) return;
    int n0 = blockIdx.y * 64;

    __shared__ float sA [2][128][20];
    __shared__ float sBg[2][16][68];
    __shared__ float sBu[2][16][68];

    int tid = threadIdx.x;
    const size_t wbase = (size_t)e * HIDDEN * INTER;
    int maxslot = off + cnt - 1;

    const float* asrc[2]; int arowi[2], akc[2];
#pragma unroll
    for (int j = 0; j < 2; ++j) {
        int c = tid + j * 256;
        int row = c >> 2, kc = (c & 3) << 2;
        int slot = off + m0 + row; if (slot > maxslot) slot = maxslot;
        asrc[j] = hidden + (size_t)g_row_token[slot] * HIDDEN + kc;
        arowi[j] = row; akc[j] = kc;
    }
    int bkr = tid >> 4, bnc = (tid & 15) << 2;
    const float* gsrc = gate_w + wbase + (size_t)bkr * INTER + n0 + bnc;
    const float* usrc = up_w   + wbase + (size_t)bkr * INTER + n0 + bnc;

    auto load_tile = [&](int s, int k0) {
#pragma unroll
        for (int j = 0; j < 2; ++j)
            CP16(smem_u32(&sA[s][arowi[j]][akc[j]]), asrc[j] + k0);
        CP16(smem_u32(&sBg[s][bkr][bnc]), gsrc + (size_t)k0 * INTER);
        CP16(smem_u32(&sBu[s][bkr][bnc]), usrc + (size_t)k0 * INTER);
    };

    float cg[2][4][4] = {}, cu[2][4][4] = {};
    int warp = tid >> 5, lane = tid & 31;
    int wm = warp >> 1, wn = warp & 1;
    int gid = lane >> 2, tig = lane & 3;

    load_tile(0, 0); CP_COMMIT;
    const int KT = HIDDEN / 16;
    for (int kt = 0; kt < KT; ++kt) {
        int s = kt & 1;
        if (kt + 1 < KT) { load_tile(s ^ 1, (kt + 1) * 16); CP_COMMIT; CP_WAIT(1); }
        else             { CP_WAIT(0); }
        __syncthreads();
#pragma unroll
        for (int ks = 0; ks < 2; ++ks) {
            int k8 = ks * 8;
            uint32_t af[2][4];
#pragma unroll
            for (int mt = 0; mt < 2; ++mt) {
                int r = wm * 32 + mt * 16;
                af[mt][0] = f2tfu(sA[s][r + gid    ][k8 + tig    ]);
                af[mt][1] = f2tfu(sA[s][r + gid + 8][k8 + tig    ]);
                af[mt][2] = f2tfu(sA[s][r + gid    ][k8 + tig + 4]);
                af[mt][3] = f2tfu(sA[s][r + gid + 8][k8 + tig + 4]);
            }
            uint32_t bg[4][2], bu[4][2];
#pragma unroll
            for (int nt = 0; nt < 4; ++nt) {
                int cix = wn * 32 + nt * 8 + gid;
                bg[nt][0] = f2tfu(sBg[s][k8 + tig    ][cix]);
                bg[nt][1] = f2tfu(sBg[s][k8 + tig + 4][cix]);
                bu[nt][0] = f2tfu(sBu[s][k8 + tig    ][cix]);
                bu[nt][1] = f2tfu(sBu[s][k8 + tig + 4][cix]);
            }
#pragma unroll
            for (int mt = 0; mt < 2; ++mt)
#pragma unroll
                for (int nt = 0; nt < 4; ++nt) {
                    MMA_TF32(cg[mt][nt], af[mt], bg[nt]);
                    MMA_TF32(cu[mt][nt], af[mt], bu[nt]);
                }
        }
        __syncthreads();
    }
#pragma unroll
    for (int mt = 0; mt < 2; ++mt) {
#pragma unroll
        for (int i = 0; i < 4; ++i) {
            int row  = wm * 32 + mt * 16 + gid + ((i >> 1) << 3);
            int srow = m0 + row;
            if (srow >= cnt) continue;
            int ps = g_poff[e] + srow;
#pragma unroll
            for (int nt = 0; nt < 4; ++nt) {
                int k = n0 + wn * 32 + nt * 8 + 2 * tig + (i & 1);
                float g = cg[mt][nt][i], u = cu[mt][nt][i];
                *(float*)act_addr(ps, k) = f2tf(g / (1.f + __expf(-g)) * u);
            }
        }
    }
}

__global__ void __launch_bounds__(256, 2)
gemm2_legacy(const float* __restrict__ down_w) {
    if (g_ok2) return;
    int e = blockIdx.z;
    int off = g_offsets[e], cnt = g_offsets[e + 1] - off;
    int m0 = blockIdx.x * 128;
    if (m0 >= cnt) return;
    int n0 = blockIdx.y * 128;

    __shared__ float sA[2][128][20];
    __shared__ float sB[2][16][132];

    int tid = threadIdx.x;
    const size_t wbase = (size_t)e * INTER * HIDDEN;

    int aps[2], akc2[2], arowi[2];
#pragma unroll
    for (int j = 0; j < 2; ++j) {
        int c = tid + j * 256;
        int row = c >> 2, kc = (c & 3) << 2;
        aps[j] = g_poff[e] + m0 + row;
        arowi[j] = row; akc2[j] = kc;
    }
    const float* bsrc[2]; int bkri[2], bnci[2];
#pragma unroll
    for (int j = 0; j < 2; ++j) {
        int c = tid + j * 256;
        int kr = c >> 5, nc = (c & 31) << 2;
        bsrc[j] = down_w + wbase + (size_t)kr * HIDDEN + n0 + nc;
        bkri[j] = kr; bnci[j] = nc;
    }
    auto load_tile = [&](int s, int k0) {
#pragma unroll
        for (int j = 0; j < 2; ++j)
            CP16(smem_u32(&sA[s][arowi[j]][akc2[j]]), act_addr(aps[j], k0 + akc2[j]));
#pragma unroll
        for (int j = 0; j < 2; ++j)
            CP16(smem_u32(&sB[s][bkri[j]][bnci[j]]), bsrc[j] + (size_t)k0 * HIDDEN);
    };

    float acc[2][8][4] = {};
    int warp = tid >> 5, lane = tid & 31;
    int wm = warp >> 1, wn = warp & 1;
    int gid = lane >> 2, tig = lane & 3;

    load_tile(0, 0); CP_COMMIT;
    const int KT = INTER / 16;
    for (int kt = 0; kt < KT; ++kt) {
        int s = kt & 1;
        if (kt + 1 < KT) { load_tile(s ^ 1, (kt + 1) * 16); CP_COMMIT; CP_WAIT(1); }
        else             { CP_WAIT(0); }
        __syncthreads();
#pragma unroll
        for (int ks = 0; ks < 2; ++ks) {
            int k8 = ks * 8;
            uint32_t af[2][4];
#pragma unroll
            for (int mt = 0; mt < 2; ++mt) {
                int r = wm * 32 + mt * 16;
                af[mt][0] = f2tfu(sA[s][r + gid    ][k8 + tig    ]);
                af[mt][1] = f2tfu(sA[s][r + gid + 8][k8 + tig    ]);
                af[mt][2] = f2tfu(sA[s][r + gid    ][k8 + tig + 4]);
                af[mt][3] = f2tfu(sA[s][r + gid + 8][k8 + tig + 4]);
            }
            uint32_t bf[8][2];
#pragma unroll
            for (int nt = 0; nt < 8; ++nt) {
                int cix = wn * 64 + nt * 8 + gid;
                bf[nt][0] = f2tfu(sB[s][k8 + tig    ][cix]);
                bf[nt][1] = f2tfu(sB[s][k8 + tig + 4][cix]);
            }
#pragma unroll
            for (int mt = 0; mt < 2; ++mt)
#pragma unroll
                for (int nt = 0; nt < 8; ++nt)
                    MMA_TF32(acc[mt][nt], af[mt], bf[nt]);
        }
        __syncthreads();
    }
#pragma unroll
    for (int mt = 0; mt < 2; ++mt) {
#pragma unroll
        for (int i = 0; i < 4; ++i) {
            int row  = wm * 32 + mt * 16 + gid + ((i >> 1) << 3);
            int srow = m0 + row;
            if (srow >= cnt) continue;
            int slot = off + srow;
            float w  = g_row_weight[slot];
            float* orow = g_pout + (size_t)g_s2p[slot] * HIDDEN + n0 + wn * 64;
#pragma unroll
            for (int nt = 0; nt < 8; ++nt)
                orow[nt * 8 + 2 * tig + (i & 1)] = acc[mt][nt][i] * w;
        }
    }
}

// ---------------- combine ----------------
__global__ void combine_kernel(float* __restrict__ out) {
    int t = blockIdx.x, c = threadIdx.x;
    const float* base = g_pout + (size_t)t * TOPK * HIDDEN + c * 4;
    float4 acc = make_float4(0.f, 0.f, 0.f, 0.f);
#pragma unroll
    for (int k = 0; k < TOPK; ++k) {
        float4 v = *(const float4*)(base + (size_t)k * HIDDEN);
        acc.x += v.x; acc.y += v.y; acc.z += v.z; acc.w += v.w;
    }
    *(float4*)(out + (size_t)t * HIDDEN + c * 4) = acc;
}

// ---------------- launch ----------------
extern "C" void kernel_launch(void* const* d_in, const int* in_sizes, int n_in,
                              void* d_out, int out_size) {
    const float* hidden = (const float*)d_in[0];
    const float* logits = (const float*)d_in[1];
    const float* gate   = (const float*)d_in[2];
    const float* up     = (const float*)d_in[3];
    const float* down   = (const float*)d_in[4];
    float* out = (float*)d_out;

    static cudaStream_t s2 = nullptr;
    static cudaEvent_t evF = nullptr, evJ1 = nullptr, evJ2 = nullptr;
    if (s2 == nullptr) {   // first (non-captured) correctness call
        cudaStreamCreateWithFlags(&s2, cudaStreamNonBlocking);
        cudaEventCreateWithFlags(&evF,  cudaEventDisableTiming);
        cudaEventCreateWithFlags(&evJ1, cudaEventDisableTiming);
        cudaEventCreateWithFlags(&evJ2, cudaEventDisableTiming);
        cudaFuncSetAttribute(gemm1_tc, cudaFuncAttributeMaxDynamicSharedMemorySize, 2 * STG + 1024);
        cudaFuncSetAttribute(gemm2_tc, cudaFuncAttributeMaxDynamicSharedMemorySize, 2 * STG + 1024);
    }

    float *wtg, *wtu, *wtd;
    cudaGetSymbolAddress((void**)&wtg, g_wtg);
    cudaGetSymbolAddress((void**)&wtu, g_wtu);
    cudaGetSymbolAddress((void**)&wtd, g_wtd);

    selftest_kernel <<<1, 128>>>();

    // fork: routing chain + gather + down-tiling on s2
    cudaEventRecord(evF, 0);
    cudaStreamWaitEvent(s2, evF, 0);
    init_kernel     <<<1, 64, 0, s2>>>();
    route_kernel    <<<TOKENS / 256, 256, 0, s2>>>(logits);
    scan_kernel     <<<1, 32, 0, s2>>>();
    scatter_kernel  <<<NPAIRS / 256, 256, 0, s2>>>();
    gather_kernel   <<<dim3(PBMAX, KT1), 256, 0, s2>>>(hidden);
    cudaEventRecord(evJ1, s2);                 // gemm1 deps ready
    tile_kernel     <<<dim3(INTER / 64, HIDDEN / 32, NEXP), 256, 0, s2>>>(down, wtd, INTER, HIDDEN, 16, KT2);
    cudaEventRecord(evJ2, s2);                 // gemm2 deps ready

    // main stream: gate/up tiling only (gemm1's weights)
    tile_kernel     <<<dim3(HIDDEN / 64, INTER / 32, NEXP), 256>>>(gate, wtg, HIDDEN, INTER, 6, KT1);
    tile_kernel     <<<dim3(HIDDEN / 64, INTER / 32, NEXP), 256>>>(up,   wtu, HIDDEN, INTER, 6, KT1);

    cudaStreamWaitEvent(0, evJ1, 0);           // join routing/gather before GEMM1
    gemm1_tc        <<<dim3(MCAP / 128, INTER / 128, NEXP), 256, 2 * STG + 1024>>>();
    verify1_kernel  <<<1, 64>>>(hidden);
    gemm1_legacy    <<<dim3(MCAP / 128, INTER / 64,  NEXP), 256>>>(hidden, gate, up);
    cudaStreamWaitEvent(0, evJ2, 0);           // join down-tiling before GEMM2
    gemm2_tc        <<<dim3(MCAP / 128, HIDDEN / 256, NEXP), 256, 2 * STG + 1024>>>();
    verify2_kernel  <<<1, 64>>>();
    gemm2_legacy    <<<dim3(MCAP / 128, HIDDEN / 128, NEXP), 256>>>(down);
    combine_kernel  <<<TOKENS, 512>>>(out);
}

// round 15
// speedup vs baseline: 2.5224x; 1.3278x over previous
#include <cuda_runtime.h>
#include <cstdint>

#define TOKENS 4096
#define HIDDEN 2048
#define INTER  768
#define NEXP   64
#define TOPK   8
#define NPAIRS (TOKENS*TOPK)
#define MCAP   2048
#define BK     32
#define STG    49152        // stage: A 16KB + B 2x16KB
#define KT1    (HIDDEN/BK)  // 64
#define KT2    (INTER/BK)   // 24
#define WSZ    100663296
#define PBMAX  320
#define G1CNT  (16*6)       // gemm1 bids per expert (incl. early-exit)
#define G1TOT  (G1CNT*NEXP) // 6144
#define G2CNT  (16*8)
#define G2TOT  (G2CNT*NEXP) // 8192

__device__ int   g_done[NEXP];
__device__ int   g_counts[NEXP];
__device__ int   g_offsets[NEXP+1];
__device__ int   g_poff[NEXP+1];
__device__ int   g_cursor[NEXP];
__device__ int   g_pair_e[NPAIRS];
__device__ float g_pair_w[NPAIRS];
__device__ int   g_row_token[NPAIRS];
__device__ float g_row_weight[NPAIRS];
__device__ int   g_s2p[NPAIRS];
__device__ float g_act[(size_t)PBMAX * 128 * INTER];    // tiled [pb][kk24][16KB]
__device__ float g_pout[(size_t)NPAIRS * HIDDEN];
__device__ float g_hs[(size_t)PBMAX * 128 * HIDDEN];    // gathered A, tiled [pb][kk64][16KB]
__device__ float g_wtg[WSZ];   // gate^T tiled [e][nb6][kk64][16KB]
__device__ float g_wtu[WSZ];
__device__ float g_wtd[WSZ];   // down^T tiled [e][nb16][kk24][16KB]

__device__ __forceinline__ uint32_t smem_u32(const void* p) {
    return (uint32_t)__cvta_generic_to_shared(p);
}
__device__ __forceinline__ float f2tf(float x) {
    uint32_t r;
    asm("cvt.rna.tf32.f32 %0, %1;" : "=r"(r) : "f"(x));
    return __uint_as_float(r);
}
#define SW128(o) ((o) ^ (((o) >> 3) & 0x70))
#define MBAR_INIT(mb, c) asm volatile("mbarrier.init.shared.b64 [%0], %1;" :: "r"(mb), "r"(c) : "memory")
#define MBAR_ARRIVE_TX(mb, tx) asm volatile("mbarrier.arrive.expect_tx.shared.b64 _, [%0], %1;" :: "r"(mb), "r"(tx) : "memory")
#define BULK_G2S(dst, src, sz, mb)                                            \
    asm volatile("cp.async.bulk.shared::cluster.global.mbarrier::complete_tx::bytes [%0], [%1], %2, [%3];" \
                 :: "r"(dst), "l"(src), "r"(sz), "r"(mb) : "memory")
#define MBAR_WAIT(mb, ph)                                                     \
    asm volatile("{\n\t.reg .pred P1;\n\t"                                    \
        "WL_%=:\n\t"                                                          \
        "mbarrier.try_wait.parity.acquire.cta.shared::cta.b64 P1, [%0], %1, 0x989680;\n\t" \
        "@P1 bra.uni WD_%=;\n\t"                                              \
        "bra.uni WL_%=;\n\t"                                                  \
        "WD_%=:\n\t}" :: "r"(mb), "r"(ph) : "memory")

#if defined(__CUDA_ARCH_FEAT_SM103_ALL) || defined(__CUDA_ARCH_FEAT_SM100_ALL) || defined(__CUDA_ARCH_FEAT_SM101_ALL)
#define TC_OK 1
#endif

#ifdef TC_OK
#define TC_ALLOC(sm, n)  asm volatile("tcgen05.alloc.cta_group::1.sync.aligned.shared::cta.b32 [%0], %1;" :: "r"(sm), "r"(n) : "memory")
#define TC_DEALLOC(t, n) asm volatile("tcgen05.dealloc.cta_group::1.sync.aligned.b32 %0, %1;" :: "r"(t), "r"(n))
#define TC_RELINQ()      asm volatile("tcgen05.relinquish_alloc_permit.cta_group::1.sync.aligned;")
#define TC_COMMIT(mb)    asm volatile("tcgen05.commit.cta_group::1.mbarrier::arrive::one.shared::cluster.b64 [%0];" :: "r"(mb) : "memory")
#define TC_FENCE_AFTER() asm volatile("tcgen05.fence::after_thread_sync;" ::: "memory")
#define TC_WAIT_LD()     asm volatile("tcgen05.wait::ld.sync.aligned;" ::: "memory")
#define FENCE_ASYNC()    asm volatile("fence.proxy.async.shared::cta;" ::: "memory")
#define LDTM_X32(r, a)                                                        \
    asm volatile("tcgen05.ld.sync.aligned.32x32b.x32.b32 "                    \
        "{%0,%1,%2,%3,%4,%5,%6,%7,%8,%9,%10,%11,%12,%13,%14,%15,"             \
        "%16,%17,%18,%19,%20,%21,%22,%23,%24,%25,%26,%27,%28,%29,%30,%31},[%32];" \
        : "=r"((r)[0]),"=r"((r)[1]),"=r"((r)[2]),"=r"((r)[3]),                \
          "=r"((r)[4]),"=r"((r)[5]),"=r"((r)[6]),"=r"((r)[7]),                \
          "=r"((r)[8]),"=r"((r)[9]),"=r"((r)[10]),"=r"((r)[11]),              \
          "=r"((r)[12]),"=r"((r)[13]),"=r"((r)[14]),"=r"((r)[15]),            \
          "=r"((r)[16]),"=r"((r)[17]),"=r"((r)[18]),"=r"((r)[19]),            \
          "=r"((r)[20]),"=r"((r)[21]),"=r"((r)[22]),"=r"((r)[23]),            \
          "=r"((r)[24]),"=r"((r)[25]),"=r"((r)[26]),"=r"((r)[27]),            \
          "=r"((r)[28]),"=r"((r)[29]),"=r"((r)[30]),"=r"((r)[31]) : "r"(a))

__device__ __forceinline__ uint64_t desc_k(uint32_t a) {     // SW128 K-major
    return (uint64_t(2) << 61) | (uint64_t(1) << 46) | (uint64_t(64) << 32) |
           (uint64_t(1) << 16) | ((uint64_t)(a >> 4) & 0x3FFF);
}
#define IDESC64 ((1u<<4)|(2u<<7)|(2u<<10)|(8u<<17)|(8u<<24))
__device__ __forceinline__ void mma_n64(uint32_t d, uint64_t ad, uint64_t bd, uint32_t acc) {
    asm volatile(
        "{\n\t.reg .pred p;\n\tsetp.ne.u32 p, %4, 0;\n\t"
        "tcgen05.mma.cta_group::1.kind::tf32 [%0], %1, %2, %3, {%5,%5,%5,%5}, p;\n\t}"
        :: "r"(d), "l"(ad), "l"(bd), "r"(IDESC64), "r"(acc), "r"(0u) : "memory");
}
#endif

// ---------------- tiled-layout helpers ----------------
__device__ __forceinline__ char* act_addr(int ps, int k) {
    size_t tile = (size_t)(ps >> 7) * KT2 + (k >> 5);
    uint32_t inner = SW128((uint32_t)(((ps & 127) << 7) + ((k & 31) << 2)));
    return (char*)g_act + tile * 16384 + inner;
}

// ---------------- prep ----------------
// 2 k-subtiles per block (k-span 64)
__global__ void tile_kernel(const float* __restrict__ src, float* __restrict__ dst,
                            int K, int N, int NB, int KK) {
    __shared__ float t[32][33];
    int e = blockIdx.z;
    int k0 = blockIdx.x * 64, n0 = blockIdx.y * 32;
    int r = threadIdx.x >> 3, c4 = (threadIdx.x & 7) << 2;
    int n = n0 + r;
#pragma unroll
    for (int h = 0; h < 2; ++h) {
        int kk0 = k0 + h * 32;
        float4 v = *(const float4*)(src + ((size_t)e * K + kk0 + r) * N + n0 + c4);
        t[r][c4] = v.x; t[r][c4 + 1] = v.y; t[r][c4 + 2] = v.z; t[r][c4 + 3] = v.w;
        __syncthreads();
        size_t tile = ((size_t)e * NB + (n >> 7)) * KK + (kk0 >> 5);
        uint32_t inner = SW128((uint32_t)(((n & 127) << 7) + (c4 << 2)));
        float4 o;
        o.x = f2tf(t[c4    ][r]);
        o.y = f2tf(t[c4 + 1][r]);
        o.z = f2tf(t[c4 + 2][r]);
        o.w = f2tf(t[c4 + 3][r]);
        *(float4*)((char*)dst + tile * 16384 + inner) = o;
        __syncthreads();
    }
}
__global__ void init_kernel() {
    if (threadIdx.x < NEXP) { g_counts[threadIdx.x] = 0; g_done[threadIdx.x] = 0; }
}

__global__ void route_kernel(const float* __restrict__ logits) {
    int t = blockIdx.x * blockDim.x + threadIdx.x;
    if (t >= TOKENS) return;
    float l[NEXP];
    const float* lp = logits + (size_t)t * NEXP;
#pragma unroll
    for (int i = 0; i < NEXP; ++i) l[i] = lp[i];
    float val[TOPK]; int sel[TOPK];
#pragma unroll
    for (int k = 0; k < TOPK; ++k) {
        float best = -1e30f; int bi = 0;
#pragma unroll
        for (int i = 0; i < NEXP; ++i)
            if (l[i] > best) { best = l[i]; bi = i; }
        val[k] = best; sel[k] = bi; l[bi] = -1e30f;
    }
    float m = val[0], s = 0.f, w[TOPK];
#pragma unroll
    for (int k = 0; k < TOPK; ++k) { w[k] = __expf(val[k] - m); s += w[k]; }
    float inv = 1.f / s;
#pragma unroll
    for (int k = 0; k < TOPK; ++k) {
        g_pair_e[t * TOPK + k] = sel[k];
        g_pair_w[t * TOPK + k] = w[k] * inv;
        atomicAdd(&g_counts[sel[k]], 1);
    }
}
__global__ void scan_kernel() {
    if (threadIdx.x == 0) {
        int acc = 0, pacc = 0;
        for (int e = 0; e < NEXP; ++e) {
            g_offsets[e] = acc; g_cursor[e] = acc;
            g_poff[e] = pacc;
            acc += g_counts[e];
            pacc += (g_counts[e] + 127) & ~127;
        }
        g_offsets[NEXP] = acc;
        g_poff[NEXP] = pacc;
    }
}
__global__ void scatter_kernel() {
    int p = blockIdx.x * blockDim.x + threadIdx.x;
    if (p >= NPAIRS) return;
    int slot = atomicAdd(&g_cursor[g_pair_e[p]], 1);
    g_row_token[slot]  = p >> 3;
    g_row_weight[slot] = g_pair_w[p];
    g_s2p[slot] = p;
}
__global__ void gather_kernel(const float* __restrict__ hidden) {
    int pb = blockIdx.x, kk = blockIdx.y;
    __shared__ int s_e;
    if (threadIdx.x == 0) {
        int e = 0;
        while (e < NEXP && !(g_poff[e] <= pb * 128 && pb * 128 < g_poff[e + 1])) ++e;
        s_e = e;
    }
    __syncthreads();
    int e = s_e;
    if (e >= NEXP) return;
    int off = g_offsets[e], cnt = g_counts[e];
    char* tile = (char*)g_hs + ((size_t)pb * KT1 + kk) * 16384;
#pragma unroll
    for (int j = 0; j < 4; ++j) {
        int f = threadIdx.x + j * 256;
        int row = f >> 3, c = f & 7;
        int lidx = pb * 128 + row - g_poff[e];
        if (lidx > cnt - 1) lidx = cnt - 1;
        int token = g_row_token[off + lidx];
        float4 v = *(const float4*)(hidden + (size_t)token * HIDDEN + kk * 32 + c * 4);
        v.x = f2tf(v.x); v.y = f2tf(v.y); v.z = f2tf(v.z); v.w = f2tf(v.w);
        *(float4*)(tile + SW128((uint32_t)(row * 128 + c * 16))) = v;
    }
}

// ==== fused tcgen05 GEMM1+GEMM2, per-expert dataflow gating ====
__global__ void __launch_bounds__(256, 2)
gemm_fused() {
#ifdef TC_OK
    int bid = blockIdx.x;
    int tid = threadIdx.x, wid = tid >> 5, lane = tid & 31;

    extern __shared__ char dyn[];
    uint32_t sbase = (smem_u32(dyn) + 1023u) & ~1023u;
    __shared__ uint32_t s_tmem[1];
    __shared__ __align__(8) uint64_t s_full[2], s_mdone[2], s_fin[1];

    if (bid < G1TOT) {
        // ---------------- GEMM1: gate+up, swiglu -> g_act ----------------
        int e  = bid / G1CNT;
        int r  = bid % G1CNT;
        int mb = r / 6, nb = r % 6;
        int off = g_offsets[e], cnt = g_offsets[e + 1] - off;
        int m0 = mb * 128;
        if (m0 >= cnt) {                       // early-exit: still signal
            if (tid == 0) atomicAdd(&g_done[e], 1);
            return;
        }
        int n0 = nb * 128;

        if (wid == 0) { TC_ALLOC(smem_u32(s_tmem), 256); TC_RELINQ(); }
        if (tid == 0) {
#pragma unroll
            for (int i = 0; i < 2; ++i) {
                MBAR_INIT(smem_u32(&s_full[i]), 1);
                MBAR_INIT(smem_u32(&s_mdone[i]), 1);
            }
            MBAR_INIT(smem_u32(s_fin), 1);
        }
        __syncthreads();
        uint32_t tmem = s_tmem[0];
        int pb = (g_poff[e] + m0) >> 7;

        if (tid == 32) {   // producer warp
            uint32_t full[2]  = { smem_u32(&s_full[0]),  smem_u32(&s_full[1])  };
            uint32_t mdone[2] = { smem_u32(&s_mdone[0]), smem_u32(&s_mdone[1]) };
            const char* a0 = (const char*)g_hs + ((size_t)pb * KT1) * 16384;
            const char* tg = (const char*)g_wtg + (((size_t)e * 6 + nb) * KT1) * 16384;
            const char* tu = (const char*)g_wtu + (((size_t)e * 6 + nb) * KT1) * 16384;
            for (int kt = 0; kt < KT1; ++kt) {
                int s = kt & 1;
                if (kt >= 2) MBAR_WAIT(mdone[s], (kt / 2 - 1) & 1);
                MBAR_ARRIVE_TX(full[s], 49152u);
                uint32_t sb = sbase + s * STG;
                BULK_G2S(sb,           a0 + (size_t)kt * 16384, 16384u, full[s]);
                BULK_G2S(sb + 16384u,  tg + (size_t)kt * 16384, 16384u, full[s]);
                BULK_G2S(sb + 32768u,  tu + (size_t)kt * 16384, 16384u, full[s]);
            }
        }
        if (tid == 0) {    // consumer
            uint32_t full[2]  = { smem_u32(&s_full[0]),  smem_u32(&s_full[1])  };
            uint32_t mdone[2] = { smem_u32(&s_mdone[0]), smem_u32(&s_mdone[1]) };
            for (int kt = 0; kt < KT1; ++kt) {
                int s = kt & 1;
                MBAR_WAIT(full[s], (kt / 2) & 1);
                FENCE_ASYNC();
                uint32_t sb = sbase + s * STG;
                uint64_t ad = desc_k(sb);
                uint64_t bg = desc_k(sb + 16384u), bu = desc_k(sb + 32768u);
#pragma unroll
                for (int ks = 0; ks < 4; ++ks) {
                    uint32_t acc = (kt > 0 || ks > 0) ? 1u : 0u;
#pragma unroll
                    for (int j = 0; j < 2; ++j) {
                        mma_n64(tmem + j * 64,       ad + ks * 2, bg + j * 512 + ks * 2, acc);
                        mma_n64(tmem + 128 + j * 64, ad + ks * 2, bu + j * 512 + ks * 2, acc);
                    }
                }
                TC_COMMIT(mdone[s]);
            }
            TC_COMMIT(smem_u32(s_fin));
            MBAR_WAIT(smem_u32(s_fin), 0);
        }
        __syncthreads();
        TC_FENCE_AFTER();

        int sp = wid & 3, ch = wid >> 2;
        int row = sp * 32 + lane;
        bool valid = (m0 + row) < cnt;
        int ps = g_poff[e] + m0 + row;
        size_t tb0 = (size_t)(ps >> 7) * KT2 * 16384;
        uint32_t rinner = (uint32_t)((ps & 127) << 7);
        uint32_t tmem2 = s_tmem[0];
#pragma unroll
        for (int cb = 0; cb < 2; ++cb) {
            int c0 = ch * 64 + cb * 32;
            uint32_t rg[32], ru[32];
            LDTM_X32(rg, tmem2 + c0);
            LDTM_X32(ru, tmem2 + 128 + c0);
            TC_WAIT_LD();
            if (valid) {
                char* tile = (char*)g_act + tb0 + (size_t)((n0 + c0) >> 5) * 16384;
#pragma unroll
                for (int i = 0; i < 32; i += 4) {
                    float4 v;
#pragma unroll
                    for (int q = 0; q < 4; ++q) {
                        float g = __uint_as_float(rg[i + q]);
                        float u = __uint_as_float(ru[i + q]);
                        ((float*)&v)[q] = f2tf(g / (1.f + __expf(-g)) * u);
                    }
                    *(float4*)(tile + SW128(rinner + i * 4)) = v;
                }
            }
        }
        __syncthreads();
        if (wid == 0) TC_DEALLOC(tmem2, 256);
        __syncthreads();
        if (tid == 0) {                       // release: g_act visible, then signal
            __threadfence();
            atomicAdd(&g_done[e], 1);
        }
    } else {
        // ---------------- GEMM2: down-proj -> g_pout ----------------
        int b2 = bid - G1TOT;
        int e  = b2 / G2CNT;
        int r  = b2 % G2CNT;
        int mb = r / 8, nbp = r % 8;
        int off = g_offsets[e], cnt = g_offsets[e + 1] - off;
        int m0 = mb * 128;
        if (m0 >= cnt) return;
        int nb0 = nbp * 2;
        int n0 = nb0 * 128;

        // wait for this expert's gemm1 CTAs (acquire)
        if (tid == 0) {
            while (*(volatile int*)&g_done[e] < G1CNT) __nanosleep(200);
            __threadfence();
        }
        __syncthreads();

        if (wid == 0) { TC_ALLOC(smem_u32(s_tmem), 256); TC_RELINQ(); }
        if (tid == 0) {
#pragma unroll
            for (int i = 0; i < 2; ++i) {
                MBAR_INIT(smem_u32(&s_full[i]), 1);
                MBAR_INIT(smem_u32(&s_mdone[i]), 1);
            }
            MBAR_INIT(smem_u32(s_fin), 1);
        }
        __syncthreads();
        uint32_t tmem = s_tmem[0];
        int pb = (g_poff[e] + m0) >> 7;

        if (tid == 32) {   // producer
            uint32_t full[2]  = { smem_u32(&s_full[0]),  smem_u32(&s_full[1])  };
            uint32_t mdone[2] = { smem_u32(&s_mdone[0]), smem_u32(&s_mdone[1]) };
            const char* a0 = (const char*)g_act + ((size_t)pb * KT2) * 16384;
            const char* b0p = (const char*)g_wtd + (((size_t)e * 16 + nb0)     * KT2) * 16384;
            const char* b1p = (const char*)g_wtd + (((size_t)e * 16 + nb0 + 1) * KT2) * 16384;
            for (int kt = 0; kt < KT2; ++kt) {
                int s = kt & 1;
                if (kt >= 2) MBAR_WAIT(mdone[s], (kt / 2 - 1) & 1);
                MBAR_ARRIVE_TX(full[s], 49152u);
                uint32_t sb = sbase + s * STG;
                BULK_G2S(sb,          a0  + (size_t)kt * 16384, 16384u, full[s]);
                BULK_G2S(sb + 16384u, b0p + (size_t)kt * 16384, 16384u, full[s]);
                BULK_G2S(sb + 32768u, b1p + (size_t)kt * 16384, 16384u, full[s]);
            }
        }
        if (tid == 0) {    // consumer
            uint32_t full[2]  = { smem_u32(&s_full[0]),  smem_u32(&s_full[1])  };
            uint32_t mdone[2] = { smem_u32(&s_mdone[0]), smem_u32(&s_mdone[1]) };
            for (int kt = 0; kt < KT2; ++kt) {
                int s = kt & 1;
                MBAR_WAIT(full[s], (kt / 2) & 1);
                FENCE_ASYNC();
                uint32_t sb = sbase + s * STG;
                uint64_t ad = desc_k(sb);
                uint64_t b0 = desc_k(sb + 16384u), b1 = desc_k(sb + 32768u);
#pragma unroll
                for (int ks = 0; ks < 4; ++ks) {
                    uint32_t acc = (kt > 0 || ks > 0) ? 1u : 0u;
#pragma unroll
                    for (int j = 0; j < 4; ++j) {
                        uint64_t bd = (j < 2) ? (b0 + j * 512 + ks * 2)
                                              : (b1 + (j - 2) * 512 + ks * 2);
                        mma_n64(tmem + j * 64, ad + ks * 2, bd, acc);
                    }
                }
                TC_COMMIT(mdone[s]);
            }
            TC_COMMIT(smem_u32(s_fin));
            MBAR_WAIT(smem_u32(s_fin), 0);
        }
        __syncthreads();
        TC_FENCE_AFTER();

        int sp = wid & 3, ch = wid >> 2;
        int row = sp * 32 + lane;
        bool valid = (m0 + row) < cnt;
        int slot = off + m0 + row; if (slot > NPAIRS - 1) slot = NPAIRS - 1;
        float w = g_row_weight[slot];
        float* dst = g_pout + (size_t)g_s2p[slot] * HIDDEN + n0;
        uint32_t tmem2 = s_tmem[0];
#pragma unroll
        for (int cb = 0; cb < 4; ++cb) {
            int c0 = ch * 128 + cb * 32;
            uint32_t rr[32];
            LDTM_X32(rr, tmem2 + c0);
            TC_WAIT_LD();
            if (valid) {
#pragma unroll
                for (int i = 0; i < 32; i += 4) {
                    float4 v;
                    ((float*)&v)[0] = __uint_as_float(rr[i])     * w;
                    ((float*)&v)[1] = __uint_as_float(rr[i + 1]) * w;
                    ((float*)&v)[2] = __uint_as_float(rr[i + 2]) * w;
                    ((float*)&v)[3] = __uint_as_float(rr[i + 3]) * w;
                    *(float4*)(dst + c0 + i) = v;
                }
            }
        }
        __syncthreads();
        if (wid == 0) TC_DEALLOC(tmem2, 256);
    }
#endif
}

// ---------------- combine ----------------
__global__ void combine_kernel(float* __restrict__ out) {
    int t = blockIdx.x, c = threadIdx.x;
    const float* base = g_pout + (size_t)t * TOPK * HIDDEN + c * 4;
    float4 acc = make_float4(0.f, 0.f, 0.f, 0.f);
#pragma unroll
    for (int k = 0; k < TOPK; ++k) {
        float4 v = *(const float4*)(base + (size_t)k * HIDDEN);
        acc.x += v.x; acc.y += v.y; acc.z += v.z; acc.w += v.w;
    }
    *(float4*)(out + (size_t)t * HIDDEN + c * 4) = acc;
}

// ---------------- launch ----------------
extern "C" void kernel_launch(void* const* d_in, const int* in_sizes, int n_in,
                              void* d_out, int out_size) {
    const float* hidden = (const float*)d_in[0];
    const float* logits = (const float*)d_in[1];
    const float* gate   = (const float*)d_in[2];
    const float* up     = (const float*)d_in[3];
    const float* down   = (const float*)d_in[4];
    float* out = (float*)d_out;

    static cudaStream_t s2 = nullptr, s3 = nullptr;
    static cudaEvent_t evF = nullptr, evJ1 = nullptr, evJ3 = nullptr;
    if (s2 == nullptr) {   // first (non-captured) correctness call
        cudaStreamCreateWithFlags(&s2, cudaStreamNonBlocking);
        cudaStreamCreateWithFlags(&s3, cudaStreamNonBlocking);
        cudaEventCreateWithFlags(&evF,  cudaEventDisableTiming);
        cudaEventCreateWithFlags(&evJ1, cudaEventDisableTiming);
        cudaEventCreateWithFlags(&evJ3, cudaEventDisableTiming);
        cudaFuncSetAttribute(gemm_fused, cudaFuncAttributeMaxDynamicSharedMemorySize, 2 * STG + 1024);
    }

    float *wtg, *wtu, *wtd;
    cudaGetSymbolAddress((void**)&wtg, g_wtg);
    cudaGetSymbolAddress((void**)&wtu, g_wtu);
    cudaGetSymbolAddress((void**)&wtd, g_wtd);

    // fork
    cudaEventRecord(evF, 0);
    cudaStreamWaitEvent(s2, evF, 0);
    cudaStreamWaitEvent(s3, evF, 0);

    // s2: routing chain + gather
    init_kernel     <<<1, 64, 0, s2>>>();
    route_kernel    <<<TOKENS / 256, 256, 0, s2>>>(logits);
    scan_kernel     <<<1, 32, 0, s2>>>();
    scatter_kernel  <<<NPAIRS / 256, 256, 0, s2>>>();
    gather_kernel   <<<dim3(PBMAX, KT1), 256, 0, s2>>>(hidden);
    cudaEventRecord(evJ1, s2);

    // s3: down-weight tiling (needed by gemm2 part of fused kernel)
    tile_kernel     <<<dim3(INTER / 64, HIDDEN / 32, NEXP), 256, 0, s3>>>(down, wtd, INTER, HIDDEN, 16, KT2);
    cudaEventRecord(evJ3, s3);

    // main: gate/up tiling
    tile_kernel     <<<dim3(HIDDEN / 64, INTER / 32, NEXP), 256>>>(gate, wtg, HIDDEN, INTER, 6, KT1);
    tile_kernel     <<<dim3(HIDDEN / 64, INTER / 32, NEXP), 256>>>(up,   wtu, HIDDEN, INTER, 6, KT1);

    cudaStreamWaitEvent(0, evJ1, 0);
    cudaStreamWaitEvent(0, evJ3, 0);
    gemm_fused      <<<G1TOT + G2TOT, 256, 2 * STG + 1024>>>();
    combine_kernel  <<<TOKENS, 512>>>(out);
}